// round 1
// baseline (speedup 1.0000x reference)
#include <cuda_runtime.h>
#include <cstdint>

// ---------------- problem constants ----------------
namespace {
constexpr int Bv = 128, Lv = 64, Tv = 20, Vv = 32000;
constexpr int Ev = 512, Hv = 1024, Av = 512, Fv = 2048;
constexpr int G4H = 4 * Hv;
}

// ---------------- scratch (device globals; no allocation allowed) ----------------
__device__ float g_mean[Bv * Fv];
__device__ float g_h[Bv * Hv];
__device__ float g_c[Bv * Hv];
__device__ float g_xenc[(size_t)Bv * Lv * Av];
__device__ float g_embx[(size_t)Tv * Bv * Ev];
__device__ float g_embgate[(size_t)Tv * Bv * G4H];
__device__ float g_xd[Bv * Av];
__device__ float g_alpha[Bv * Lv];
__device__ float g_ctx[Bv * Fv];
__device__ float g_gates[Bv * G4H];
__device__ float g_Hall[(size_t)Tv * Bv * Hv];
__device__ int   g_yflag;  // 1 => y buffer is int64, 0 => int32

__device__ __forceinline__ float sigmoidf_(float x) { return 1.0f / (1.0f + expf(-x)); }

// ---------------- y dtype detector ----------------
// If y is int64 (little-endian, values < 2^31), every odd 32-bit word is 0.
// If y is int32, the odd words are random tokens in [0, 32000) -> essentially
// impossible for all 1344 of them to be zero.
__global__ void detect_y_kernel(const int* __restrict__ y32) {
    __shared__ int ok;
    if (threadIdx.x == 0) ok = 1;
    __syncthreads();
    for (int i = threadIdx.x; i < (Bv * (Tv + 1)) / 2; i += blockDim.x)
        if (y32[2 * i + 1] != 0) ok = 0;  // benign same-value race
    __syncthreads();
    if (threadIdx.x == 0) g_yflag = ok;
}

// ---------------- embedding gather: g_embx[(t*B+b)*E + e] = emb[y[b][t]][e] ----------------
__global__ void gather_emb_kernel(const void* __restrict__ yraw,
                                  const float* __restrict__ emb) {
    size_t idx = (size_t)blockIdx.x * blockDim.x + threadIdx.x;  // over T*B*E
    if (idx >= (size_t)Tv * Bv * Ev) return;
    int e = (int)(idx % Ev);
    int r = (int)(idx / Ev);
    int b = r % Bv;
    int t = r / Bv;
    int token;
    if (g_yflag)
        token = (int)((const long long*)yraw)[(size_t)b * (Tv + 1) + t];
    else
        token = ((const int*)yraw)[(size_t)b * (Tv + 1) + t];
    g_embx[idx] = emb[(size_t)token * Ev + e];
}

// ---------------- mean over L: g_mean[b*F+f] ----------------
__global__ void mean_kernel(const float* __restrict__ X) {
    int idx = blockIdx.x * blockDim.x + threadIdx.x;  // over B*F
    int f = idx % Fv, b = idx / Fv;
    const float* Xb = X + (size_t)b * Lv * Fv + f;
    float s = 0.f;
#pragma unroll
    for (int l = 0; l < Lv; l++) s += Xb[(size_t)l * Fv];
    g_mean[idx] = s * (1.0f / Lv);
}

// ---------------- attention scores + softmax (fused), writes alpha + output weights ----------------
__global__ void attn_kernel(const float* __restrict__ score_w,
                            const float* __restrict__ score_b,
                            float* __restrict__ wout, int t) {
    int b = blockIdx.x;
    __shared__ float sc[Lv];
    int warp = threadIdx.x >> 5, lane = threadIdx.x & 31;

    for (int l = warp; l < Lv; l += 8) {
        const float* xe = g_xenc + ((size_t)(b * Lv + l)) * Av;
        const float* xdb = g_xd + (size_t)b * Av;
        float s = 0.f;
        for (int a = lane; a < Av; a += 32)
            s += tanhf(xe[a] + xdb[a]) * score_w[a];
#pragma unroll
        for (int o = 16; o; o >>= 1) s += __shfl_xor_sync(0xFFFFFFFFu, s, o);
        if (lane == 0) sc[l] = s + score_b[0];
    }
    __syncthreads();
    __shared__ float smax, ssum;
    if (warp == 0) {
        float m = fmaxf(sc[lane], sc[lane + 32]);
#pragma unroll
        for (int o = 16; o; o >>= 1) m = fmaxf(m, __shfl_xor_sync(0xFFFFFFFFu, m, o));
        float s = expf(sc[lane] - m) + expf(sc[lane + 32] - m);
#pragma unroll
        for (int o = 16; o; o >>= 1) s += __shfl_xor_sync(0xFFFFFFFFu, s, o);
        if (lane == 0) { smax = m; ssum = s; }
    }
    __syncthreads();
    float inv = 1.0f / ssum;
    for (int l = threadIdx.x; l < Lv; l += blockDim.x) {
        float a = expf(sc[l] - smax) * inv;
        g_alpha[b * Lv + l] = a;
        if (wout) wout[((size_t)b * Tv + t) * Lv + l] = a;
    }
}

// ---------------- context: ctx[b,f] = sum_l alpha[b,l] * X[b,l,f] ----------------
__global__ void context_kernel(const float* __restrict__ X) {
    int b = blockIdx.y;
    int f = blockIdx.x * blockDim.x + threadIdx.x;
    __shared__ float al[Lv];
    if (threadIdx.x < Lv) al[threadIdx.x] = g_alpha[b * Lv + threadIdx.x];
    __syncthreads();
    const float* Xb = X + (size_t)b * Lv * Fv + f;
    float s = 0.f;
#pragma unroll
    for (int l = 0; l < Lv; l++) s += al[l] * Xb[(size_t)l * Fv];
    g_ctx[(size_t)b * Fv + f] = s;
}

// ---------------- LSTM pointwise ----------------
__global__ void lstm_kernel(int t) {
    int idx = blockIdx.x * blockDim.x + threadIdx.x;  // over B*H
    int j = idx % Hv, b = idx / Hv;
    const float* g = g_gates + (size_t)b * G4H;
    float ig = sigmoidf_(g[j]);
    float fg = sigmoidf_(g[Hv + j]);
    float gg = tanhf(g[2 * Hv + j]);
    float og = sigmoidf_(g[3 * Hv + j]);
    float c2 = fg * g_c[idx] + ig * gg;
    float h2 = og * tanhf(c2);
    g_c[idx] = c2;
    g_h[idx] = h2;
    g_Hall[(size_t)t * Bv * Hv + idx] = h2;
}

// ---------------- generic SGEMM: C = A@B + bias1 + bias2 + Cin ----------------
// A row-major [M,K] lda, B row-major [K,N] ldb, C row-major [M,N] ldc.
// grid.x = M/BM (so consecutive blocks share a B tile for L2 reuse), grid.y = N/BN.
// REMAP epilogue: row m = t*B+b of [T*B, V] result -> out[(b*T+t)*V + n] + bias1[n].
template <int BM, int BN, int BK, int TM, int TN, bool REMAP>
__global__ __launch_bounds__(256) void sgemm_kernel(
    int M, int N, int K,
    const float* __restrict__ A, int lda,
    const float* __restrict__ Bm, int ldb,
    float* __restrict__ C, int ldc,
    const float* __restrict__ bias1,
    const float* __restrict__ bias2,
    const float* __restrict__ Cin) {
    constexpr int THREADS = (BM / TM) * (BN / TN);
    static_assert(THREADS == 256, "expect 256 threads");
    __shared__ float As[BK][BM + 4];
    __shared__ float Bs[BK][BN];
    const int tid = threadIdx.x;
    const int bm0 = blockIdx.x * BM;
    const int bn0 = blockIdx.y * BN;
    const int nTx = BN / TN;
    const int tx = tid % nTx, ty = tid / nTx;

    float acc[TM][TN];
#pragma unroll
    for (int i = 0; i < TM; i++)
#pragma unroll
        for (int j = 0; j < TN; j++) acc[i][j] = 0.f;

    for (int k0 = 0; k0 < K; k0 += BK) {
#pragma unroll
        for (int it = 0; it < (BM * BK) / THREADS; ++it) {
            int i = tid + it * THREADS;
            int r = i / BK, c = i % BK;
            As[c][r] = A[(size_t)(bm0 + r) * lda + (k0 + c)];
        }
#pragma unroll
        for (int it = 0; it < (BK * BN) / THREADS; ++it) {
            int i = tid + it * THREADS;
            int r = i / BN, c = i % BN;
            Bs[r][c] = Bm[(size_t)(k0 + r) * ldb + (bn0 + c)];
        }
        __syncthreads();
#pragma unroll
        for (int kk = 0; kk < BK; kk++) {
            float ar[TM], br[TN];
#pragma unroll
            for (int i = 0; i < TM; i += 4)
                *reinterpret_cast<float4*>(&ar[i]) =
                    *reinterpret_cast<const float4*>(&As[kk][ty * TM + i]);
#pragma unroll
            for (int j = 0; j < TN; j += 4)
                *reinterpret_cast<float4*>(&br[j]) =
                    *reinterpret_cast<const float4*>(&Bs[kk][tx * TN + j]);
#pragma unroll
            for (int i = 0; i < TM; i++)
#pragma unroll
                for (int j = 0; j < TN; j++)
                    acc[i][j] = fmaf(ar[i], br[j], acc[i][j]);
        }
        __syncthreads();
    }

#pragma unroll
    for (int i = 0; i < TM; i++) {
        int m = bm0 + ty * TM + i;
#pragma unroll
        for (int j = 0; j < TN; j++) {
            int n = bn0 + tx * TN + j;
            float v = acc[i][j];
            if (bias1) v += bias1[n];
            if (bias2) v += bias2[n];
            if (Cin) v += Cin[(size_t)m * ldc + n];
            if (REMAP) {
                int t = m / Bv, b = m % Bv;
                C[((size_t)b * Tv + t) * (size_t)Vv + n] = v;
            } else {
                C[(size_t)m * ldc + n] = v;
            }
        }
    }
}

// ---------------- host orchestration ----------------
extern "C" void kernel_launch(void* const* d_in, const int* in_sizes, int n_in,
                              void* d_out, int out_size) {
    const float* X       = (const float*)d_in[0];
    const void*  yraw    = d_in[1];
    const float* emb     = (const float*)d_in[2];
    const float* fc1_w   = (const float*)d_in[3];
    const float* fc1_b   = (const float*)d_in[4];
    const float* fc2_w   = (const float*)d_in[5];
    const float* fc2_b   = (const float*)d_in[6];
    const float* score_w = (const float*)d_in[7];
    const float* score_b = (const float*)d_in[8];
    const float* sm_w    = (const float*)d_in[9];
    const float* sm_b    = (const float*)d_in[10];
    const float* lm_w    = (const float*)d_in[11];
    const float* lm_b    = (const float*)d_in[12];
    const float* w_ih    = (const float*)d_in[13];
    const float* b_ih    = (const float*)d_in[14];
    const float* w_hh    = (const float*)d_in[15];
    const float* b_hh    = (const float*)d_in[16];
    const float* out_w   = (const float*)d_in[17];
    const float* out_b   = (const float*)d_in[18];

    float *p_mean, *p_h, *p_c, *p_xenc, *p_embx, *p_embgate, *p_xd, *p_ctx, *p_gates, *p_Hall;
    cudaGetSymbolAddress((void**)&p_mean, g_mean);
    cudaGetSymbolAddress((void**)&p_h, g_h);
    cudaGetSymbolAddress((void**)&p_c, g_c);
    cudaGetSymbolAddress((void**)&p_xenc, g_xenc);
    cudaGetSymbolAddress((void**)&p_embx, g_embx);
    cudaGetSymbolAddress((void**)&p_embgate, g_embgate);
    cudaGetSymbolAddress((void**)&p_xd, g_xd);
    cudaGetSymbolAddress((void**)&p_ctx, g_ctx);
    cudaGetSymbolAddress((void**)&p_gates, g_gates);
    cudaGetSymbolAddress((void**)&p_Hall, g_Hall);

    float* outp = (float*)d_out;
    const size_t osz = (size_t)Bv * Tv * Vv;
    const size_t wsz = (size_t)Bv * Tv * Lv;
    float* wout = ((size_t)out_size >= osz + wsz) ? (outp + osz) : nullptr;

    // --- preprocessing (step-invariant) ---
    detect_y_kernel<<<1, 256>>>((const int*)yraw);
    gather_emb_kernel<<<(Tv * Bv * Ev) / 256, 256>>>(yraw, emb);
    mean_kernel<<<(Bv * Fv) / 256, 256>>>(X);
    // h0 = mean @ sm_w + sm_b ; c0 = mean @ lm_w + lm_b
    sgemm_kernel<64, 64, 16, 4, 4, false><<<dim3(Bv / 64, Hv / 64), 256>>>(
        Bv, Hv, Fv, p_mean, Fv, sm_w, Hv, p_h, Hv, sm_b, nullptr, nullptr);
    sgemm_kernel<64, 64, 16, 4, 4, false><<<dim3(Bv / 64, Hv / 64), 256>>>(
        Bv, Hv, Fv, p_mean, Fv, lm_w, Hv, p_c, Hv, lm_b, nullptr, nullptr);
    // x_enc = X @ fc2_w + fc2_b   [8192 x 512], K=2048
    sgemm_kernel<128, 128, 8, 8, 8, false><<<dim3((Bv * Lv) / 128, Av / 128), 256>>>(
        Bv * Lv, Av, Fv, X, Fv, fc2_w, Av, p_xenc, Av, fc2_b, nullptr, nullptr);
    // embgate = embx @ w_ih[:E] + b_ih + b_hh   [2560 x 4096], K=512
    sgemm_kernel<128, 128, 8, 8, 8, false><<<dim3((Tv * Bv) / 128, G4H / 128), 256>>>(
        Tv * Bv, G4H, Ev, p_embx, Ev, w_ih, G4H, p_embgate, G4H, b_ih, b_hh, nullptr);

    // --- recurrent loop ---
    for (int t = 0; t < Tv; t++) {
        // xd = h @ fc1_w + fc1_b  [128 x 512], K=1024
        sgemm_kernel<64, 64, 16, 4, 4, false><<<dim3(Bv / 64, Av / 64), 256>>>(
            Bv, Av, Hv, p_h, Hv, fc1_w, Av, p_xd, Av, fc1_b, nullptr, nullptr);
        attn_kernel<<<Bv, 256>>>(score_w, score_b, wout, t);
        context_kernel<<<dim3(Fv / 256, Bv), 256>>>(X);
        // gates = ctx @ w_ih[E:] + embgate[t]   [128 x 4096], K=2048
        sgemm_kernel<64, 64, 16, 4, 4, false><<<dim3(Bv / 64, G4H / 64), 256>>>(
            Bv, G4H, Fv, p_ctx, Fv, w_ih + (size_t)Ev * G4H, G4H, p_gates, G4H,
            nullptr, nullptr, p_embgate + (size_t)t * Bv * G4H);
        // gates += h @ w_hh   [128 x 4096], K=1024
        sgemm_kernel<64, 64, 16, 4, 4, false><<<dim3(Bv / 64, G4H / 64), 256>>>(
            Bv, G4H, Hv, p_h, Hv, w_hh, G4H, p_gates, G4H,
            nullptr, nullptr, p_gates);
        lstm_kernel<<<(Bv * Hv) / 256, 256>>>(t);
    }

    // --- batched logits: [T*B, V] = Hall @ out_w + out_b, remapped to [B,T,V] ---
    sgemm_kernel<128, 128, 8, 8, 8, true><<<dim3((Tv * Bv) / 128, Vv / 128), 256>>>(
        Tv * Bv, Vv, Hv, p_Hall, Hv, out_w, Vv, outp, Vv, out_b, nullptr, nullptr);
}

// round 3
// speedup vs baseline: 2.1680x; 2.1680x over previous
#include <cuda_runtime.h>
#include <cuda_bf16.h>
#include <cstdint>

// ---------------- problem constants ----------------
namespace {
constexpr int Bv = 128, Lv = 64, Tv = 20, Vv = 32000;
constexpr int Ev = 512, Hv = 1024, Av = 512, Fv = 2048;
constexpr int G4H = 4 * Hv;          // 4096
constexpr int CAT = Fv + Hv;         // 3072 : [ctx | h]
constexpr int S_XD = 8, S_GT = 4, S_HC = 4;
// logits mma tile
constexpr int LDT = 40;                 // smem leading dim in bf16 (pad 32->40, conflict-free)
constexpr int BUFSZ = 4 * 128 * LDT;    // bf16 units per k-chunk buffer (Ah,Al,Bh,Bl)
constexpr int OFF_AL = 128 * LDT;
constexpr int OFF_BH = 2 * 128 * LDT;
constexpr int OFF_BL = 3 * 128 * LDT;
constexpr int LOGITS_SMEM = 2 * BUFSZ * 2;  // bytes (double buffered)
}

// ---------------- scratch (device globals) ----------------
__device__ float g_mean[Bv * Fv];
__device__ float g_c[Bv * Hv];
__device__ float g_cat[(size_t)Bv * CAT];             // [ctx(2048) | h(1024)]
__device__ float g_xenc[(size_t)Bv * Lv * Av];
__device__ float g_embx[(size_t)Tv * Bv * Ev];
__device__ float g_embgate[(size_t)Tv * Bv * G4H];
__device__ float g_xdp[(size_t)S_XD * Bv * Av];
__device__ float g_alpha[Bv * Lv];
__device__ float g_gatep[(size_t)S_GT * Bv * G4H];
__device__ float g_hp[(size_t)S_HC * Bv * Hv];
__device__ float g_cp[(size_t)S_HC * Bv * Hv];
__device__ float g_Hall[(size_t)Tv * Bv * Hv];
__device__ __nv_bfloat16 g_Ahi[(size_t)Tv * Bv * Hv];
__device__ __nv_bfloat16 g_Alo[(size_t)Tv * Bv * Hv];
__device__ __nv_bfloat16 g_Bhi[(size_t)Vv * Hv];
__device__ __nv_bfloat16 g_Blo[(size_t)Vv * Hv];
__device__ int g_yflag;

__device__ __forceinline__ float sigmoidf_(float x) { return 1.0f / (1.0f + expf(-x)); }

// ---------------- PTX helpers (plain sm_103-legal features only) ----------------
__device__ __forceinline__ uint32_t smem_u32(const void* p) {
    uint32_t a;
    asm("{ .reg .u64 t; cvta.to.shared.u64 t, %1; cvt.u32.u64 %0, t; }" : "=r"(a) : "l"(p));
    return a;
}
__device__ __forceinline__ void cp16(uint32_t s, const void* g) {
    asm volatile("cp.async.cg.shared.global [%0], [%1], 16;" :: "r"(s), "l"(g));
}
__device__ __forceinline__ void ldsm4(uint32_t& r0, uint32_t& r1, uint32_t& r2,
                                      uint32_t& r3, uint32_t a) {
    asm volatile("ldmatrix.sync.aligned.m8n8.x4.shared.b16 {%0,%1,%2,%3}, [%4];"
                 : "=r"(r0), "=r"(r1), "=r"(r2), "=r"(r3) : "r"(a));
}
__device__ __forceinline__ void mma16816(float* c, const uint32_t* a, const uint32_t* b) {
    asm volatile(
        "mma.sync.aligned.m16n8k16.row.col.f32.bf16.bf16.f32 "
        "{%0,%1,%2,%3}, {%4,%5,%6,%7}, {%8,%9}, {%0,%1,%2,%3};"
        : "+f"(c[0]), "+f"(c[1]), "+f"(c[2]), "+f"(c[3])
        : "r"(a[0]), "r"(a[1]), "r"(a[2]), "r"(a[3]), "r"(b[0]), "r"(b[1]));
}

// ---------------- y dtype detector + gather ----------------
__global__ void detect_y_kernel(const int* __restrict__ y32) {
    __shared__ int ok;
    if (threadIdx.x == 0) ok = 1;
    __syncthreads();
    for (int i = threadIdx.x; i < (Bv * (Tv + 1)) / 2; i += blockDim.x)
        if (y32[2 * i + 1] != 0) ok = 0;
    __syncthreads();
    if (threadIdx.x == 0) g_yflag = ok;
}

__global__ void gather_emb_kernel(const void* __restrict__ yraw,
                                  const float* __restrict__ emb) {
    size_t idx = (size_t)blockIdx.x * blockDim.x + threadIdx.x;
    if (idx >= (size_t)Tv * Bv * Ev) return;
    int e = (int)(idx % Ev);
    int r = (int)(idx / Ev);
    int b = r % Bv, t = r / Bv;
    int token;
    if (g_yflag)
        token = (int)((const long long*)yraw)[(size_t)b * (Tv + 1) + t];
    else
        token = ((const int*)yraw)[(size_t)b * (Tv + 1) + t];
    g_embx[idx] = emb[(size_t)token * Ev + e];
}

__global__ void mean_kernel(const float* __restrict__ X) {
    int idx = blockIdx.x * blockDim.x + threadIdx.x;
    int f = idx % Fv, b = idx / Fv;
    const float* Xb = X + (size_t)b * Lv * Fv + f;
    float s = 0.f;
#pragma unroll
    for (int l = 0; l < Lv; l++) s += Xb[(size_t)l * Fv];
    g_mean[idx] = s * (1.0f / Lv);
}

// ---------------- split-K GEMM for M=128 (partials out) ----------------
template <int BN, int BK>
__global__ __launch_bounds__(256) void skgemm(
    int N, int K, int S,
    const float* __restrict__ A, int lda,
    const float* __restrict__ B1, const float* __restrict__ B2, int Ksplit, int ldb,
    float* __restrict__ Part) {
    __shared__ float As[BK][128 + 4];
    __shared__ float Bs[BK][BN];
    int tid = threadIdx.x;
    int bn0 = blockIdx.x * BN;
    int s = blockIdx.y;
    int Ks = K / S, kbeg = s * Ks, kend = kbeg + Ks;
    int tx = tid & 15, ty = tid >> 4;
    float acc[8][2] = {};
    for (int k0 = kbeg; k0 < kend; k0 += BK) {
#pragma unroll
        for (int it = 0; it < (128 * BK) / 256; it++) {
            int i = tid + it * 256;
            int r = i / BK, c = i % BK;
            As[c][r] = A[(size_t)r * lda + k0 + c];
        }
#pragma unroll
        for (int it = 0; it < (BK * BN) / 256; it++) {
            int i = tid + it * 256;
            int r = i / BN, c = i % BN;
            int kg = k0 + r;
            const float* src = (kg < Ksplit) ? (B1 + (size_t)kg * ldb)
                                             : (B2 + (size_t)(kg - Ksplit) * ldb);
            Bs[r][c] = src[bn0 + c];
        }
        __syncthreads();
#pragma unroll
        for (int kk = 0; kk < BK; kk++) {
            float ar[8], br[2];
#pragma unroll
            for (int i = 0; i < 8; i += 4)
                *reinterpret_cast<float4*>(ar + i) =
                    *reinterpret_cast<const float4*>(&As[kk][ty * 8 + i]);
            br[0] = Bs[kk][tx * 2];
            br[1] = Bs[kk][tx * 2 + 1];
#pragma unroll
            for (int i = 0; i < 8; i++) {
                acc[i][0] = fmaf(ar[i], br[0], acc[i][0]);
                acc[i][1] = fmaf(ar[i], br[1], acc[i][1]);
            }
        }
        __syncthreads();
    }
    float* P = Part + (size_t)s * 128 * N;
#pragma unroll
    for (int i = 0; i < 8; i++) {
        int r = ty * 8 + i;
        P[(size_t)r * N + bn0 + tx * 2] = acc[i][0];
        P[(size_t)r * N + bn0 + tx * 2 + 1] = acc[i][1];
    }
}

// ---------------- reduce h0/c0 ----------------
__global__ void reduce_hc(const float* __restrict__ sm_b, const float* __restrict__ lm_b) {
    int idx = blockIdx.x * blockDim.x + threadIdx.x;
    int b = idx / Hv, j = idx % Hv;
    float h = sm_b[j], c = lm_b[j];
#pragma unroll
    for (int s = 0; s < S_HC; s++) {
        h += g_hp[(size_t)s * Bv * Hv + idx];
        c += g_cp[(size_t)s * Bv * Hv + idx];
    }
    g_cat[(size_t)b * CAT + Fv + j] = h;
    g_c[idx] = c;
}

// ---------------- attention (sums xd partials inline) ----------------
__global__ void attn_kernel(const float* __restrict__ fc1_b,
                            const float* __restrict__ score_w,
                            const float* __restrict__ score_b,
                            float* __restrict__ wout, int t) {
    int b = blockIdx.x;
    __shared__ float xd_s[Av];
    __shared__ float sc[Lv];
    int tid = threadIdx.x, warp = tid >> 5, lane = tid & 31;
    for (int a = tid; a < Av; a += 256) {
        float s = fc1_b[a];
#pragma unroll
        for (int p = 0; p < S_XD; p++) s += g_xdp[(size_t)p * Bv * Av + b * Av + a];
        xd_s[a] = s;
    }
    __syncthreads();
    for (int l = warp; l < Lv; l += 8) {
        const float* xe = g_xenc + (size_t)(b * Lv + l) * Av;
        float s = 0.f;
        for (int a = lane; a < Av; a += 32) s += tanhf(xe[a] + xd_s[a]) * score_w[a];
#pragma unroll
        for (int o = 16; o; o >>= 1) s += __shfl_xor_sync(0xFFFFFFFFu, s, o);
        if (lane == 0) sc[l] = s + score_b[0];
    }
    __syncthreads();
    __shared__ float smax, ssum;
    if (warp == 0) {
        float m = fmaxf(sc[lane], sc[lane + 32]);
#pragma unroll
        for (int o = 16; o; o >>= 1) m = fmaxf(m, __shfl_xor_sync(0xFFFFFFFFu, m, o));
        float s = expf(sc[lane] - m) + expf(sc[lane + 32] - m);
#pragma unroll
        for (int o = 16; o; o >>= 1) s += __shfl_xor_sync(0xFFFFFFFFu, s, o);
        if (lane == 0) { smax = m; ssum = s; }
    }
    __syncthreads();
    float inv = 1.0f / ssum;
    for (int l = tid; l < Lv; l += blockDim.x) {
        float a = expf(sc[l] - smax) * inv;
        g_alpha[b * Lv + l] = a;
        if (wout) wout[((size_t)b * Tv + t) * Lv + l] = a;
    }
}

// ---------------- context -> g_cat[:, :F] ----------------
__global__ void context_kernel(const float* __restrict__ X) {
    int b = blockIdx.y;
    int f = blockIdx.x * blockDim.x + threadIdx.x;
    __shared__ float al[Lv];
    if (threadIdx.x < Lv) al[threadIdx.x] = g_alpha[b * Lv + threadIdx.x];
    __syncthreads();
    const float* Xb = X + (size_t)b * Lv * Fv + f;
    float s = 0.f;
#pragma unroll
    for (int l = 0; l < Lv; l++) s += al[l] * Xb[(size_t)l * Fv];
    g_cat[(size_t)b * CAT + f] = s;
}

// ---------------- fused gates-reduce + LSTM pointwise ----------------
__global__ void lstm_fuse(int t) {
    int idx = blockIdx.x * blockDim.x + threadIdx.x;
    int b = idx / Hv, j = idx % Hv;
    size_t base = (size_t)b * G4H;
    const float* EG = g_embgate + ((size_t)t * Bv) * G4H + base;
    float ig = EG[j], fg = EG[Hv + j], gg = EG[2 * Hv + j], og = EG[3 * Hv + j];
#pragma unroll
    for (int s = 0; s < S_GT; s++) {
        const float* P = g_gatep + (size_t)s * Bv * G4H + base;
        ig += P[j];
        fg += P[Hv + j];
        gg += P[2 * Hv + j];
        og += P[3 * Hv + j];
    }
    ig = sigmoidf_(ig);
    fg = sigmoidf_(fg);
    og = sigmoidf_(og);
    gg = tanhf(gg);
    float c2 = fg * g_c[idx] + ig * gg;
    float h2 = og * tanhf(c2);
    g_c[idx] = c2;
    g_cat[(size_t)b * CAT + Fv + j] = h2;
    g_Hall[(size_t)t * Bv * Hv + idx] = h2;
}

// ---------------- big SIMT SGEMM (x_enc, embgate) ----------------
template <int BM, int BN, int BK, int TM, int TN>
__global__ __launch_bounds__(256) void sgemm_kernel(
    int M, int N, int K,
    const float* __restrict__ A, int lda,
    const float* __restrict__ Bm, int ldb,
    float* __restrict__ C, int ldc,
    const float* __restrict__ bias1,
    const float* __restrict__ bias2) {
    __shared__ float As[BK][BM + 4];
    __shared__ float Bs[BK][BN];
    const int tid = threadIdx.x;
    const int bm0 = blockIdx.x * BM;
    const int bn0 = blockIdx.y * BN;
    const int nTx = BN / TN;
    const int tx = tid % nTx, ty = tid / nTx;
    float acc[TM][TN];
#pragma unroll
    for (int i = 0; i < TM; i++)
#pragma unroll
        for (int j = 0; j < TN; j++) acc[i][j] = 0.f;
    for (int k0 = 0; k0 < K; k0 += BK) {
#pragma unroll
        for (int it = 0; it < (BM * BK) / 256; ++it) {
            int i = tid + it * 256;
            int r = i / BK, c = i % BK;
            As[c][r] = A[(size_t)(bm0 + r) * lda + (k0 + c)];
        }
#pragma unroll
        for (int it = 0; it < (BK * BN) / 256; ++it) {
            int i = tid + it * 256;
            int r = i / BN, c = i % BN;
            Bs[r][c] = Bm[(size_t)(k0 + r) * ldb + (bn0 + c)];
        }
        __syncthreads();
#pragma unroll
        for (int kk = 0; kk < BK; kk++) {
            float ar[TM], br[TN];
#pragma unroll
            for (int i = 0; i < TM; i += 4)
                *reinterpret_cast<float4*>(&ar[i]) =
                    *reinterpret_cast<const float4*>(&As[kk][ty * TM + i]);
#pragma unroll
            for (int j = 0; j < TN; j += 4)
                *reinterpret_cast<float4*>(&br[j]) =
                    *reinterpret_cast<const float4*>(&Bs[kk][tx * TN + j]);
#pragma unroll
            for (int i = 0; i < TM; i++)
#pragma unroll
                for (int j = 0; j < TN; j++) acc[i][j] = fmaf(ar[i], br[j], acc[i][j]);
        }
        __syncthreads();
    }
#pragma unroll
    for (int i = 0; i < TM; i++) {
        int m = bm0 + ty * TM + i;
#pragma unroll
        for (int j = 0; j < TN; j++) {
            int n = bn0 + tx * TN + j;
            float v = acc[i][j];
            if (bias1) v += bias1[n];
            if (bias2) v += bias2[n];
            C[(size_t)m * ldc + n] = v;
        }
    }
}

// ---------------- bf16 hi/lo conversion ----------------
__global__ void convA_kernel() {
    int idx = blockIdx.x * blockDim.x + threadIdx.x;
    float a = g_Hall[idx];
    __nv_bfloat16 h = __float2bfloat16_rn(a);
    g_Ahi[idx] = h;
    g_Alo[idx] = __float2bfloat16_rn(a - __bfloat162float(h));
}

__global__ void transB_kernel(const float* __restrict__ w) {  // w: [Hv, Vv]
    __shared__ float tile[32][33];
    int n0 = blockIdx.x * 32, k0 = blockIdx.y * 32;
    int tx = threadIdx.x, ty = threadIdx.y;
#pragma unroll
    for (int i = 0; i < 4; i++) {
        int k = k0 + ty + i * 8;
        tile[ty + i * 8][tx] = w[(size_t)k * Vv + n0 + tx];
    }
    __syncthreads();
#pragma unroll
    for (int i = 0; i < 4; i++) {
        int n = n0 + ty + i * 8;
        int k = k0 + tx;
        float v = tile[tx][ty + i * 8];
        __nv_bfloat16 h = __float2bfloat16_rn(v);
        g_Bhi[(size_t)n * Hv + k] = h;
        g_Blo[(size_t)n * Hv + k] = __float2bfloat16_rn(v - __bfloat162float(h));
    }
}

// ---------------- logits GEMM via mma.sync (bf16 hi/lo, 3 passes) ----------------
// C[2560, 32000] = Hall @ out_w^T, K=1024.  Block tile 128x128, BK=32, 8 warps
// (each 64x32). cp.async double-buffered smem; ldmatrix.x4 fragment loads.
__global__ void __launch_bounds__(256) logits_mma(const float* __restrict__ outb,
                                                  float* __restrict__ outp) {
    extern __shared__ __nv_bfloat16 smb[];
    const int tid = threadIdx.x, lane = tid & 31, wid = tid >> 5;
    const int wm = wid & 1, wn = wid >> 1;  // 2 (M) x 4 (N) warps
    const int bm0 = blockIdx.x * 128, bn0 = blockIdx.y * 128;
    const uint32_t sbase = smem_u32(smb);

    float acc[4][4][4];
#pragma unroll
    for (int i = 0; i < 4; i++)
#pragma unroll
        for (int j = 0; j < 4; j++)
#pragma unroll
            for (int k = 0; k < 4; k++) acc[i][j][k] = 0.f;

    auto issue = [&](int buf, int kc) {
        const int k0 = kc * 32;
#pragma unroll
        for (int j = 0; j < 2; j++) {
            int c = tid + j * 256;
            int r = c >> 2, sg = c & 3;
            uint32_t so = sbase + (uint32_t)(buf * BUFSZ + r * LDT + sg * 8) * 2;
            size_t ga = (size_t)(bm0 + r) * Hv + k0 + sg * 8;
            size_t gb = (size_t)(bn0 + r) * Hv + k0 + sg * 8;
            cp16(so, g_Ahi + ga);
            cp16(so + OFF_AL * 2, g_Alo + ga);
            cp16(so + OFF_BH * 2, g_Bhi + gb);
            cp16(so + OFF_BL * 2, g_Blo + gb);
        }
        asm volatile("cp.async.commit_group;" ::: "memory");
    };

    // ldmatrix lane->address patterns
    const int arow = ((lane >> 3) & 1) * 8 + (lane & 7);  // A: M0 rows@k0, M1 rows+8@k0, M2 rows@k0+8, M3 rows+8@k0+8
    const int akof = (lane >> 4) * 8;
    const int brow = ((lane >> 4) & 1) * 8 + (lane & 7);  // B: M0 n@k0, M1 n@k0+8, M2 n+8@k0, M3 n+8@k0+8
    const int bkof = ((lane >> 3) & 1) * 8;

    issue(0, 0);
    constexpr int NKC = Hv / 32;  // 32 chunks
    for (int kc = 0; kc < NKC; kc++) {
        if (kc + 1 < NKC) {
            issue((kc + 1) & 1, kc + 1);
            asm volatile("cp.async.wait_group 1;" ::: "memory");
        } else {
            asm volatile("cp.async.wait_group 0;" ::: "memory");
        }
        __syncthreads();
        const uint32_t bo = sbase + (uint32_t)((kc & 1) * BUFSZ) * 2;
#pragma unroll
        for (int ks = 0; ks < 2; ks++) {
            const int k0 = ks * 16;
            uint32_t bh[4][2], bl[4][2];
#pragma unroll
            for (int p = 0; p < 2; p++) {
                uint32_t ab = bo + (uint32_t)(OFF_BH + (wn * 32 + p * 16 + brow) * LDT + k0 + bkof) * 2;
                ldsm4(bh[2 * p][0], bh[2 * p][1], bh[2 * p + 1][0], bh[2 * p + 1][1], ab);
                ldsm4(bl[2 * p][0], bl[2 * p][1], bl[2 * p + 1][0], bl[2 * p + 1][1],
                      ab + (uint32_t)(OFF_BL - OFF_BH) * 2);
            }
#pragma unroll
            for (int mf = 0; mf < 4; mf++) {
                uint32_t ah[4], al[4];
                uint32_t aa = bo + (uint32_t)((wm * 64 + mf * 16 + arow) * LDT + k0 + akof) * 2;
                ldsm4(ah[0], ah[1], ah[2], ah[3], aa);
                ldsm4(al[0], al[1], al[2], al[3], aa + (uint32_t)OFF_AL * 2);
#pragma unroll
                for (int nf = 0; nf < 4; nf++) {
                    mma16816(acc[mf][nf], ah, bh[nf]);
                    mma16816(acc[mf][nf], ah, bl[nf]);
                    mma16816(acc[mf][nf], al, bh[nf]);
                }
            }
        }
        __syncthreads();
    }

    // epilogue: C row m = t*B+b -> out[(b*T+t)*V + n] + out_b[n]
#pragma unroll
    for (int mf = 0; mf < 4; mf++) {
#pragma unroll
        for (int half = 0; half < 2; half++) {
            int m = bm0 + wm * 64 + mf * 16 + (lane >> 2) + half * 8;
            int tt = m >> 7, bb = m & 127;
            float* dst = outp + ((size_t)bb * Tv + tt) * (size_t)Vv;
#pragma unroll
            for (int nf = 0; nf < 4; nf++) {
                int n = bn0 + wn * 32 + nf * 8 + (lane & 3) * 2;
                float2 v;
                v.x = acc[mf][nf][half * 2 + 0] + outb[n];
                v.y = acc[mf][nf][half * 2 + 1] + outb[n + 1];
                *reinterpret_cast<float2*>(dst + n) = v;
            }
        }
    }
}

// ---------------- host orchestration ----------------
extern "C" void kernel_launch(void* const* d_in, const int* in_sizes, int n_in,
                              void* d_out, int out_size) {
    const float* X       = (const float*)d_in[0];
    const void*  yraw    = d_in[1];
    const float* emb     = (const float*)d_in[2];
    const float* fc1_w   = (const float*)d_in[3];
    const float* fc1_b   = (const float*)d_in[4];
    const float* fc2_w   = (const float*)d_in[5];
    const float* fc2_b   = (const float*)d_in[6];
    const float* score_w = (const float*)d_in[7];
    const float* score_b = (const float*)d_in[8];
    const float* sm_w    = (const float*)d_in[9];
    const float* sm_b    = (const float*)d_in[10];
    const float* lm_w    = (const float*)d_in[11];
    const float* lm_b    = (const float*)d_in[12];
    const float* w_ih    = (const float*)d_in[13];
    const float* b_ih    = (const float*)d_in[14];
    const float* w_hh    = (const float*)d_in[15];
    const float* b_hh    = (const float*)d_in[16];
    const float* out_w   = (const float*)d_in[17];
    const float* out_b   = (const float*)d_in[18];

    float *p_mean, *p_cat, *p_xenc, *p_embx, *p_embgate, *p_xdp, *p_gatep, *p_hp, *p_cp;
    cudaGetSymbolAddress((void**)&p_mean, g_mean);
    cudaGetSymbolAddress((void**)&p_cat, g_cat);
    cudaGetSymbolAddress((void**)&p_xenc, g_xenc);
    cudaGetSymbolAddress((void**)&p_embx, g_embx);
    cudaGetSymbolAddress((void**)&p_embgate, g_embgate);
    cudaGetSymbolAddress((void**)&p_xdp, g_xdp);
    cudaGetSymbolAddress((void**)&p_gatep, g_gatep);
    cudaGetSymbolAddress((void**)&p_hp, g_hp);
    cudaGetSymbolAddress((void**)&p_cp, g_cp);

    float* outp = (float*)d_out;
    const size_t osz = (size_t)Bv * Tv * Vv;
    const size_t wsz = (size_t)Bv * Tv * Lv;
    float* wout = ((size_t)out_size >= osz + wsz) ? (outp + osz) : nullptr;

    static int smem_set = 0;
    if (!smem_set) {
        cudaFuncSetAttribute(logits_mma, cudaFuncAttributeMaxDynamicSharedMemorySize,
                             LOGITS_SMEM);
        smem_set = 1;
    }

    // --- step-invariant preprocessing ---
    detect_y_kernel<<<1, 256>>>((const int*)yraw);
    gather_emb_kernel<<<(Tv * Bv * Ev) / 256, 256>>>(yraw, emb);
    mean_kernel<<<(Bv * Fv) / 256, 256>>>(X);
    transB_kernel<<<dim3(Vv / 32, Hv / 32), dim3(32, 8)>>>(out_w);
    skgemm<32, 32><<<dim3(Hv / 32, S_HC), 256>>>(Hv, Fv, S_HC, p_mean, Fv,
                                                 sm_w, nullptr, Fv, Hv, p_hp);
    skgemm<32, 32><<<dim3(Hv / 32, S_HC), 256>>>(Hv, Fv, S_HC, p_mean, Fv,
                                                 lm_w, nullptr, Fv, Hv, p_cp);
    reduce_hc<<<(Bv * Hv) / 256, 256>>>(sm_b, lm_b);
    sgemm_kernel<128, 128, 8, 8, 8><<<dim3((Bv * Lv) / 128, Av / 128), 256>>>(
        Bv * Lv, Av, Fv, X, Fv, fc2_w, Av, p_xenc, Av, fc2_b, nullptr);
    sgemm_kernel<128, 128, 8, 8, 8><<<dim3((Tv * Bv) / 128, G4H / 128), 256>>>(
        Tv * Bv, G4H, Ev, p_embx, Ev, w_ih, G4H, p_embgate, G4H, b_ih, b_hh);

    // --- recurrent loop ---
    for (int t = 0; t < Tv; t++) {
        skgemm<32, 32><<<dim3(Av / 32, S_XD), 256>>>(Av, Hv, S_XD, p_cat + Fv, CAT,
                                                     fc1_w, nullptr, Hv, Av, p_xdp);
        attn_kernel<<<Bv, 256>>>(fc1_b, score_w, score_b, wout, t);
        context_kernel<<<dim3(Fv / 256, Bv), 256>>>(X);
        skgemm<32, 32><<<dim3(G4H / 32, S_GT), 256>>>(G4H, CAT, S_GT, p_cat, CAT,
                                                      w_ih + (size_t)Ev * G4H, w_hh,
                                                      Fv, G4H, p_gatep);
        lstm_fuse<<<(Bv * Hv) / 256, 256>>>(t);
    }

    // --- logits: bf16 hi/lo mma.sync GEMM ---
    convA_kernel<<<(Tv * Bv * Hv) / 256, 256>>>();
    logits_mma<<<dim3(Tv * Bv / 128, Vv / 128), 256, LOGITS_SMEM>>>(out_b, outp);
}

// round 4
// speedup vs baseline: 3.1972x; 1.4747x over previous
#include <cuda_runtime.h>
#include <cuda_fp16.h>
#include <cstdint>

// ---------------- problem constants ----------------
namespace {
constexpr int Bv = 128, Lv = 64, Tv = 20, Vv = 32000;
constexpr int Ev = 512, Hv = 1024, Av = 512, Fv = 2048;
constexpr int G4H = 4 * Hv;          // 4096
constexpr int CAT = Fv + Hv;         // 3072 : [ctx | h]
constexpr int S_XD = 8, S_GT = 4, S_HC = 4;
// mma tile geometry
constexpr int LDT = 40;                 // smem leading dim (fp16), padded conflict-free
constexpr int BUFSZ = 4 * 128 * LDT;    // fp16 units per stage (Ah,Al,Bh,Bl)
constexpr int OFF_AL = 128 * LDT;
constexpr int OFF_BH = 2 * 128 * LDT;
constexpr int OFF_BL = 3 * 128 * LDT;
constexpr int GSMEM = 2 * BUFSZ * 2;    // bytes, double buffered
}

// ---------------- scratch (device globals) ----------------
__device__ float g_mean[Bv * Fv];
__device__ float g_h[Bv * Hv];
__device__ float g_c[Bv * Hv];
__device__ float g_xenc[(size_t)Bv * Lv * Av];
__device__ float g_embgate[(size_t)Tv * Bv * G4H];
__device__ float g_xdp[(size_t)S_XD * Bv * Av];
__device__ float g_gatep[(size_t)S_GT * Bv * G4H];
__device__ float g_hp[(size_t)S_HC * Bv * Hv];
__device__ float g_cp[(size_t)S_HC * Bv * Hv];
// fp16 hi/lo operand arrays
__device__ __half g_Xhi[(size_t)Bv * Lv * Fv];
__device__ __half g_Xlo[(size_t)Bv * Lv * Fv];
__device__ __half g_embxhi[(size_t)Tv * Bv * Ev];
__device__ __half g_embxlo[(size_t)Tv * Bv * Ev];
__device__ __half g_cathi[(size_t)Bv * CAT];
__device__ __half g_catlo[(size_t)Bv * CAT];
__device__ __half g_Hallhi[(size_t)Tv * Bv * Hv];
__device__ __half g_Halllo[(size_t)Tv * Bv * Hv];
__device__ __half g_owThi[(size_t)Vv * Hv];
__device__ __half g_owTlo[(size_t)Vv * Hv];
__device__ __half g_WcatThi[(size_t)G4H * CAT];
__device__ __half g_WcatTlo[(size_t)G4H * CAT];
__device__ __half g_fc2Thi[(size_t)Av * Fv];
__device__ __half g_fc2Tlo[(size_t)Av * Fv];
__device__ __half g_wihEThi[(size_t)G4H * Ev];
__device__ __half g_wihETlo[(size_t)G4H * Ev];
__device__ int g_yflag;

__device__ __forceinline__ float sigmoidf_(float x) { return 1.0f / (1.0f + expf(-x)); }

// ---------------- PTX helpers (plain sm_103-legal features only) ----------------
__device__ __forceinline__ uint32_t smem_u32(const void* p) {
    uint32_t a;
    asm("{ .reg .u64 t; cvta.to.shared.u64 t, %1; cvt.u32.u64 %0, t; }" : "=r"(a) : "l"(p));
    return a;
}
__device__ __forceinline__ void cp16(uint32_t s, const void* g) {
    asm volatile("cp.async.cg.shared.global [%0], [%1], 16;" :: "r"(s), "l"(g));
}
__device__ __forceinline__ void ldsm4(uint32_t& r0, uint32_t& r1, uint32_t& r2,
                                      uint32_t& r3, uint32_t a) {
    asm volatile("ldmatrix.sync.aligned.m8n8.x4.shared.b16 {%0,%1,%2,%3}, [%4];"
                 : "=r"(r0), "=r"(r1), "=r"(r2), "=r"(r3) : "r"(a));
}
__device__ __forceinline__ void mma16816(float* c, const uint32_t* a, const uint32_t* b) {
    asm volatile(
        "mma.sync.aligned.m16n8k16.row.col.f32.f16.f16.f32 "
        "{%0,%1,%2,%3}, {%4,%5,%6,%7}, {%8,%9}, {%0,%1,%2,%3};"
        : "+f"(c[0]), "+f"(c[1]), "+f"(c[2]), "+f"(c[3])
        : "r"(a[0]), "r"(a[1]), "r"(a[2]), "r"(a[3]), "r"(b[0]), "r"(b[1]));
}
__device__ __forceinline__ void split2h(float v, __half& hi, __half& lo) {
    hi = __float2half_rn(v);
    lo = __float2half_rn(v - __half2float(hi));
}

// ---------------- y dtype detector + gather (writes fp16 hi/lo) ----------------
__global__ void detect_y_kernel(const int* __restrict__ y32) {
    __shared__ int ok;
    if (threadIdx.x == 0) ok = 1;
    __syncthreads();
    for (int i = threadIdx.x; i < (Bv * (Tv + 1)) / 2; i += blockDim.x)
        if (y32[2 * i + 1] != 0) ok = 0;
    __syncthreads();
    if (threadIdx.x == 0) g_yflag = ok;
}

__global__ void gather_emb_kernel(const void* __restrict__ yraw,
                                  const float* __restrict__ emb) {
    size_t idx = (size_t)blockIdx.x * blockDim.x + threadIdx.x;
    if (idx >= (size_t)Tv * Bv * Ev) return;
    int e = (int)(idx % Ev);
    int r = (int)(idx / Ev);
    int b = r % Bv, t = r / Bv;
    int token;
    if (g_yflag)
        token = (int)((const long long*)yraw)[(size_t)b * (Tv + 1) + t];
    else
        token = ((const int*)yraw)[(size_t)b * (Tv + 1) + t];
    split2h(emb[(size_t)token * Ev + e], g_embxhi[idx], g_embxlo[idx]);
}

__global__ void mean_kernel(const float* __restrict__ X) {
    int idx = blockIdx.x * blockDim.x + threadIdx.x;
    int f = idx % Fv, b = idx / Fv;
    const float* Xb = X + (size_t)b * Lv * Fv + f;
    float s = 0.f;
#pragma unroll
    for (int l = 0; l < Lv; l++) s += Xb[(size_t)l * Fv];
    g_mean[idx] = s * (1.0f / Lv);
}

__global__ void convX_kernel(const float* __restrict__ X) {
    size_t idx = (size_t)blockIdx.x * blockDim.x + threadIdx.x;
    split2h(X[idx], g_Xhi[idx], g_Xlo[idx]);
}

// ---------------- weight transpose + fp16 hi/lo: src [K,N] -> dst [N,K] ----------------
__global__ void transW_kernel(const float* __restrict__ s1, const float* __restrict__ s2,
                              int Ksplit, int K, int N,
                              __half* __restrict__ dhi, __half* __restrict__ dlo) {
    __shared__ float tile[32][33];
    int n0 = blockIdx.x * 32, k0 = blockIdx.y * 32;
    int tx = threadIdx.x, ty = threadIdx.y;
#pragma unroll
    for (int i = 0; i < 4; i++) {
        int k = k0 + ty + i * 8;
        const float* s = (k < Ksplit) ? (s1 + (size_t)k * N) : (s2 + (size_t)(k - Ksplit) * N);
        tile[ty + i * 8][tx] = s[n0 + tx];
    }
    __syncthreads();
#pragma unroll
    for (int i = 0; i < 4; i++) {
        int n = n0 + ty + i * 8;
        int k = k0 + tx;
        size_t o = (size_t)n * K + k;
        split2h(tile[tx][ty + i * 8], dhi[o], dlo[o]);
    }
}

// ---------------- split-K SIMT GEMM for M=128 (partials out) ----------------
template <int BN, int BK>
__global__ __launch_bounds__(256) void skgemm(
    int N, int K, int S,
    const float* __restrict__ A, int lda,
    const float* __restrict__ B1, int ldb,
    float* __restrict__ Part) {
    __shared__ float As[BK][128 + 4];
    __shared__ float Bs[BK][BN];
    int tid = threadIdx.x;
    int bn0 = blockIdx.x * BN;
    int s = blockIdx.y;
    int Ks = K / S, kbeg = s * Ks, kend = kbeg + Ks;
    int tx = tid & 15, ty = tid >> 4;
    float acc[8][2] = {};
    for (int k0 = kbeg; k0 < kend; k0 += BK) {
#pragma unroll
        for (int it = 0; it < (128 * BK) / 256; it++) {
            int i = tid + it * 256;
            int r = i / BK, c = i % BK;
            As[c][r] = A[(size_t)r * lda + k0 + c];
        }
#pragma unroll
        for (int it = 0; it < (BK * BN) / 256; it++) {
            int i = tid + it * 256;
            int r = i / BN, c = i % BN;
            Bs[r][c] = B1[(size_t)(k0 + r) * ldb + bn0 + c];
        }
        __syncthreads();
#pragma unroll
        for (int kk = 0; kk < BK; kk++) {
            float ar[8], br[2];
#pragma unroll
            for (int i = 0; i < 8; i += 4)
                *reinterpret_cast<float4*>(ar + i) =
                    *reinterpret_cast<const float4*>(&As[kk][ty * 8 + i]);
            br[0] = Bs[kk][tx * 2];
            br[1] = Bs[kk][tx * 2 + 1];
#pragma unroll
            for (int i = 0; i < 8; i++) {
                acc[i][0] = fmaf(ar[i], br[0], acc[i][0]);
                acc[i][1] = fmaf(ar[i], br[1], acc[i][1]);
            }
        }
        __syncthreads();
    }
    float* P = Part + (size_t)s * 128 * N;
#pragma unroll
    for (int i = 0; i < 8; i++) {
        int r = ty * 8 + i;
        P[(size_t)r * N + bn0 + tx * 2] = acc[i][0];
        P[(size_t)r * N + bn0 + tx * 2 + 1] = acc[i][1];
    }
}

// ---------------- reduce h0/c0 ----------------
__global__ void reduce_hc(const float* __restrict__ sm_b, const float* __restrict__ lm_b) {
    int idx = blockIdx.x * blockDim.x + threadIdx.x;
    int b = idx / Hv, j = idx % Hv;
    float h = sm_b[j], c = lm_b[j];
#pragma unroll
    for (int s = 0; s < S_HC; s++) {
        h += g_hp[(size_t)s * Bv * Hv + idx];
        c += g_cp[(size_t)s * Bv * Hv + idx];
    }
    g_h[idx] = h;
    g_c[idx] = c;
    split2h(h, g_cathi[(size_t)b * CAT + Fv + j], g_catlo[(size_t)b * CAT + Fv + j]);
}

// ---------------- fused attention + context ----------------
__global__ void attnctx_kernel(const float* __restrict__ fc1_b,
                               const float* __restrict__ score_w,
                               const float* __restrict__ score_b,
                               const float* __restrict__ X,
                               float* __restrict__ wout, int t) {
    int b = blockIdx.x;
    __shared__ float xd_s[Av];
    __shared__ float sc[Lv];
    __shared__ float al[Lv];
    int tid = threadIdx.x, warp = tid >> 5, lane = tid & 31;
    for (int a = tid; a < Av; a += 256) {
        float s = fc1_b[a];
#pragma unroll
        for (int p = 0; p < S_XD; p++) s += g_xdp[(size_t)p * Bv * Av + b * Av + a];
        xd_s[a] = s;
    }
    __syncthreads();
    for (int l = warp; l < Lv; l += 8) {
        const float* xe = g_xenc + (size_t)(b * Lv + l) * Av;
        float s = 0.f;
        for (int a = lane; a < Av; a += 32) s += tanhf(xe[a] + xd_s[a]) * score_w[a];
#pragma unroll
        for (int o = 16; o; o >>= 1) s += __shfl_xor_sync(0xFFFFFFFFu, s, o);
        if (lane == 0) sc[l] = s + score_b[0];
    }
    __syncthreads();
    __shared__ float smax, ssum;
    if (warp == 0) {
        float m = fmaxf(sc[lane], sc[lane + 32]);
#pragma unroll
        for (int o = 16; o; o >>= 1) m = fmaxf(m, __shfl_xor_sync(0xFFFFFFFFu, m, o));
        float s = expf(sc[lane] - m) + expf(sc[lane + 32] - m);
#pragma unroll
        for (int o = 16; o; o >>= 1) s += __shfl_xor_sync(0xFFFFFFFFu, s, o);
        if (lane == 0) { smax = m; ssum = s; }
    }
    __syncthreads();
    float inv = 1.0f / ssum;
    for (int l = tid; l < Lv; l += 256) {
        float a = expf(sc[l] - smax) * inv;
        al[l] = a;
        if (wout) wout[((size_t)b * Tv + t) * Lv + l] = a;
    }
    __syncthreads();
    // context -> cat[:, :F] as fp16 hi/lo
    for (int f = tid; f < Fv; f += 256) {
        const float* Xb = X + (size_t)b * Lv * Fv + f;
        float s = 0.f;
#pragma unroll
        for (int l = 0; l < Lv; l++) s += al[l] * Xb[(size_t)l * Fv];
        split2h(s, g_cathi[(size_t)b * CAT + f], g_catlo[(size_t)b * CAT + f]);
    }
}

// ---------------- fused gates-reduce + LSTM pointwise ----------------
__global__ void lstm_fuse(int t) {
    int idx = blockIdx.x * blockDim.x + threadIdx.x;
    int b = idx / Hv, j = idx % Hv;
    size_t base = (size_t)b * G4H;
    const float* EG = g_embgate + ((size_t)t * Bv) * G4H + base;
    float ig = EG[j], fg = EG[Hv + j], gg = EG[2 * Hv + j], og = EG[3 * Hv + j];
#pragma unroll
    for (int s = 0; s < S_GT; s++) {
        const float* P = g_gatep + (size_t)s * Bv * G4H + base;
        ig += P[j];
        fg += P[Hv + j];
        gg += P[2 * Hv + j];
        og += P[3 * Hv + j];
    }
    ig = sigmoidf_(ig);
    fg = sigmoidf_(fg);
    og = sigmoidf_(og);
    gg = tanhf(gg);
    float c2 = fg * g_c[idx] + ig * gg;
    float h2 = og * tanhf(c2);
    g_c[idx] = c2;
    g_h[idx] = h2;
    __half hh, hl;
    split2h(h2, hh, hl);
    g_cathi[(size_t)b * CAT + Fv + j] = hh;
    g_catlo[(size_t)b * CAT + Fv + j] = hl;
    size_t hr = ((size_t)t * Bv + b) * Hv + j;
    g_Hallhi[hr] = hh;
    g_Halllo[hr] = hl;
}

// ---------------- generic fp16 hi/lo mma GEMM ----------------
// C[M,N] (tile 128x128) = A @ B^T; A[M, lda] row-major, B[N, ldb] row-major (k-contig).
// PASSES==2: hh + h*lo_B ; PASSES==3: + lo_A*h.
// SPLITK: kbeg = z*Kspan, write fp32 partials at C + z*MN (no bias).
// REMAP: row m = t*Bv+b -> C[(b*Tv+t)*ldc + n] (+bias1).
template <int PASSES, bool SPLITK, bool REMAP>
__global__ void __launch_bounds__(256) gemm_h2(
    int Kspan, int lda, int ldb,
    const __half* __restrict__ Ah, const __half* __restrict__ Al,
    const __half* __restrict__ Bh, const __half* __restrict__ Bl,
    float* __restrict__ C, int ldc, int MN,
    const float* __restrict__ bias1, const float* __restrict__ bias2) {
    extern __shared__ __half smb[];
    const int tid = threadIdx.x, lane = tid & 31, wid = tid >> 5;
    const int wm = wid & 1, wn = wid >> 1;  // 2(M) x 4(N) warps, each 64x32
    const int bm0 = blockIdx.x * 128, bn0 = blockIdx.y * 128;
    const int kbeg = SPLITK ? blockIdx.z * Kspan : 0;
    const uint32_t sbase = smem_u32(smb);

    float acc[4][4][4];
#pragma unroll
    for (int i = 0; i < 4; i++)
#pragma unroll
        for (int j = 0; j < 4; j++)
#pragma unroll
            for (int k = 0; k < 4; k++) acc[i][j][k] = 0.f;

    auto issue = [&](int buf, int kc) {
        const int k0 = kbeg + kc * 32;
#pragma unroll
        for (int j = 0; j < 2; j++) {
            int c = tid + j * 256;
            int r = c >> 2, sg = c & 3;
            uint32_t so = sbase + (uint32_t)(buf * BUFSZ + r * LDT + sg * 8) * 2;
            size_t ga = (size_t)(bm0 + r) * lda + k0 + sg * 8;
            size_t gb = (size_t)(bn0 + r) * ldb + k0 + sg * 8;
            cp16(so, Ah + ga);
            if (PASSES == 3) cp16(so + OFF_AL * 2, Al + ga);
            cp16(so + OFF_BH * 2, Bh + gb);
            cp16(so + OFF_BL * 2, Bl + gb);
        }
        asm volatile("cp.async.commit_group;" ::: "memory");
    };

    const int arow = ((lane >> 3) & 1) * 8 + (lane & 7);
    const int akof = (lane >> 4) * 8;
    const int brow = ((lane >> 4) & 1) * 8 + (lane & 7);
    const int bkof = ((lane >> 3) & 1) * 8;

    const int NKC = Kspan / 32;
    issue(0, 0);
    for (int kc = 0; kc < NKC; kc++) {
        if (kc + 1 < NKC) {
            issue((kc + 1) & 1, kc + 1);
            asm volatile("cp.async.wait_group 1;" ::: "memory");
        } else {
            asm volatile("cp.async.wait_group 0;" ::: "memory");
        }
        __syncthreads();
        const uint32_t bo = sbase + (uint32_t)((kc & 1) * BUFSZ) * 2;
#pragma unroll
        for (int ks = 0; ks < 2; ks++) {
            const int k0 = ks * 16;
            uint32_t bh[4][2], bl[4][2];
#pragma unroll
            for (int p = 0; p < 2; p++) {
                uint32_t ab = bo + (uint32_t)(OFF_BH + (wn * 32 + p * 16 + brow) * LDT + k0 + bkof) * 2;
                ldsm4(bh[2 * p][0], bh[2 * p][1], bh[2 * p + 1][0], bh[2 * p + 1][1], ab);
                ldsm4(bl[2 * p][0], bl[2 * p][1], bl[2 * p + 1][0], bl[2 * p + 1][1],
                      ab + (uint32_t)(OFF_BL - OFF_BH) * 2);
            }
#pragma unroll
            for (int mf = 0; mf < 4; mf++) {
                uint32_t ah[4], al4[4];
                uint32_t aa = bo + (uint32_t)((wm * 64 + mf * 16 + arow) * LDT + k0 + akof) * 2;
                ldsm4(ah[0], ah[1], ah[2], ah[3], aa);
                if (PASSES == 3)
                    ldsm4(al4[0], al4[1], al4[2], al4[3], aa + (uint32_t)OFF_AL * 2);
#pragma unroll
                for (int nf = 0; nf < 4; nf++) {
                    mma16816(acc[mf][nf], ah, bh[nf]);
                    mma16816(acc[mf][nf], ah, bl[nf]);
                    if (PASSES == 3) mma16816(acc[mf][nf], al4, bh[nf]);
                }
            }
        }
        __syncthreads();
    }

    // ---- epilogue ----
#pragma unroll
    for (int mf = 0; mf < 4; mf++) {
#pragma unroll
        for (int half = 0; half < 2; half++) {
            int m = bm0 + wm * 64 + mf * 16 + (lane >> 2) + half * 8;
            float* dst;
            if (REMAP) {
                int tt = m >> 7, bb = m & 127;
                dst = C + ((size_t)bb * Tv + tt) * (size_t)ldc;
            } else if (SPLITK) {
                dst = C + (size_t)blockIdx.z * MN + (size_t)m * ldc;
            } else {
                dst = C + (size_t)m * ldc;
            }
#pragma unroll
            for (int nf = 0; nf < 4; nf++) {
                int n = bn0 + wn * 32 + nf * 8 + (lane & 3) * 2;
                float2 v;
                v.x = acc[mf][nf][half * 2 + 0];
                v.y = acc[mf][nf][half * 2 + 1];
                if (!SPLITK) {
                    if (bias1) { v.x += bias1[n]; v.y += bias1[n + 1]; }
                    if (bias2) { v.x += bias2[n]; v.y += bias2[n + 1]; }
                }
                *reinterpret_cast<float2*>(dst + n) = v;
            }
        }
    }
}

// ---------------- host orchestration ----------------
extern "C" void kernel_launch(void* const* d_in, const int* in_sizes, int n_in,
                              void* d_out, int out_size) {
    const float* X       = (const float*)d_in[0];
    const void*  yraw    = d_in[1];
    const float* emb     = (const float*)d_in[2];
    const float* fc1_w   = (const float*)d_in[3];
    const float* fc1_b   = (const float*)d_in[4];
    const float* fc2_w   = (const float*)d_in[5];
    const float* fc2_b   = (const float*)d_in[6];
    const float* score_w = (const float*)d_in[7];
    const float* score_b = (const float*)d_in[8];
    const float* sm_w    = (const float*)d_in[9];
    const float* sm_b    = (const float*)d_in[10];
    const float* w_ih    = (const float*)d_in[11];
    const float* lm_w    = (const float*)d_in[11];
    // NOTE: keep explicit indexing below (correct order per metadata)
    (void)w_ih;

    const float* lm_w_   = (const float*)d_in[11];
    (void)lm_w; (void)lm_w_;

    // correct explicit bindings:
    const float* p_sm_w  = (const float*)d_in[9];
    const float* p_sm_b  = (const float*)d_in[10];
    const float* p_lm_w  = (const float*)d_in[11];
    const float* p_lm_b  = (const float*)d_in[12];
    const float* p_w_ih  = (const float*)d_in[13];
    const float* p_b_ih  = (const float*)d_in[14];
    const float* p_w_hh  = (const float*)d_in[15];
    const float* p_b_hh  = (const float*)d_in[16];
    const float* p_out_w = (const float*)d_in[17];
    const float* p_out_b = (const float*)d_in[18];

    float *p_mean, *p_h, *p_xenc, *p_embgate, *p_xdp, *p_gatep, *p_hp, *p_cp;
    __half *p_Xhi, *p_Xlo, *p_embxhi, *p_embxlo, *p_cathi, *p_catlo;
    __half *p_Hallhi, *p_Halllo, *p_owThi, *p_owTlo, *p_WcatThi, *p_WcatTlo;
    __half *p_fc2Thi, *p_fc2Tlo, *p_wihEThi, *p_wihETlo;
    cudaGetSymbolAddress((void**)&p_mean, g_mean);
    cudaGetSymbolAddress((void**)&p_h, g_h);
    cudaGetSymbolAddress((void**)&p_xenc, g_xenc);
    cudaGetSymbolAddress((void**)&p_embgate, g_embgate);
    cudaGetSymbolAddress((void**)&p_xdp, g_xdp);
    cudaGetSymbolAddress((void**)&p_gatep, g_gatep);
    cudaGetSymbolAddress((void**)&p_hp, g_hp);
    cudaGetSymbolAddress((void**)&p_cp, g_cp);
    cudaGetSymbolAddress((void**)&p_Xhi, g_Xhi);
    cudaGetSymbolAddress((void**)&p_Xlo, g_Xlo);
    cudaGetSymbolAddress((void**)&p_embxhi, g_embxhi);
    cudaGetSymbolAddress((void**)&p_embxlo, g_embxlo);
    cudaGetSymbolAddress((void**)&p_cathi, g_cathi);
    cudaGetSymbolAddress((void**)&p_catlo, g_catlo);
    cudaGetSymbolAddress((void**)&p_Hallhi, g_Hallhi);
    cudaGetSymbolAddress((void**)&p_Halllo, g_Halllo);
    cudaGetSymbolAddress((void**)&p_owThi, g_owThi);
    cudaGetSymbolAddress((void**)&p_owTlo, g_owTlo);
    cudaGetSymbolAddress((void**)&p_WcatThi, g_WcatThi);
    cudaGetSymbolAddress((void**)&p_WcatTlo, g_WcatTlo);
    cudaGetSymbolAddress((void**)&p_fc2Thi, g_fc2Thi);
    cudaGetSymbolAddress((void**)&p_fc2Tlo, g_fc2Tlo);
    cudaGetSymbolAddress((void**)&p_wihEThi, g_wihEThi);
    cudaGetSymbolAddress((void**)&p_wihETlo, g_wihETlo);

    float* outp = (float*)d_out;
    const size_t osz = (size_t)Bv * Tv * Vv;
    const size_t wsz = (size_t)Bv * Tv * Lv;
    float* wout = ((size_t)out_size >= osz + wsz) ? (outp + osz) : nullptr;

    static int smem_set = 0;
    if (!smem_set) {
        cudaFuncSetAttribute(gemm_h2<2, false, true>,
                             cudaFuncAttributeMaxDynamicSharedMemorySize, GSMEM);
        cudaFuncSetAttribute(gemm_h2<2, false, false>,
                             cudaFuncAttributeMaxDynamicSharedMemorySize, GSMEM);
        cudaFuncSetAttribute(gemm_h2<3, false, false>,
                             cudaFuncAttributeMaxDynamicSharedMemorySize, GSMEM);
        cudaFuncSetAttribute(gemm_h2<3, true, false>,
                             cudaFuncAttributeMaxDynamicSharedMemorySize, GSMEM);
        smem_set = 1;
    }

    // --- step-invariant preprocessing ---
    detect_y_kernel<<<1, 256>>>((const int*)yraw);
    gather_emb_kernel<<<(Tv * Bv * Ev) / 256, 256>>>(yraw, emb);
    mean_kernel<<<(Bv * Fv) / 256, 256>>>(X);
    convX_kernel<<<(int)(((size_t)Bv * Lv * Fv) / 256), 256>>>(X);
    // weight transposes + fp16 hi/lo
    transW_kernel<<<dim3(Vv / 32, Hv / 32), dim3(32, 8)>>>(
        p_out_w, nullptr, Hv, Hv, Vv, p_owThi, p_owTlo);
    transW_kernel<<<dim3(G4H / 32, CAT / 32), dim3(32, 8)>>>(
        p_w_ih + (size_t)Ev * G4H, p_w_hh, Fv, CAT, G4H, p_WcatThi, p_WcatTlo);
    transW_kernel<<<dim3(Av / 32, Fv / 32), dim3(32, 8)>>>(
        fc2_w, nullptr, Fv, Fv, Av, p_fc2Thi, p_fc2Tlo);
    transW_kernel<<<dim3(G4H / 32, Ev / 32), dim3(32, 8)>>>(
        p_w_ih, nullptr, Ev, Ev, G4H, p_wihEThi, p_wihETlo);
    // h0/c0 via fp32 split-K
    skgemm<32, 32><<<dim3(Hv / 32, S_HC), 256>>>(Hv, Fv, S_HC, p_mean, Fv, p_sm_w, Hv, p_hp);
    skgemm<32, 32><<<dim3(Hv / 32, S_HC), 256>>>(Hv, Fv, S_HC, p_mean, Fv, p_lm_w, Hv, p_cp);
    reduce_hc<<<(Bv * Hv) / 256, 256>>>(p_sm_b, p_lm_b);
    // x_enc = X @ fc2_w + fc2_b  (fp16 2-pass mma)
    gemm_h2<2, false, false><<<dim3((Bv * Lv) / 128, Av / 128, 1), 256, GSMEM>>>(
        Fv, Fv, Fv, p_Xhi, p_Xlo, p_fc2Thi, p_fc2Tlo, p_xenc, Av, 0, fc2_b, nullptr);
    // embgate = embx @ w_ih[:E] + b_ih + b_hh  (fp16 3-pass mma)
    gemm_h2<3, false, false><<<dim3((Tv * Bv) / 128, G4H / 128, 1), 256, GSMEM>>>(
        Ev, Ev, Ev, p_embxhi, p_embxlo, p_wihEThi, p_wihETlo, p_embgate, G4H, 0,
        p_b_ih, p_b_hh);

    // --- recurrent loop ---
    for (int t = 0; t < Tv; t++) {
        // xd partials: h @ fc1_w (fp32 split-K)
        skgemm<32, 32><<<dim3(Av / 32, S_XD), 256>>>(Av, Hv, S_XD, p_h, Hv, fc1_w, Av, p_xdp);
        attnctx_kernel<<<Bv, 256>>>(fc1_b, score_w, score_b, X, wout, t);
        // gates partials: [ctx|h] @ Wcat^T  (fp16 3-pass mma, split-K=4)
        gemm_h2<3, true, false><<<dim3(1, G4H / 128, S_GT), 256, GSMEM>>>(
            CAT / S_GT, CAT, CAT, p_cathi, p_catlo, p_WcatThi, p_WcatTlo,
            p_gatep, G4H, Bv * G4H, nullptr, nullptr);
        lstm_fuse<<<(Bv * Hv) / 256, 256>>>(t);
    }

    // --- logits: fp16 2-pass mma, remap epilogue ---
    gemm_h2<2, false, true><<<dim3((Tv * Bv) / 128, Vv / 128, 1), 256, GSMEM>>>(
        Hv, Hv, Hv, p_Hallhi, p_Halllo, p_owThi, p_owTlo, outp, Vv, 0, p_out_b, nullptr);
}

// round 5
// speedup vs baseline: 3.7047x; 1.1587x over previous
#include <cuda_runtime.h>
#include <cuda_fp16.h>
#include <cstdint>

// ---------------- problem constants ----------------
namespace {
constexpr int Bv = 128, Lv = 64, Tv = 20, Vv = 32000;
constexpr int Ev = 512, Hv = 1024, Av = 512, Fv = 2048;
constexpr int G4H = 4 * Hv;          // 4096
constexpr int CAT = Fv + Hv;         // 3072 : [ctx | h]
constexpr int S_XD = 8, S_GT = 4, S_HC = 4;
constexpr int LDT = 40;              // smem leading dim (fp16), conflict-free pad
}

// ---------------- scratch (device globals) ----------------
__device__ float g_mean[Bv * Fv];
__device__ float g_h[Bv * Hv];
__device__ float g_c[Bv * Hv];
__device__ float g_xenc[(size_t)Bv * Lv * Av];
__device__ float g_embgate[(size_t)Tv * Bv * G4H];
__device__ float g_xdp[(size_t)S_XD * Bv * Av];
__device__ float g_gatep[(size_t)S_GT * Bv * G4H];
__device__ float g_hp[(size_t)S_HC * Bv * Hv];
__device__ float g_cp[(size_t)S_HC * Bv * Hv];
// fp16 operands (hi everywhere; lo only for weight-correction passes)
__device__ __half g_Xhi[(size_t)Bv * Lv * Fv];
__device__ __half g_embxhi[(size_t)Tv * Bv * Ev];
__device__ __half g_cathi[(size_t)Bv * CAT];
__device__ __half g_Hallhi[(size_t)Tv * Bv * Hv];
__device__ __half g_owThi[(size_t)Vv * Hv];
__device__ __half g_WcatThi[(size_t)G4H * CAT];
__device__ __half g_WcatTlo[(size_t)G4H * CAT];
__device__ __half g_fc2Thi[(size_t)Av * Fv];
__device__ __half g_fc2Tlo[(size_t)Av * Fv];
__device__ __half g_wihEThi[(size_t)G4H * Ev];
__device__ __half g_wihETlo[(size_t)G4H * Ev];
__device__ int g_yflag;

__device__ __forceinline__ float sigmoidf_(float x) { return 1.0f / (1.0f + expf(-x)); }

// FFMA-only fast reciprocal (bit-trick seed + 2 Newton): rel err ~6e-6
__device__ __forceinline__ float rcp_fast(float d) {
    float r = __int_as_float(0x7EF311C3 - __float_as_int(d));
    r = r * (2.0f - d * r);
    r = r * (2.0f - d * r);
    return r;
}
// Pade(7,6) tanh, clamped; max abs err ~1.2e-4 near |x|=5. No MUFU, no div.
__device__ __forceinline__ float tanh_fast(float x) {
    x = fminf(fmaxf(x, -4.97f), 4.97f);
    float x2 = x * x;
    float num = x * (135135.f + x2 * (17325.f + x2 * (378.f + x2)));
    float den = 135135.f + x2 * (62370.f + x2 * (3150.f + x2 * 28.f));
    return num * rcp_fast(den);
}

// ---------------- PTX helpers (plain sm_103-legal features only) ----------------
__device__ __forceinline__ uint32_t smem_u32(const void* p) {
    uint32_t a;
    asm("{ .reg .u64 t; cvta.to.shared.u64 t, %1; cvt.u32.u64 %0, t; }" : "=r"(a) : "l"(p));
    return a;
}
__device__ __forceinline__ void cp16(uint32_t s, const void* g) {
    asm volatile("cp.async.cg.shared.global [%0], [%1], 16;" :: "r"(s), "l"(g));
}
__device__ __forceinline__ void ldsm4(uint32_t& r0, uint32_t& r1, uint32_t& r2,
                                      uint32_t& r3, uint32_t a) {
    asm volatile("ldmatrix.sync.aligned.m8n8.x4.shared.b16 {%0,%1,%2,%3}, [%4];"
                 : "=r"(r0), "=r"(r1), "=r"(r2), "=r"(r3) : "r"(a));
}
__device__ __forceinline__ void mma16816(float* c, const uint32_t* a, const uint32_t* b) {
    asm volatile(
        "mma.sync.aligned.m16n8k16.row.col.f32.f16.f16.f32 "
        "{%0,%1,%2,%3}, {%4,%5,%6,%7}, {%8,%9}, {%0,%1,%2,%3};"
        : "+f"(c[0]), "+f"(c[1]), "+f"(c[2]), "+f"(c[3])
        : "r"(a[0]), "r"(a[1]), "r"(a[2]), "r"(a[3]), "r"(b[0]), "r"(b[1]));
}
__device__ __forceinline__ void split2h(float v, __half& hi, __half& lo) {
    hi = __float2half_rn(v);
    lo = __float2half_rn(v - __half2float(hi));
}

// ---------------- y dtype detector + gather ----------------
__global__ void detect_y_kernel(const int* __restrict__ y32) {
    __shared__ int ok;
    if (threadIdx.x == 0) ok = 1;
    __syncthreads();
    for (int i = threadIdx.x; i < (Bv * (Tv + 1)) / 2; i += blockDim.x)
        if (y32[2 * i + 1] != 0) ok = 0;
    __syncthreads();
    if (threadIdx.x == 0) g_yflag = ok;
}

__global__ void gather_emb_kernel(const void* __restrict__ yraw,
                                  const float* __restrict__ emb) {
    size_t idx = (size_t)blockIdx.x * blockDim.x + threadIdx.x;
    if (idx >= (size_t)Tv * Bv * Ev) return;
    int e = (int)(idx % Ev);
    int r = (int)(idx / Ev);
    int b = r % Bv, t = r / Bv;
    int token;
    if (g_yflag)
        token = (int)((const long long*)yraw)[(size_t)b * (Tv + 1) + t];
    else
        token = ((const int*)yraw)[(size_t)b * (Tv + 1) + t];
    g_embxhi[idx] = __float2half_rn(emb[(size_t)token * Ev + e]);
}

__global__ void mean_kernel(const float* __restrict__ X) {
    int idx = blockIdx.x * blockDim.x + threadIdx.x;
    int f = idx % Fv, b = idx / Fv;
    const float* Xb = X + (size_t)b * Lv * Fv + f;
    float s = 0.f;
#pragma unroll
    for (int l = 0; l < Lv; l++) s += Xb[(size_t)l * Fv];
    g_mean[idx] = s * (1.0f / Lv);
}

// vectorized fp32 -> fp16(hi) conversion of X
__global__ void convX_kernel(const float4* __restrict__ X4) {
    size_t i = (size_t)blockIdx.x * blockDim.x + threadIdx.x;  // over elems/4
    float4 v = X4[i];
    __half2* o = reinterpret_cast<__half2*>(g_Xhi) + 2 * i;
    o[0] = __floats2half2_rn(v.x, v.y);
    o[1] = __floats2half2_rn(v.z, v.w);
}

// ---------------- weight transpose + fp16 hi(/lo): src [K,N] -> dst [N,K] ----------------
__global__ void transW_kernel(const float* __restrict__ s1, const float* __restrict__ s2,
                              int Ksplit, int K, int N,
                              __half* __restrict__ dhi, __half* __restrict__ dlo) {
    __shared__ float tile[32][33];
    int n0 = blockIdx.x * 32, k0 = blockIdx.y * 32;
    int tx = threadIdx.x, ty = threadIdx.y;
#pragma unroll
    for (int i = 0; i < 4; i++) {
        int k = k0 + ty + i * 8;
        const float* s = (k < Ksplit) ? (s1 + (size_t)k * N) : (s2 + (size_t)(k - Ksplit) * N);
        tile[ty + i * 8][tx] = s[n0 + tx];
    }
    __syncthreads();
#pragma unroll
    for (int i = 0; i < 4; i++) {
        int n = n0 + ty + i * 8;
        int k = k0 + tx;
        size_t o = (size_t)n * K + k;
        float v = tile[tx][ty + i * 8];
        __half h = __float2half_rn(v);
        dhi[o] = h;
        if (dlo) dlo[o] = __float2half_rn(v - __half2float(h));
    }
}

// ---------------- split-K SIMT GEMM for M=128 (partials out) ----------------
template <int BN, int BK>
__global__ __launch_bounds__(256) void skgemm(
    int N, int K, int S,
    const float* __restrict__ A, int lda,
    const float* __restrict__ B1, int ldb,
    float* __restrict__ Part) {
    __shared__ float As[BK][128 + 4];
    __shared__ float Bs[BK][BN];
    int tid = threadIdx.x;
    int bn0 = blockIdx.x * BN;
    int s = blockIdx.y;
    int Ks = K / S, kbeg = s * Ks, kend = kbeg + Ks;
    int tx = tid & 15, ty = tid >> 4;
    float acc[8][2] = {};
    for (int k0 = kbeg; k0 < kend; k0 += BK) {
#pragma unroll
        for (int it = 0; it < (128 * BK) / 256; it++) {
            int i = tid + it * 256;
            int r = i / BK, c = i % BK;
            As[c][r] = A[(size_t)r * lda + k0 + c];
        }
#pragma unroll
        for (int it = 0; it < (BK * BN) / 256; it++) {
            int i = tid + it * 256;
            int r = i / BN, c = i % BN;
            Bs[r][c] = B1[(size_t)(k0 + r) * ldb + bn0 + c];
        }
        __syncthreads();
#pragma unroll
        for (int kk = 0; kk < BK; kk++) {
            float ar[8], br[2];
#pragma unroll
            for (int i = 0; i < 8; i += 4)
                *reinterpret_cast<float4*>(ar + i) =
                    *reinterpret_cast<const float4*>(&As[kk][ty * 8 + i]);
            br[0] = Bs[kk][tx * 2];
            br[1] = Bs[kk][tx * 2 + 1];
#pragma unroll
            for (int i = 0; i < 8; i++) {
                acc[i][0] = fmaf(ar[i], br[0], acc[i][0]);
                acc[i][1] = fmaf(ar[i], br[1], acc[i][1]);
            }
        }
        __syncthreads();
    }
    float* P = Part + (size_t)s * 128 * N;
#pragma unroll
    for (int i = 0; i < 8; i++) {
        int r = ty * 8 + i;
        P[(size_t)r * N + bn0 + tx * 2] = acc[i][0];
        P[(size_t)r * N + bn0 + tx * 2 + 1] = acc[i][1];
    }
}

// ---------------- reduce h0/c0 ----------------
__global__ void reduce_hc(const float* __restrict__ sm_b, const float* __restrict__ lm_b) {
    int idx = blockIdx.x * blockDim.x + threadIdx.x;
    int b = idx / Hv, j = idx % Hv;
    float h = sm_b[j], c = lm_b[j];
#pragma unroll
    for (int s = 0; s < S_HC; s++) {
        h += g_hp[(size_t)s * Bv * Hv + idx];
        c += g_cp[(size_t)s * Bv * Hv + idx];
    }
    g_h[idx] = h;
    g_c[idx] = c;
    g_cathi[(size_t)b * CAT + Fv + j] = __float2half_rn(h);
}

// ---------------- fused attention + context ----------------
__global__ void attnctx_kernel(const float* __restrict__ fc1_b,
                               const float* __restrict__ score_w,
                               const float* __restrict__ score_b,
                               const float* __restrict__ X,
                               float* __restrict__ wout, int t) {
    int b = blockIdx.x;
    __shared__ float xd_s[Av];
    __shared__ float sc[Lv];
    __shared__ float al[Lv];
    int tid = threadIdx.x, warp = tid >> 5, lane = tid & 31;
    for (int a = tid; a < Av; a += 256) {
        float s = fc1_b[a];
#pragma unroll
        for (int p = 0; p < S_XD; p++) s += g_xdp[(size_t)p * Bv * Av + b * Av + a];
        xd_s[a] = s;
    }
    __syncthreads();
    for (int l = warp; l < Lv; l += 8) {
        const float* xe = g_xenc + (size_t)(b * Lv + l) * Av;
        float s = 0.f;
        for (int a = lane; a < Av; a += 32) s += tanh_fast(xe[a] + xd_s[a]) * score_w[a];
#pragma unroll
        for (int o = 16; o; o >>= 1) s += __shfl_xor_sync(0xFFFFFFFFu, s, o);
        if (lane == 0) sc[l] = s + score_b[0];
    }
    __syncthreads();
    __shared__ float smax, ssum;
    if (warp == 0) {
        float m = fmaxf(sc[lane], sc[lane + 32]);
#pragma unroll
        for (int o = 16; o; o >>= 1) m = fmaxf(m, __shfl_xor_sync(0xFFFFFFFFu, m, o));
        float s = expf(sc[lane] - m) + expf(sc[lane + 32] - m);
#pragma unroll
        for (int o = 16; o; o >>= 1) s += __shfl_xor_sync(0xFFFFFFFFu, s, o);
        if (lane == 0) { smax = m; ssum = s; }
    }
    __syncthreads();
    float inv = 1.0f / ssum;
    for (int l = tid; l < Lv; l += 256) {
        float a = expf(sc[l] - smax) * inv;
        al[l] = a;
        if (wout) wout[((size_t)b * Tv + t) * Lv + l] = a;
    }
    __syncthreads();
    for (int f = tid; f < Fv; f += 256) {
        const float* Xb = X + (size_t)b * Lv * Fv + f;
        float s = 0.f;
#pragma unroll
        for (int l = 0; l < Lv; l++) s += al[l] * Xb[(size_t)l * Fv];
        g_cathi[(size_t)b * CAT + f] = __float2half_rn(s);
    }
}

// ---------------- fused gates-reduce + LSTM pointwise ----------------
__global__ void lstm_fuse(int t) {
    int idx = blockIdx.x * blockDim.x + threadIdx.x;
    int b = idx / Hv, j = idx % Hv;
    size_t base = (size_t)b * G4H;
    const float* EG = g_embgate + ((size_t)t * Bv) * G4H + base;
    float ig = EG[j], fg = EG[Hv + j], gg = EG[2 * Hv + j], og = EG[3 * Hv + j];
#pragma unroll
    for (int s = 0; s < S_GT; s++) {
        const float* P = g_gatep + (size_t)s * Bv * G4H + base;
        ig += P[j];
        fg += P[Hv + j];
        gg += P[2 * Hv + j];
        og += P[3 * Hv + j];
    }
    ig = sigmoidf_(ig);
    fg = sigmoidf_(fg);
    og = sigmoidf_(og);
    gg = tanhf(gg);
    float c2 = fg * g_c[idx] + ig * gg;
    float h2 = og * tanhf(c2);
    g_c[idx] = c2;
    g_h[idx] = h2;
    __half hh = __float2half_rn(h2);
    g_cathi[(size_t)b * CAT + Fv + j] = hh;
    g_Hallhi[((size_t)t * Bv + b) * Hv + j] = hh;
}

// ---------------- generic fp16 mma GEMM (PASSES = 1 or 2) ----------------
// C[M,N] tile 128x128 = A @ B^T. PASSES==1: Ah*Bh. PASSES==2: + Ah*Bl.
// SPLITK: kbeg = z*Kspan, fp32 partials at C + z*MN (no bias).
// REMAP: row m = t*Bv+b -> C[(b*Tv+t)*ldc + n] (+bias1).
template <int PASSES, bool SPLITK, bool REMAP>
__global__ void __launch_bounds__(256) gemm_h2(
    int Kspan, int lda, int ldb,
    const __half* __restrict__ Ah,
    const __half* __restrict__ Bh, const __half* __restrict__ Bl,
    float* __restrict__ C, int ldc, int MN,
    const float* __restrict__ bias1, const float* __restrict__ bias2) {
    constexpr int NREG = 1 + PASSES;             // Ah + Bh (+Bl)
    constexpr int RBUF = NREG * 128 * LDT;       // fp16 units per stage
    constexpr int OFF_B = 128 * LDT;
    constexpr int OFF_BL2 = 2 * 128 * LDT;
    extern __shared__ __half smb[];
    const int tid = threadIdx.x, lane = tid & 31, wid = tid >> 5;
    const int wm = wid & 1, wn = wid >> 1;  // 2(M) x 4(N) warps, each 64x32
    const int bm0 = blockIdx.x * 128, bn0 = blockIdx.y * 128;
    const int kbeg = SPLITK ? blockIdx.z * Kspan : 0;
    const uint32_t sbase = smem_u32(smb);

    float acc[4][4][4];
#pragma unroll
    for (int i = 0; i < 4; i++)
#pragma unroll
        for (int j = 0; j < 4; j++)
#pragma unroll
            for (int k = 0; k < 4; k++) acc[i][j][k] = 0.f;

    auto issue = [&](int buf, int kc) {
        const int k0 = kbeg + kc * 32;
#pragma unroll
        for (int j = 0; j < 2; j++) {
            int c = tid + j * 256;
            int r = c >> 2, sg = c & 3;
            uint32_t so = sbase + (uint32_t)(buf * RBUF + r * LDT + sg * 8) * 2;
            size_t ga = (size_t)(bm0 + r) * lda + k0 + sg * 8;
            size_t gb = (size_t)(bn0 + r) * ldb + k0 + sg * 8;
            cp16(so, Ah + ga);
            cp16(so + OFF_B * 2, Bh + gb);
            if (PASSES == 2) cp16(so + OFF_BL2 * 2, Bl + gb);
        }
        asm volatile("cp.async.commit_group;" ::: "memory");
    };

    const int arow = ((lane >> 3) & 1) * 8 + (lane & 7);
    const int akof = (lane >> 4) * 8;
    const int brow = ((lane >> 4) & 1) * 8 + (lane & 7);
    const int bkof = ((lane >> 3) & 1) * 8;

    const int NKC = Kspan / 32;
    issue(0, 0);
    for (int kc = 0; kc < NKC; kc++) {
        if (kc + 1 < NKC) {
            issue((kc + 1) & 1, kc + 1);
            asm volatile("cp.async.wait_group 1;" ::: "memory");
        } else {
            asm volatile("cp.async.wait_group 0;" ::: "memory");
        }
        __syncthreads();
        const uint32_t bo = sbase + (uint32_t)((kc & 1) * RBUF) * 2;
#pragma unroll
        for (int ks = 0; ks < 2; ks++) {
            const int k0 = ks * 16;
            uint32_t bh[4][2], bl[4][2];
#pragma unroll
            for (int p = 0; p < 2; p++) {
                uint32_t ab = bo + (uint32_t)(OFF_B + (wn * 32 + p * 16 + brow) * LDT + k0 + bkof) * 2;
                ldsm4(bh[2 * p][0], bh[2 * p][1], bh[2 * p + 1][0], bh[2 * p + 1][1], ab);
                if (PASSES == 2)
                    ldsm4(bl[2 * p][0], bl[2 * p][1], bl[2 * p + 1][0], bl[2 * p + 1][1],
                          ab + (uint32_t)(OFF_BL2 - OFF_B) * 2);
            }
#pragma unroll
            for (int mf = 0; mf < 4; mf++) {
                uint32_t ah[4];
                uint32_t aa = bo + (uint32_t)((wm * 64 + mf * 16 + arow) * LDT + k0 + akof) * 2;
                ldsm4(ah[0], ah[1], ah[2], ah[3], aa);
#pragma unroll
                for (int nf = 0; nf < 4; nf++) {
                    mma16816(acc[mf][nf], ah, bh[nf]);
                    if (PASSES == 2) mma16816(acc[mf][nf], ah, bl[nf]);
                }
            }
        }
        __syncthreads();
    }

    // ---- epilogue ----
#pragma unroll
    for (int mf = 0; mf < 4; mf++) {
#pragma unroll
        for (int half = 0; half < 2; half++) {
            int m = bm0 + wm * 64 + mf * 16 + (lane >> 2) + half * 8;
            float* dst;
            if (REMAP) {
                int tt = m >> 7, bb = m & 127;
                dst = C + ((size_t)bb * Tv + tt) * (size_t)ldc;
            } else if (SPLITK) {
                dst = C + (size_t)blockIdx.z * MN + (size_t)m * ldc;
            } else {
                dst = C + (size_t)m * ldc;
            }
#pragma unroll
            for (int nf = 0; nf < 4; nf++) {
                int n = bn0 + wn * 32 + nf * 8 + (lane & 3) * 2;
                float2 v;
                v.x = acc[mf][nf][half * 2 + 0];
                v.y = acc[mf][nf][half * 2 + 1];
                if (!SPLITK) {
                    if (bias1) { v.x += bias1[n]; v.y += bias1[n + 1]; }
                    if (bias2) { v.x += bias2[n]; v.y += bias2[n + 1]; }
                }
                *reinterpret_cast<float2*>(dst + n) = v;
            }
        }
    }
}

// smem bytes per PASSES variant: (1+P) regions * 128*LDT halfs * 2 stages * 2B
constexpr int SMEM_P1 = 2 * (2 * 128 * LDT) * 2;  // 40960
constexpr int SMEM_P2 = 2 * (3 * 128 * LDT) * 2;  // 61440

// ---------------- host orchestration ----------------
extern "C" void kernel_launch(void* const* d_in, const int* in_sizes, int n_in,
                              void* d_out, int out_size) {
    const float* X       = (const float*)d_in[0];
    const void*  yraw    = d_in[1];
    const float* emb     = (const float*)d_in[2];
    const float* fc1_w   = (const float*)d_in[3];
    const float* fc1_b   = (const float*)d_in[4];
    const float* fc2_w   = (const float*)d_in[5];
    const float* fc2_b   = (const float*)d_in[6];
    const float* score_w = (const float*)d_in[7];
    const float* score_b = (const float*)d_in[8];
    const float* sm_w    = (const float*)d_in[9];
    const float* sm_b    = (const float*)d_in[10];
    const float* lm_w    = (const float*)d_in[11];
    const float* lm_b    = (const float*)d_in[12];
    const float* w_ih    = (const float*)d_in[13];
    const float* b_ih    = (const float*)d_in[14];
    const float* w_hh    = (const float*)d_in[15];
    const float* b_hh    = (const float*)d_in[16];
    const float* out_w   = (const float*)d_in[17];
    const float* out_b   = (const float*)d_in[18];

    float *p_mean, *p_h, *p_xenc, *p_embgate, *p_xdp, *p_gatep, *p_hp, *p_cp;
    __half *p_Xhi, *p_embxhi, *p_cathi, *p_Hallhi, *p_owThi;
    __half *p_WcatThi, *p_WcatTlo, *p_fc2Thi, *p_fc2Tlo, *p_wihEThi, *p_wihETlo;
    cudaGetSymbolAddress((void**)&p_mean, g_mean);
    cudaGetSymbolAddress((void**)&p_h, g_h);
    cudaGetSymbolAddress((void**)&p_xenc, g_xenc);
    cudaGetSymbolAddress((void**)&p_embgate, g_embgate);
    cudaGetSymbolAddress((void**)&p_xdp, g_xdp);
    cudaGetSymbolAddress((void**)&p_gatep, g_gatep);
    cudaGetSymbolAddress((void**)&p_hp, g_hp);
    cudaGetSymbolAddress((void**)&p_cp, g_cp);
    cudaGetSymbolAddress((void**)&p_Xhi, g_Xhi);
    cudaGetSymbolAddress((void**)&p_embxhi, g_embxhi);
    cudaGetSymbolAddress((void**)&p_cathi, g_cathi);
    cudaGetSymbolAddress((void**)&p_Hallhi, g_Hallhi);
    cudaGetSymbolAddress((void**)&p_owThi, g_owThi);
    cudaGetSymbolAddress((void**)&p_WcatThi, g_WcatThi);
    cudaGetSymbolAddress((void**)&p_WcatTlo, g_WcatTlo);
    cudaGetSymbolAddress((void**)&p_fc2Thi, g_fc2Thi);
    cudaGetSymbolAddress((void**)&p_fc2Tlo, g_fc2Tlo);
    cudaGetSymbolAddress((void**)&p_wihEThi, g_wihEThi);
    cudaGetSymbolAddress((void**)&p_wihETlo, g_wihETlo);

    float* outp = (float*)d_out;
    const size_t osz = (size_t)Bv * Tv * Vv;
    const size_t wsz = (size_t)Bv * Tv * Lv;
    float* wout = ((size_t)out_size >= osz + wsz) ? (outp + osz) : nullptr;

    static int smem_set = 0;
    if (!smem_set) {
        cudaFuncSetAttribute(gemm_h2<1, false, true>,
                             cudaFuncAttributeMaxDynamicSharedMemorySize, SMEM_P1);
        cudaFuncSetAttribute(gemm_h2<2, false, false>,
                             cudaFuncAttributeMaxDynamicSharedMemorySize, SMEM_P2);
        cudaFuncSetAttribute(gemm_h2<2, true, false>,
                             cudaFuncAttributeMaxDynamicSharedMemorySize, SMEM_P2);
        smem_set = 1;
    }

    // --- step-invariant preprocessing ---
    detect_y_kernel<<<1, 256>>>((const int*)yraw);
    gather_emb_kernel<<<(Tv * Bv * Ev) / 256, 256>>>(yraw, emb);
    mean_kernel<<<(Bv * Fv) / 256, 256>>>(X);
    convX_kernel<<<(int)(((size_t)Bv * Lv * Fv) / 4 / 256), 256>>>((const float4*)X);
    transW_kernel<<<dim3(Vv / 32, Hv / 32), dim3(32, 8)>>>(
        out_w, nullptr, Hv, Hv, Vv, p_owThi, nullptr);
    transW_kernel<<<dim3(G4H / 32, CAT / 32), dim3(32, 8)>>>(
        w_ih + (size_t)Ev * G4H, w_hh, Fv, CAT, G4H, p_WcatThi, p_WcatTlo);
    transW_kernel<<<dim3(Av / 32, Fv / 32), dim3(32, 8)>>>(
        fc2_w, nullptr, Fv, Fv, Av, p_fc2Thi, p_fc2Tlo);
    transW_kernel<<<dim3(G4H / 32, Ev / 32), dim3(32, 8)>>>(
        w_ih, nullptr, Ev, Ev, G4H, p_wihEThi, p_wihETlo);
    // h0/c0 via fp32 split-K
    skgemm<32, 32><<<dim3(Hv / 32, S_HC), 256>>>(Hv, Fv, S_HC, p_mean, Fv, sm_w, Hv, p_hp);
    skgemm<32, 32><<<dim3(Hv / 32, S_HC), 256>>>(Hv, Fv, S_HC, p_mean, Fv, lm_w, Hv, p_cp);
    reduce_hc<<<(Bv * Hv) / 256, 256>>>(sm_b, lm_b);
    // x_enc = X @ fc2_w + fc2_b  (2-pass: weight-lo correction)
    gemm_h2<2, false, false><<<dim3((Bv * Lv) / 128, Av / 128, 1), 256, SMEM_P2>>>(
        Fv, Fv, Fv, p_Xhi, p_fc2Thi, p_fc2Tlo, p_xenc, Av, 0, fc2_b, nullptr);
    // embgate = embx @ w_ih[:E] + b_ih + b_hh  (2-pass)
    gemm_h2<2, false, false><<<dim3((Tv * Bv) / 128, G4H / 128, 1), 256, SMEM_P2>>>(
        Ev, Ev, Ev, p_embxhi, p_wihEThi, p_wihETlo, p_embgate, G4H, 0, b_ih, b_hh);

    // --- recurrent loop ---
    for (int t = 0; t < Tv; t++) {
        // xd partials: h @ fc1_w (fp32 split-K)
        skgemm<32, 32><<<dim3(Av / 32, S_XD), 256>>>(Av, Hv, S_XD, p_h, Hv, fc1_w, Av, p_xdp);
        attnctx_kernel<<<Bv, 256>>>(fc1_b, score_w, score_b, X, wout, t);
        // gates partials: [ctx|h] @ Wcat^T  (2-pass, split-K=4)
        gemm_h2<2, true, false><<<dim3(1, G4H / 128, S_GT), 256, SMEM_P2>>>(
            CAT / S_GT, CAT, CAT, p_cathi, p_WcatThi, p_WcatTlo,
            p_gatep, G4H, Bv * G4H, nullptr, nullptr);
        lstm_fuse<<<(Bv * Hv) / 256, 256>>>(t);
    }

    // --- logits: 1-pass fp16 mma, remap epilogue ---
    gemm_h2<1, false, true><<<dim3((Tv * Bv) / 128, Vv / 128, 1), 256, SMEM_P1>>>(
        Hv, Hv, Hv, p_Hallhi, p_owThi, nullptr, outp, Vv, 0, out_b, nullptr);
}

// round 6
// speedup vs baseline: 3.7604x; 1.0150x over previous
#include <cuda_runtime.h>
#include <cuda_fp16.h>
#include <cstdint>

// ---------------- problem constants ----------------
namespace {
constexpr int Bv = 128, Lv = 64, Tv = 20, Vv = 32000;
constexpr int Ev = 512, Hv = 1024, Av = 512, Fv = 2048;
constexpr int G4H = 4 * Hv;          // 4096
constexpr int CAT = Fv + Hv;         // 3072 : [ctx | h]
constexpr int S_XD = 8, S_GT = 4, S_HC = 4;
constexpr int LDT = 40;              // smem leading dim (fp16), conflict-free pad
// big logits kernel: 128x256 tile, 3-stage
constexpr int BIG_STG = (128 + 256) * LDT;    // halfs per stage
constexpr int BIG_OFFB = 128 * LDT;
constexpr int SMEM_BIG = 3 * BIG_STG * 2;     // 92160 bytes
constexpr int SMEM_P1 = 2 * (2 * 128 * LDT) * 2;  // 40960
constexpr int SMEM_P2 = 2 * (3 * 128 * LDT) * 2;  // 61440
}

// ---------------- scratch (device globals) ----------------
__device__ float g_mean[Bv * Fv];
__device__ float g_h[Bv * Hv];
__device__ float g_c[Bv * Hv];
__device__ float g_embgate[(size_t)Tv * Bv * G4H];
__device__ float g_xdp[(size_t)S_XD * Bv * Av];
__device__ float g_gatep[(size_t)S_GT * Bv * G4H];
__device__ float g_hp[(size_t)S_HC * Bv * Hv];
__device__ float g_cp[(size_t)S_HC * Bv * Hv];
// fp16 operands
__device__ __half g_Xhi[(size_t)Bv * Lv * Fv];
__device__ __half g_xench[(size_t)Bv * Lv * Av];
__device__ __half g_embxhi[(size_t)Tv * Bv * Ev];
__device__ __half g_cathi[(size_t)Bv * CAT];
__device__ __half g_Hallhi[(size_t)Tv * Bv * Hv];
__device__ __half g_owThi[(size_t)Vv * Hv];
__device__ __half g_WcatThi[(size_t)G4H * CAT];
__device__ __half g_WcatTlo[(size_t)G4H * CAT];
__device__ __half g_fc2Thi[(size_t)Av * Fv];
__device__ __half g_wihEThi[(size_t)G4H * Ev];
__device__ __half g_wihETlo[(size_t)G4H * Ev];
__device__ int g_yflag;

__device__ __forceinline__ float sigmoidf_(float x) { return 1.0f / (1.0f + expf(-x)); }

__device__ __forceinline__ float rcp_fast(float d) {
    float r = __int_as_float(0x7EF311C3 - __float_as_int(d));
    r = r * (2.0f - d * r);
    r = r * (2.0f - d * r);
    return r;
}
__device__ __forceinline__ float tanh_fast(float x) {
    x = fminf(fmaxf(x, -4.97f), 4.97f);
    float x2 = x * x;
    float num = x * (135135.f + x2 * (17325.f + x2 * (378.f + x2)));
    float den = 135135.f + x2 * (62370.f + x2 * (3150.f + x2 * 28.f));
    return num * rcp_fast(den);
}

// ---------------- PTX helpers ----------------
__device__ __forceinline__ uint32_t smem_u32(const void* p) {
    uint32_t a;
    asm("{ .reg .u64 t; cvta.to.shared.u64 t, %1; cvt.u32.u64 %0, t; }" : "=r"(a) : "l"(p));
    return a;
}
__device__ __forceinline__ void cp16(uint32_t s, const void* g) {
    asm volatile("cp.async.cg.shared.global [%0], [%1], 16;" :: "r"(s), "l"(g));
}
__device__ __forceinline__ void ldsm4(uint32_t& r0, uint32_t& r1, uint32_t& r2,
                                      uint32_t& r3, uint32_t a) {
    asm volatile("ldmatrix.sync.aligned.m8n8.x4.shared.b16 {%0,%1,%2,%3}, [%4];"
                 : "=r"(r0), "=r"(r1), "=r"(r2), "=r"(r3) : "r"(a));
}
__device__ __forceinline__ void mma16816(float* c, const uint32_t* a, const uint32_t* b) {
    asm volatile(
        "mma.sync.aligned.m16n8k16.row.col.f32.f16.f16.f32 "
        "{%0,%1,%2,%3}, {%4,%5,%6,%7}, {%8,%9}, {%0,%1,%2,%3};"
        : "+f"(c[0]), "+f"(c[1]), "+f"(c[2]), "+f"(c[3])
        : "r"(a[0]), "r"(a[1]), "r"(a[2]), "r"(a[3]), "r"(b[0]), "r"(b[1]));
}

// ---------------- y dtype detector + gather ----------------
__global__ void detect_y_kernel(const int* __restrict__ y32) {
    __shared__ int ok;
    if (threadIdx.x == 0) ok = 1;
    __syncthreads();
    for (int i = threadIdx.x; i < (Bv * (Tv + 1)) / 2; i += blockDim.x)
        if (y32[2 * i + 1] != 0) ok = 0;
    __syncthreads();
    if (threadIdx.x == 0) g_yflag = ok;
}

__global__ void gather_emb_kernel(const void* __restrict__ yraw,
                                  const float* __restrict__ emb) {
    size_t idx = (size_t)blockIdx.x * blockDim.x + threadIdx.x;
    if (idx >= (size_t)Tv * Bv * Ev) return;
    int e = (int)(idx % Ev);
    int r = (int)(idx / Ev);
    int b = r % Bv, t = r / Bv;
    int token;
    if (g_yflag)
        token = (int)((const long long*)yraw)[(size_t)b * (Tv + 1) + t];
    else
        token = ((const int*)yraw)[(size_t)b * (Tv + 1) + t];
    g_embxhi[idx] = __float2half_rn(emb[(size_t)token * Ev + e]);
}

__global__ void mean_kernel(const float* __restrict__ X) {
    int idx = blockIdx.x * blockDim.x + threadIdx.x;
    int f = idx % Fv, b = idx / Fv;
    const float* Xb = X + (size_t)b * Lv * Fv + f;
    float s = 0.f;
#pragma unroll
    for (int l = 0; l < Lv; l++) s += Xb[(size_t)l * Fv];
    g_mean[idx] = s * (1.0f / Lv);
}

__global__ void convX_kernel(const float4* __restrict__ X4) {
    size_t i = (size_t)blockIdx.x * blockDim.x + threadIdx.x;
    float4 v = X4[i];
    __half2* o = reinterpret_cast<__half2*>(g_Xhi) + 2 * i;
    o[0] = __floats2half2_rn(v.x, v.y);
    o[1] = __floats2half2_rn(v.z, v.w);
}

// ---------------- weight transpose + fp16 hi(/lo): src [K,N] -> dst [N,K] ----------------
__global__ void transW_kernel(const float* __restrict__ s1, const float* __restrict__ s2,
                              int Ksplit, int K, int N,
                              __half* __restrict__ dhi, __half* __restrict__ dlo) {
    __shared__ float tile[32][33];
    int n0 = blockIdx.x * 32, k0 = blockIdx.y * 32;
    int tx = threadIdx.x, ty = threadIdx.y;
#pragma unroll
    for (int i = 0; i < 4; i++) {
        int k = k0 + ty + i * 8;
        const float* s = (k < Ksplit) ? (s1 + (size_t)k * N) : (s2 + (size_t)(k - Ksplit) * N);
        tile[ty + i * 8][tx] = s[n0 + tx];
    }
    __syncthreads();
#pragma unroll
    for (int i = 0; i < 4; i++) {
        int n = n0 + ty + i * 8;
        int k = k0 + tx;
        size_t o = (size_t)n * K + k;
        float v = tile[tx][ty + i * 8];
        __half h = __float2half_rn(v);
        dhi[o] = h;
        if (dlo) dlo[o] = __float2half_rn(v - __half2float(h));
    }
}

// ---------------- split-K SIMT GEMM for M=128 (partials out) ----------------
template <int BN, int BK>
__global__ __launch_bounds__(256) void skgemm(
    int N, int K, int S,
    const float* __restrict__ A, int lda,
    const float* __restrict__ B1, int ldb,
    float* __restrict__ Part) {
    __shared__ float As[BK][128 + 4];
    __shared__ float Bs[BK][BN];
    int tid = threadIdx.x;
    int bn0 = blockIdx.x * BN;
    int s = blockIdx.y;
    int Ks = K / S, kbeg = s * Ks, kend = kbeg + Ks;
    int tx = tid & 15, ty = tid >> 4;
    float acc[8][2] = {};
    for (int k0 = kbeg; k0 < kend; k0 += BK) {
#pragma unroll
        for (int it = 0; it < (128 * BK) / 256; it++) {
            int i = tid + it * 256;
            int r = i / BK, c = i % BK;
            As[c][r] = A[(size_t)r * lda + k0 + c];
        }
#pragma unroll
        for (int it = 0; it < (BK * BN) / 256; it++) {
            int i = tid + it * 256;
            int r = i / BN, c = i % BN;
            Bs[r][c] = B1[(size_t)(k0 + r) * ldb + bn0 + c];
        }
        __syncthreads();
#pragma unroll
        for (int kk = 0; kk < BK; kk++) {
            float ar[8], br[2];
#pragma unroll
            for (int i = 0; i < 8; i += 4)
                *reinterpret_cast<float4*>(ar + i) =
                    *reinterpret_cast<const float4*>(&As[kk][ty * 8 + i]);
            br[0] = Bs[kk][tx * 2];
            br[1] = Bs[kk][tx * 2 + 1];
#pragma unroll
            for (int i = 0; i < 8; i++) {
                acc[i][0] = fmaf(ar[i], br[0], acc[i][0]);
                acc[i][1] = fmaf(ar[i], br[1], acc[i][1]);
            }
        }
        __syncthreads();
    }
    float* P = Part + (size_t)s * 128 * N;
#pragma unroll
    for (int i = 0; i < 8; i++) {
        int r = ty * 8 + i;
        P[(size_t)r * N + bn0 + tx * 2] = acc[i][0];
        P[(size_t)r * N + bn0 + tx * 2 + 1] = acc[i][1];
    }
}

// ---------------- reduce h0/c0 ----------------
__global__ void reduce_hc(const float* __restrict__ sm_b, const float* __restrict__ lm_b) {
    int idx = blockIdx.x * blockDim.x + threadIdx.x;
    int b = idx / Hv, j = idx % Hv;
    float h = sm_b[j], c = lm_b[j];
#pragma unroll
    for (int s = 0; s < S_HC; s++) {
        h += g_hp[(size_t)s * Bv * Hv + idx];
        c += g_cp[(size_t)s * Bv * Hv + idx];
    }
    g_h[idx] = h;
    g_c[idx] = c;
    g_cathi[(size_t)b * CAT + Fv + j] = __float2half_rn(h);
}

// ---------------- fused attention + context (fp16 inputs) ----------------
__global__ void attnctx_kernel(const float* __restrict__ fc1_b,
                               const float* __restrict__ score_w,
                               const float* __restrict__ score_b,
                               float* __restrict__ wout, int t) {
    int b = blockIdx.x;
    __shared__ float xd_s[Av];
    __shared__ float sc[Lv];
    __shared__ float al[Lv];
    int tid = threadIdx.x, warp = tid >> 5, lane = tid & 31;
    for (int a = tid; a < Av; a += 256) {
        float s = fc1_b[a];
#pragma unroll
        for (int p = 0; p < S_XD; p++) s += g_xdp[(size_t)p * Bv * Av + b * Av + a];
        xd_s[a] = s;
    }
    __syncthreads();
    for (int l = warp; l < Lv; l += 8) {
        const __half* xe = g_xench + (size_t)(b * Lv + l) * Av;
        float s = 0.f;
        for (int a = lane; a < Av; a += 32)
            s += tanh_fast(__half2float(xe[a]) + xd_s[a]) * score_w[a];
#pragma unroll
        for (int o = 16; o; o >>= 1) s += __shfl_xor_sync(0xFFFFFFFFu, s, o);
        if (lane == 0) sc[l] = s + score_b[0];
    }
    __syncthreads();
    __shared__ float smax, ssum;
    if (warp == 0) {
        float m = fmaxf(sc[lane], sc[lane + 32]);
#pragma unroll
        for (int o = 16; o; o >>= 1) m = fmaxf(m, __shfl_xor_sync(0xFFFFFFFFu, m, o));
        float s = expf(sc[lane] - m) + expf(sc[lane + 32] - m);
#pragma unroll
        for (int o = 16; o; o >>= 1) s += __shfl_xor_sync(0xFFFFFFFFu, s, o);
        if (lane == 0) { smax = m; ssum = s; }
    }
    __syncthreads();
    float inv = 1.0f / ssum;
    for (int l = tid; l < Lv; l += 256) {
        float a = expf(sc[l] - smax) * inv;
        al[l] = a;
        if (wout) wout[((size_t)b * Tv + t) * Lv + l] = a;
    }
    __syncthreads();
    // context from fp16 X (L2-resident)
    for (int f = tid; f < Fv; f += 256) {
        const __half* Xb = g_Xhi + (size_t)b * Lv * Fv + f;
        float s = 0.f;
#pragma unroll
        for (int l = 0; l < Lv; l++) s += al[l] * __half2float(Xb[(size_t)l * Fv]);
        g_cathi[(size_t)b * CAT + f] = __float2half_rn(s);
    }
}

// ---------------- fused gates-reduce + LSTM pointwise ----------------
__global__ void lstm_fuse(int t) {
    int idx = blockIdx.x * blockDim.x + threadIdx.x;
    int b = idx / Hv, j = idx % Hv;
    size_t base = (size_t)b * G4H;
    const float* EG = g_embgate + ((size_t)t * Bv) * G4H + base;
    float ig = EG[j], fg = EG[Hv + j], gg = EG[2 * Hv + j], og = EG[3 * Hv + j];
#pragma unroll
    for (int s = 0; s < S_GT; s++) {
        const float* P = g_gatep + (size_t)s * Bv * G4H + base;
        ig += P[j];
        fg += P[Hv + j];
        gg += P[2 * Hv + j];
        og += P[3 * Hv + j];
    }
    ig = sigmoidf_(ig);
    fg = sigmoidf_(fg);
    og = sigmoidf_(og);
    gg = tanhf(gg);
    float c2 = fg * g_c[idx] + ig * gg;
    float h2 = og * tanhf(c2);
    g_c[idx] = c2;
    g_h[idx] = h2;
    __half hh = __float2half_rn(h2);
    g_cathi[(size_t)b * CAT + Fv + j] = hh;
    g_Hallhi[((size_t)t * Bv + b) * Hv + j] = hh;
}

// ---------------- generic fp16 mma GEMM 128x128 (PASSES 1/2) ----------------
template <int PASSES, bool SPLITK, bool HOUT>
__global__ void __launch_bounds__(256) gemm_h2(
    int Kspan, int lda, int ldb,
    const __half* __restrict__ Ah,
    const __half* __restrict__ Bh, const __half* __restrict__ Bl,
    void* __restrict__ Cv, int ldc, int MN,
    const float* __restrict__ bias1, const float* __restrict__ bias2) {
    constexpr int NREG = 1 + PASSES;
    constexpr int RBUF = NREG * 128 * LDT;
    constexpr int OFF_B = 128 * LDT;
    constexpr int OFF_BL2 = 2 * 128 * LDT;
    extern __shared__ __half smb[];
    const int tid = threadIdx.x, lane = tid & 31, wid = tid >> 5;
    const int wm = wid & 1, wn = wid >> 1;
    const int bm0 = blockIdx.x * 128, bn0 = blockIdx.y * 128;
    const int kbeg = SPLITK ? blockIdx.z * Kspan : 0;
    const uint32_t sbase = smem_u32(smb);

    float acc[4][4][4];
#pragma unroll
    for (int i = 0; i < 4; i++)
#pragma unroll
        for (int j = 0; j < 4; j++)
#pragma unroll
            for (int k = 0; k < 4; k++) acc[i][j][k] = 0.f;

    auto issue = [&](int buf, int kc) {
        const int k0 = kbeg + kc * 32;
#pragma unroll
        for (int j = 0; j < 2; j++) {
            int c = tid + j * 256;
            int r = c >> 2, sg = c & 3;
            uint32_t so = sbase + (uint32_t)(buf * RBUF + r * LDT + sg * 8) * 2;
            size_t ga = (size_t)(bm0 + r) * lda + k0 + sg * 8;
            size_t gb = (size_t)(bn0 + r) * ldb + k0 + sg * 8;
            cp16(so, Ah + ga);
            cp16(so + OFF_B * 2, Bh + gb);
            if (PASSES == 2) cp16(so + OFF_BL2 * 2, Bl + gb);
        }
        asm volatile("cp.async.commit_group;" ::: "memory");
    };

    const int arow = ((lane >> 3) & 1) * 8 + (lane & 7);
    const int akof = (lane >> 4) * 8;
    const int brow = ((lane >> 4) & 1) * 8 + (lane & 7);
    const int bkof = ((lane >> 3) & 1) * 8;

    const int NKC = Kspan / 32;
    issue(0, 0);
    for (int kc = 0; kc < NKC; kc++) {
        if (kc + 1 < NKC) {
            issue((kc + 1) & 1, kc + 1);
            asm volatile("cp.async.wait_group 1;" ::: "memory");
        } else {
            asm volatile("cp.async.wait_group 0;" ::: "memory");
        }
        __syncthreads();
        const uint32_t bo = sbase + (uint32_t)((kc & 1) * RBUF) * 2;
#pragma unroll
        for (int ks = 0; ks < 2; ks++) {
            const int k0 = ks * 16;
            uint32_t bh[4][2], bl[4][2];
#pragma unroll
            for (int p = 0; p < 2; p++) {
                uint32_t ab = bo + (uint32_t)(OFF_B + (wn * 32 + p * 16 + brow) * LDT + k0 + bkof) * 2;
                ldsm4(bh[2 * p][0], bh[2 * p][1], bh[2 * p + 1][0], bh[2 * p + 1][1], ab);
                if (PASSES == 2)
                    ldsm4(bl[2 * p][0], bl[2 * p][1], bl[2 * p + 1][0], bl[2 * p + 1][1],
                          ab + (uint32_t)(OFF_BL2 - OFF_B) * 2);
            }
#pragma unroll
            for (int mf = 0; mf < 4; mf++) {
                uint32_t ah[4];
                uint32_t aa = bo + (uint32_t)((wm * 64 + mf * 16 + arow) * LDT + k0 + akof) * 2;
                ldsm4(ah[0], ah[1], ah[2], ah[3], aa);
#pragma unroll
                for (int nf = 0; nf < 4; nf++) {
                    mma16816(acc[mf][nf], ah, bh[nf]);
                    if (PASSES == 2) mma16816(acc[mf][nf], ah, bl[nf]);
                }
            }
        }
        __syncthreads();
    }

#pragma unroll
    for (int mf = 0; mf < 4; mf++) {
#pragma unroll
        for (int half = 0; half < 2; half++) {
            int m = bm0 + wm * 64 + mf * 16 + (lane >> 2) + half * 8;
#pragma unroll
            for (int nf = 0; nf < 4; nf++) {
                int n = bn0 + wn * 32 + nf * 8 + (lane & 3) * 2;
                float vx = acc[mf][nf][half * 2 + 0];
                float vy = acc[mf][nf][half * 2 + 1];
                if (!SPLITK) {
                    if (bias1) { vx += bias1[n]; vy += bias1[n + 1]; }
                    if (bias2) { vx += bias2[n]; vy += bias2[n + 1]; }
                }
                if (HOUT) {
                    __half* Ch = (__half*)Cv;
                    *reinterpret_cast<__half2*>(Ch + (size_t)m * ldc + n) =
                        __floats2half2_rn(vx, vy);
                } else {
                    float* Cf = (float*)Cv;
                    size_t off = SPLITK ? ((size_t)blockIdx.z * MN + (size_t)m * ldc + n)
                                        : ((size_t)m * ldc + n);
                    float2 v{vx, vy};
                    *reinterpret_cast<float2*>(Cf + off) = v;
                }
            }
        }
    }
}

// ---------------- big logits GEMM: 128x256 tile, 512 thr, 3-stage ----------------
__global__ void __launch_bounds__(512) gemm_big(
    const __half* __restrict__ Ah, const __half* __restrict__ Bh,
    const float* __restrict__ bias, float* __restrict__ C) {
    extern __shared__ __half smb[];
    const int tid = threadIdx.x, lane = tid & 31, wid = tid >> 5;
    const int wm = wid & 3, wn = wid >> 2;  // 4(M) x 4(N) warps, each 32x64
    const int bm0 = blockIdx.x * 128, bn0 = blockIdx.y * 256;
    const uint32_t sbase = smem_u32(smb);

    float acc[2][8][4];
#pragma unroll
    for (int i = 0; i < 2; i++)
#pragma unroll
        for (int j = 0; j < 8; j++)
#pragma unroll
            for (int k = 0; k < 4; k++) acc[i][j][k] = 0.f;

    auto issue = [&](int st, int kc) {
        const int k0 = kc * 32;
        {   // A: 512 cp (tid covers it)
            int r = tid >> 2, sg = tid & 3;
            uint32_t so = sbase + (uint32_t)(st * BIG_STG + r * LDT + sg * 8) * 2;
            cp16(so, Ah + (size_t)(bm0 + r) * Hv + k0 + sg * 8);
        }
#pragma unroll
        for (int j = 0; j < 2; j++) {  // B: 1024 cp
            int c = tid + j * 512;
            int r = c >> 2, sg = c & 3;
            uint32_t so = sbase + (uint32_t)(st * BIG_STG + BIG_OFFB + r * LDT + sg * 8) * 2;
            cp16(so, Bh + (size_t)(bn0 + r) * Hv + k0 + sg * 8);
        }
        asm volatile("cp.async.commit_group;" ::: "memory");
    };

    const int arow = ((lane >> 3) & 1) * 8 + (lane & 7);
    const int akof = (lane >> 4) * 8;
    const int brow = ((lane >> 4) & 1) * 8 + (lane & 7);
    const int bkof = ((lane >> 3) & 1) * 8;

    constexpr int NKC = Hv / 32;  // 32
    issue(0, 0);
    issue(1, 1);
    for (int kc = 0; kc < NKC; kc++) {
        if (kc + 1 < NKC)
            asm volatile("cp.async.wait_group 1;" ::: "memory");
        else
            asm volatile("cp.async.wait_group 0;" ::: "memory");
        __syncthreads();
        if (kc + 2 < NKC) issue((kc + 2) % 3, kc + 2);
        const uint32_t bo = sbase + (uint32_t)((kc % 3) * BIG_STG) * 2;
#pragma unroll
        for (int ks = 0; ks < 2; ks++) {
            const int k0 = ks * 16;
            uint32_t bf[8][2];
#pragma unroll
            for (int p = 0; p < 4; p++) {
                uint32_t ab = bo + (uint32_t)(BIG_OFFB + (wn * 64 + p * 16 + brow) * LDT + k0 + bkof) * 2;
                ldsm4(bf[2 * p][0], bf[2 * p][1], bf[2 * p + 1][0], bf[2 * p + 1][1], ab);
            }
#pragma unroll
            for (int mf = 0; mf < 2; mf++) {
                uint32_t ah4[4];
                uint32_t aa = bo + (uint32_t)((wm * 32 + mf * 16 + arow) * LDT + k0 + akof) * 2;
                ldsm4(ah4[0], ah4[1], ah4[2], ah4[3], aa);
#pragma unroll
                for (int nf = 0; nf < 8; nf++) mma16816(acc[mf][nf], ah4, bf[nf]);
            }
        }
    }

    // epilogue: row m = t*Bv+b -> C[(b*Tv+t)*Vv + n] + bias[n]
#pragma unroll
    for (int mf = 0; mf < 2; mf++) {
#pragma unroll
        for (int half = 0; half < 2; half++) {
            int m = bm0 + wm * 32 + mf * 16 + (lane >> 2) + half * 8;
            int tt = m >> 7, bb = m & 127;
            float* dst = C + ((size_t)bb * Tv + tt) * (size_t)Vv;
#pragma unroll
            for (int nf = 0; nf < 8; nf++) {
                int n = bn0 + wn * 64 + nf * 8 + (lane & 3) * 2;
                float2 v;
                v.x = acc[mf][nf][half * 2 + 0] + bias[n];
                v.y = acc[mf][nf][half * 2 + 1] + bias[n + 1];
                *reinterpret_cast<float2*>(dst + n) = v;
            }
        }
    }
}

// ---------------- host orchestration ----------------
extern "C" void kernel_launch(void* const* d_in, const int* in_sizes, int n_in,
                              void* d_out, int out_size) {
    const float* X       = (const float*)d_in[0];
    const void*  yraw    = d_in[1];
    const float* emb     = (const float*)d_in[2];
    const float* fc1_w   = (const float*)d_in[3];
    const float* fc1_b   = (const float*)d_in[4];
    const float* fc2_w   = (const float*)d_in[5];
    const float* fc2_b   = (const float*)d_in[6];
    const float* score_w = (const float*)d_in[7];
    const float* score_b = (const float*)d_in[8];
    const float* sm_w    = (const float*)d_in[9];
    const float* sm_b    = (const float*)d_in[10];
    const float* lm_w    = (const float*)d_in[11];
    const float* lm_b    = (const float*)d_in[12];
    const float* w_ih    = (const float*)d_in[13];
    const float* b_ih    = (const float*)d_in[14];
    const float* w_hh    = (const float*)d_in[15];
    const float* b_hh    = (const float*)d_in[16];
    const float* out_w   = (const float*)d_in[17];
    const float* out_b   = (const float*)d_in[18];

    float *p_mean, *p_h, *p_embgate, *p_xdp, *p_gatep, *p_hp, *p_cp;
    __half *p_embxhi, *p_cathi, *p_Hallhi, *p_owThi, *p_xench;
    __half *p_WcatThi, *p_WcatTlo, *p_fc2Thi, *p_wihEThi, *p_wihETlo, *p_Xhi;
    cudaGetSymbolAddress((void**)&p_mean, g_mean);
    cudaGetSymbolAddress((void**)&p_h, g_h);
    cudaGetSymbolAddress((void**)&p_embgate, g_embgate);
    cudaGetSymbolAddress((void**)&p_xdp, g_xdp);
    cudaGetSymbolAddress((void**)&p_gatep, g_gatep);
    cudaGetSymbolAddress((void**)&p_hp, g_hp);
    cudaGetSymbolAddress((void**)&p_cp, g_cp);
    cudaGetSymbolAddress((void**)&p_embxhi, g_embxhi);
    cudaGetSymbolAddress((void**)&p_cathi, g_cathi);
    cudaGetSymbolAddress((void**)&p_Hallhi, g_Hallhi);
    cudaGetSymbolAddress((void**)&p_owThi, g_owThi);
    cudaGetSymbolAddress((void**)&p_xench, g_xench);
    cudaGetSymbolAddress((void**)&p_WcatThi, g_WcatThi);
    cudaGetSymbolAddress((void**)&p_WcatTlo, g_WcatTlo);
    cudaGetSymbolAddress((void**)&p_fc2Thi, g_fc2Thi);
    cudaGetSymbolAddress((void**)&p_wihEThi, g_wihEThi);
    cudaGetSymbolAddress((void**)&p_wihETlo, g_wihETlo);
    cudaGetSymbolAddress((void**)&p_Xhi, g_Xhi);

    float* outp = (float*)d_out;
    const size_t osz = (size_t)Bv * Tv * Vv;
    const size_t wsz = (size_t)Bv * Tv * Lv;
    float* wout = ((size_t)out_size >= osz + wsz) ? (outp + osz) : nullptr;

    static int smem_set = 0;
    if (!smem_set) {
        cudaFuncSetAttribute(gemm_big, cudaFuncAttributeMaxDynamicSharedMemorySize, SMEM_BIG);
        cudaFuncSetAttribute(gemm_h2<1, false, true>,
                             cudaFuncAttributeMaxDynamicSharedMemorySize, SMEM_P1);
        cudaFuncSetAttribute(gemm_h2<2, false, false>,
                             cudaFuncAttributeMaxDynamicSharedMemorySize, SMEM_P2);
        cudaFuncSetAttribute(gemm_h2<2, true, false>,
                             cudaFuncAttributeMaxDynamicSharedMemorySize, SMEM_P2);
        smem_set = 1;
    }

    // --- step-invariant preprocessing ---
    detect_y_kernel<<<1, 256>>>((const int*)yraw);
    gather_emb_kernel<<<(Tv * Bv * Ev) / 256, 256>>>(yraw, emb);
    mean_kernel<<<(Bv * Fv) / 256, 256>>>(X);
    convX_kernel<<<(int)(((size_t)Bv * Lv * Fv) / 4 / 256), 256>>>((const float4*)X);
    transW_kernel<<<dim3(Vv / 32, Hv / 32), dim3(32, 8)>>>(
        out_w, nullptr, Hv, Hv, Vv, p_owThi, nullptr);
    transW_kernel<<<dim3(G4H / 32, CAT / 32), dim3(32, 8)>>>(
        w_ih + (size_t)Ev * G4H, w_hh, Fv, CAT, G4H, p_WcatThi, p_WcatTlo);
    transW_kernel<<<dim3(Av / 32, Fv / 32), dim3(32, 8)>>>(
        fc2_w, nullptr, Fv, Fv, Av, p_fc2Thi, nullptr);
    transW_kernel<<<dim3(G4H / 32, Ev / 32), dim3(32, 8)>>>(
        w_ih, nullptr, Ev, Ev, G4H, p_wihEThi, p_wihETlo);
    // h0/c0 via fp32 split-K
    skgemm<32, 32><<<dim3(Hv / 32, S_HC), 256>>>(Hv, Fv, S_HC, p_mean, Fv, sm_w, Hv, p_hp);
    skgemm<32, 32><<<dim3(Hv / 32, S_HC), 256>>>(Hv, Fv, S_HC, p_mean, Fv, lm_w, Hv, p_cp);
    reduce_hc<<<(Bv * Hv) / 256, 256>>>(sm_b, lm_b);
    // x_enc = X @ fc2_w + fc2_b  (1-pass, fp16 output)
    gemm_h2<1, false, true><<<dim3((Bv * Lv) / 128, Av / 128, 1), 256, SMEM_P1>>>(
        Fv, Fv, Fv, p_Xhi, p_fc2Thi, nullptr, p_xench, Av, 0, fc2_b, nullptr);
    // embgate = embx @ w_ih[:E] + b_ih + b_hh  (2-pass, fp32 out)
    gemm_h2<2, false, false><<<dim3((Tv * Bv) / 128, G4H / 128, 1), 256, SMEM_P2>>>(
        Ev, Ev, Ev, p_embxhi, p_wihEThi, p_wihETlo, p_embgate, G4H, 0, b_ih, b_hh);

    // --- recurrent loop ---
    for (int t = 0; t < Tv; t++) {
        skgemm<32, 32><<<dim3(Av / 32, S_XD), 256>>>(Av, Hv, S_XD, p_h, Hv, fc1_w, Av, p_xdp);
        attnctx_kernel<<<Bv, 256>>>(fc1_b, score_w, score_b, wout, t);
        gemm_h2<2, true, false><<<dim3(1, G4H / 128, S_GT), 256, SMEM_P2>>>(
            CAT / S_GT, CAT, CAT, p_cathi, p_WcatThi, p_WcatTlo,
            p_gatep, G4H, Bv * G4H, nullptr, nullptr);
        lstm_fuse<<<(Bv * Hv) / 256, 256>>>(t);
    }

    // --- logits: 1-pass fp16 128x256 3-stage mma, remap epilogue ---
    gemm_big<<<dim3(Tv * Bv / 128, Vv / 256), 512, SMEM_BIG>>>(
        p_Hallhi, p_owThi, out_b, outp);
}

// round 7
// speedup vs baseline: 5.4290x; 1.4437x over previous
#include <cuda_runtime.h>
#include <cuda_fp16.h>
#include <cstdint>

// ---------------- problem constants ----------------
namespace {
constexpr int Bv = 128, Lv = 64, Tv = 20, Vv = 32000;
constexpr int Ev = 512, Hv = 1024, Av = 512, Fv = 2048;
constexpr int G4H = 4 * Hv;          // 4096
constexpr int CAT = Fv + Hv;         // 3072 : [ctx | h]
constexpr int S_XD = 8, S_GT = 4, S_HC = 4;
constexpr int LDT = 40;              // smem leading dim (fp16), conflict-free pad
constexpr int NBLK = 128;            // persistent loop grid
// big logits kernel: 128x256 tile, 3-stage
constexpr int BIG_STG = (128 + 256) * LDT;
constexpr int BIG_OFFB = 128 * LDT;
constexpr int SMEM_BIG = 3 * BIG_STG * 2;         // 92160 bytes
constexpr int SMEM_P1 = 2 * (2 * 128 * LDT) * 2;  // 40960
constexpr int SMEM_P2 = 2 * (3 * 128 * LDT) * 2;  // 61440
constexpr int SMEM_LOOP = SMEM_P2;                // 61440 (covers all phases)
}

// ---------------- scratch (device globals) ----------------
__device__ float g_mean[Bv * Fv];
__device__ float g_h[Bv * Hv];
__device__ float g_c[Bv * Hv];
__device__ float g_embgate[(size_t)Tv * Bv * G4H];
__device__ float g_xdp[(size_t)S_XD * Bv * Av];
__device__ float g_gatep[(size_t)S_GT * Bv * G4H];
__device__ float g_hp[(size_t)S_HC * Bv * Hv];
__device__ float g_cp[(size_t)S_HC * Bv * Hv];
__device__ unsigned g_bar;
// fp16 operands
__device__ __half g_Xhi[(size_t)Bv * Lv * Fv];
__device__ __half g_xench[(size_t)Bv * Lv * Av];
__device__ __half g_embxhi[(size_t)Tv * Bv * Ev];
__device__ __half g_cathi[(size_t)Bv * CAT];
__device__ __half g_Hallhi[(size_t)Tv * Bv * Hv];
__device__ __half g_owThi[(size_t)Vv * Hv];
__device__ __half g_WcatThi[(size_t)G4H * CAT];
__device__ __half g_WcatTlo[(size_t)G4H * CAT];
__device__ __half g_fc2Thi[(size_t)Av * Fv];
__device__ __half g_wihEThi[(size_t)G4H * Ev];
__device__ __half g_wihETlo[(size_t)G4H * Ev];
__device__ int g_yflag;

__device__ __forceinline__ float sigmoidf_(float x) { return 1.0f / (1.0f + expf(-x)); }

__device__ __forceinline__ float rcp_fast(float d) {
    float r = __int_as_float(0x7EF311C3 - __float_as_int(d));
    r = r * (2.0f - d * r);
    r = r * (2.0f - d * r);
    return r;
}
__device__ __forceinline__ float tanh_fast(float x) {
    x = fminf(fmaxf(x, -4.97f), 4.97f);
    float x2 = x * x;
    float num = x * (135135.f + x2 * (17325.f + x2 * (378.f + x2)));
    float den = 135135.f + x2 * (62370.f + x2 * (3150.f + x2 * 28.f));
    return num * rcp_fast(den);
}

// ---------------- PTX helpers ----------------
__device__ __forceinline__ uint32_t smem_u32(const void* p) {
    uint32_t a;
    asm("{ .reg .u64 t; cvta.to.shared.u64 t, %1; cvt.u32.u64 %0, t; }" : "=r"(a) : "l"(p));
    return a;
}
__device__ __forceinline__ void cp16(uint32_t s, const void* g) {
    asm volatile("cp.async.cg.shared.global [%0], [%1], 16;" :: "r"(s), "l"(g));
}
__device__ __forceinline__ void ldsm4(uint32_t& r0, uint32_t& r1, uint32_t& r2,
                                      uint32_t& r3, uint32_t a) {
    asm volatile("ldmatrix.sync.aligned.m8n8.x4.shared.b16 {%0,%1,%2,%3}, [%4];"
                 : "=r"(r0), "=r"(r1), "=r"(r2), "=r"(r3) : "r"(a));
}
__device__ __forceinline__ void mma16816(float* c, const uint32_t* a, const uint32_t* b) {
    asm volatile(
        "mma.sync.aligned.m16n8k16.row.col.f32.f16.f16.f32 "
        "{%0,%1,%2,%3}, {%4,%5,%6,%7}, {%8,%9}, {%0,%1,%2,%3};"
        : "+f"(c[0]), "+f"(c[1]), "+f"(c[2]), "+f"(c[3])
        : "r"(a[0]), "r"(a[1]), "r"(a[2]), "r"(a[3]), "r"(b[0]), "r"(b[1]));
}

// grid barrier: monotonic counter, release-arrive + acquire-spin (thread 0 only)
__device__ __forceinline__ void gridbar(unsigned& tgt) {
    __syncthreads();
    if (threadIdx.x == 0) {
        tgt += NBLK;
        __threadfence();
        atomicAdd(&g_bar, 1u);
        unsigned v;
        do {
            asm volatile("ld.acquire.gpu.u32 %0, [%1];" : "=r"(v) : "l"(&g_bar));
            if (v >= tgt) break;
            __nanosleep(32);
        } while (true);
    }
    __syncthreads();
}

__global__ void reset_bar_kernel() { g_bar = 0; }

// ---------------- y dtype detector + gather ----------------
__global__ void detect_y_kernel(const int* __restrict__ y32) {
    __shared__ int ok;
    if (threadIdx.x == 0) ok = 1;
    __syncthreads();
    for (int i = threadIdx.x; i < (Bv * (Tv + 1)) / 2; i += blockDim.x)
        if (y32[2 * i + 1] != 0) ok = 0;
    __syncthreads();
    if (threadIdx.x == 0) g_yflag = ok;
}

__global__ void gather_emb_kernel(const void* __restrict__ yraw,
                                  const float* __restrict__ emb) {
    size_t idx = (size_t)blockIdx.x * blockDim.x + threadIdx.x;
    if (idx >= (size_t)Tv * Bv * Ev) return;
    int e = (int)(idx % Ev);
    int r = (int)(idx / Ev);
    int b = r % Bv, t = r / Bv;
    int token;
    if (g_yflag)
        token = (int)((const long long*)yraw)[(size_t)b * (Tv + 1) + t];
    else
        token = ((const int*)yraw)[(size_t)b * (Tv + 1) + t];
    g_embxhi[idx] = __float2half_rn(emb[(size_t)token * Ev + e]);
}

__global__ void mean_kernel(const float* __restrict__ X) {
    int idx = blockIdx.x * blockDim.x + threadIdx.x;
    int f = idx % Fv, b = idx / Fv;
    const float* Xb = X + (size_t)b * Lv * Fv + f;
    float s = 0.f;
#pragma unroll
    for (int l = 0; l < Lv; l++) s += Xb[(size_t)l * Fv];
    g_mean[idx] = s * (1.0f / Lv);
}

__global__ void convX_kernel(const float4* __restrict__ X4) {
    size_t i = (size_t)blockIdx.x * blockDim.x + threadIdx.x;
    float4 v = X4[i];
    __half2* o = reinterpret_cast<__half2*>(g_Xhi) + 2 * i;
    o[0] = __floats2half2_rn(v.x, v.y);
    o[1] = __floats2half2_rn(v.z, v.w);
}

// ---------------- weight transpose + fp16 hi(/lo) ----------------
__global__ void transW_kernel(const float* __restrict__ s1, const float* __restrict__ s2,
                              int Ksplit, int K, int N,
                              __half* __restrict__ dhi, __half* __restrict__ dlo) {
    __shared__ float tile[32][33];
    int n0 = blockIdx.x * 32, k0 = blockIdx.y * 32;
    int tx = threadIdx.x, ty = threadIdx.y;
#pragma unroll
    for (int i = 0; i < 4; i++) {
        int k = k0 + ty + i * 8;
        const float* s = (k < Ksplit) ? (s1 + (size_t)k * N) : (s2 + (size_t)(k - Ksplit) * N);
        tile[ty + i * 8][tx] = s[n0 + tx];
    }
    __syncthreads();
#pragma unroll
    for (int i = 0; i < 4; i++) {
        int n = n0 + ty + i * 8;
        int k = k0 + tx;
        size_t o = (size_t)n * K + k;
        float v = tile[tx][ty + i * 8];
        __half h = __float2half_rn(v);
        dhi[o] = h;
        if (dlo) dlo[o] = __float2half_rn(v - __half2float(h));
    }
}

// ---------------- split-K SIMT GEMM for M=128 (h0/c0 only) ----------------
template <int BN, int BK>
__global__ __launch_bounds__(256) void skgemm(
    int N, int K, int S,
    const float* __restrict__ A, int lda,
    const float* __restrict__ B1, int ldb,
    float* __restrict__ Part) {
    __shared__ float As[BK][128 + 4];
    __shared__ float Bs[BK][BN];
    int tid = threadIdx.x;
    int bn0 = blockIdx.x * BN;
    int s = blockIdx.y;
    int Ks = K / S, kbeg = s * Ks, kend = kbeg + Ks;
    int tx = tid & 15, ty = tid >> 4;
    float acc[8][2] = {};
    for (int k0 = kbeg; k0 < kend; k0 += BK) {
#pragma unroll
        for (int it = 0; it < (128 * BK) / 256; it++) {
            int i = tid + it * 256;
            int r = i / BK, c = i % BK;
            As[c][r] = A[(size_t)r * lda + k0 + c];
        }
#pragma unroll
        for (int it = 0; it < (BK * BN) / 256; it++) {
            int i = tid + it * 256;
            int r = i / BN, c = i % BN;
            Bs[r][c] = B1[(size_t)(k0 + r) * ldb + bn0 + c];
        }
        __syncthreads();
#pragma unroll
        for (int kk = 0; kk < BK; kk++) {
            float ar[8], br[2];
#pragma unroll
            for (int i = 0; i < 8; i += 4)
                *reinterpret_cast<float4*>(ar + i) =
                    *reinterpret_cast<const float4*>(&As[kk][ty * 8 + i]);
            br[0] = Bs[kk][tx * 2];
            br[1] = Bs[kk][tx * 2 + 1];
#pragma unroll
            for (int i = 0; i < 8; i++) {
                acc[i][0] = fmaf(ar[i], br[0], acc[i][0]);
                acc[i][1] = fmaf(ar[i], br[1], acc[i][1]);
            }
        }
        __syncthreads();
    }
    float* P = Part + (size_t)s * 128 * N;
#pragma unroll
    for (int i = 0; i < 8; i++) {
        int r = ty * 8 + i;
        P[(size_t)r * N + bn0 + tx * 2] = acc[i][0];
        P[(size_t)r * N + bn0 + tx * 2 + 1] = acc[i][1];
    }
}

__global__ void reduce_hc(const float* __restrict__ sm_b, const float* __restrict__ lm_b) {
    int idx = blockIdx.x * blockDim.x + threadIdx.x;
    int b = idx / Hv, j = idx % Hv;
    float h = sm_b[j], c = lm_b[j];
#pragma unroll
    for (int s = 0; s < S_HC; s++) {
        h += g_hp[(size_t)s * Bv * Hv + idx];
        c += g_cp[(size_t)s * Bv * Hv + idx];
    }
    g_h[idx] = h;
    g_c[idx] = c;
    g_cathi[(size_t)b * CAT + Fv + j] = __float2half_rn(h);
}

// ---------------- PERSISTENT recurrent-loop kernel ----------------
// 128 blocks x 256 threads, co-resident; 4 phases per step with grid barriers.
__global__ void __launch_bounds__(256) loop_kernel(
    const float* __restrict__ fc1_w, const float* __restrict__ fc1_b,
    const float* __restrict__ score_w, const float* __restrict__ score_b,
    float* __restrict__ wout) {
    extern __shared__ char smem[];
    const int tid = threadIdx.x, lane = tid & 31, warp = tid >> 5;
    const int blk = blockIdx.x;
    unsigned tgt = 0;

    for (int t = 0; t < Tv; t++) {
        // ---------- P1: xd partials = h @ fc1_w (split-K, SIMT fp32) ----------
        {
            float* As = (float*)smem;            // [32][132]
            float* Bs = As + 32 * 132;           // [32][32]
            const int bn0 = (blk & 15) * 32;
            const int sp = blk >> 4;
            const int kbeg = sp * (Hv / S_XD);
            const int tx = tid & 15, ty = tid >> 4;
            float acc[8][2] = {};
            for (int k0 = kbeg; k0 < kbeg + Hv / S_XD; k0 += 32) {
#pragma unroll
                for (int it = 0; it < 16; it++) {
                    int i = tid + it * 256;
                    int r = i >> 5, c = i & 31;
                    As[c * 132 + r] = g_h[(size_t)r * Hv + k0 + c];
                }
#pragma unroll
                for (int it = 0; it < 4; it++) {
                    int i = tid + it * 256;
                    int r = i >> 5, c = i & 31;
                    Bs[r * 32 + c] = fc1_w[(size_t)(k0 + r) * Av + bn0 + c];
                }
                __syncthreads();
#pragma unroll
                for (int kk = 0; kk < 32; kk++) {
                    float ar[8], br0 = Bs[kk * 32 + tx * 2], br1 = Bs[kk * 32 + tx * 2 + 1];
#pragma unroll
                    for (int i = 0; i < 8; i += 4)
                        *reinterpret_cast<float4*>(ar + i) =
                            *reinterpret_cast<const float4*>(&As[kk * 132 + ty * 8 + i]);
#pragma unroll
                    for (int i = 0; i < 8; i++) {
                        acc[i][0] = fmaf(ar[i], br0, acc[i][0]);
                        acc[i][1] = fmaf(ar[i], br1, acc[i][1]);
                    }
                }
                __syncthreads();
            }
            float* P = g_xdp + (size_t)sp * Bv * Av;
#pragma unroll
            for (int i = 0; i < 8; i++) {
                int r = ty * 8 + i;
                P[(size_t)r * Av + bn0 + tx * 2] = acc[i][0];
                P[(size_t)r * Av + bn0 + tx * 2 + 1] = acc[i][1];
            }
        }
        gridbar(tgt);

        // ---------- P2: attention + softmax + context (block = batch b) ----------
        {
            float* xd_s = (float*)smem;      // 512
            float* sc = xd_s + Av;           // 64
            float* al = sc + Lv;             // 64
            float* red = al + Lv;            // 2 (smax, ssum)
            const int b = blk;
            for (int a = tid; a < Av; a += 256) {
                float s = fc1_b[a];
#pragma unroll
                for (int p = 0; p < S_XD; p++) s += g_xdp[(size_t)p * Bv * Av + b * Av + a];
                xd_s[a] = s;
            }
            __syncthreads();
            for (int l = warp; l < Lv; l += 8) {
                const __half* xe = g_xench + (size_t)(b * Lv + l) * Av;
                float s = 0.f;
                for (int a = lane; a < Av; a += 32)
                    s += tanh_fast(__half2float(xe[a]) + xd_s[a]) * score_w[a];
#pragma unroll
                for (int o = 16; o; o >>= 1) s += __shfl_xor_sync(0xFFFFFFFFu, s, o);
                if (lane == 0) sc[l] = s + score_b[0];
            }
            __syncthreads();
            if (warp == 0) {
                float m = fmaxf(sc[lane], sc[lane + 32]);
#pragma unroll
                for (int o = 16; o; o >>= 1) m = fmaxf(m, __shfl_xor_sync(0xFFFFFFFFu, m, o));
                float s = expf(sc[lane] - m) + expf(sc[lane + 32] - m);
#pragma unroll
                for (int o = 16; o; o >>= 1) s += __shfl_xor_sync(0xFFFFFFFFu, s, o);
                if (lane == 0) { red[0] = m; red[1] = s; }
            }
            __syncthreads();
            float inv = 1.0f / red[1], smax = red[0];
            for (int l = tid; l < Lv; l += 256) {
                float a = expf(sc[l] - smax) * inv;
                al[l] = a;
                if (wout) wout[((size_t)b * Tv + t) * Lv + l] = a;
            }
            __syncthreads();
            for (int f = tid; f < Fv; f += 256) {
                const __half* Xb = g_Xhi + (size_t)b * Lv * Fv + f;
                float s = 0.f;
#pragma unroll
                for (int l = 0; l < Lv; l++) s += al[l] * __half2float(Xb[(size_t)l * Fv]);
                g_cathi[(size_t)b * CAT + f] = __float2half_rn(s);
            }
        }
        gridbar(tgt);

        // ---------- P3: gates partials = cat @ Wcat^T (2-pass fp16 mma, split-K) ----------
        {
            constexpr int RBUF = 3 * 128 * LDT;
            constexpr int OFF_B = 128 * LDT;
            constexpr int OFF_BL2 = 2 * 128 * LDT;
            constexpr int KSPAN = CAT / S_GT;     // 768
            constexpr int NKC = KSPAN / 32;       // 24
            __half* smb = (__half*)smem;
            const uint32_t sbase = smem_u32(smb);
            const int bn0 = (blk & 31) * 128;
            const int ksp = blk >> 5;
            const int kbeg = ksp * KSPAN;
            const int wm = warp & 1, wn = warp >> 1;
            float acc[4][4][4] = {};
            const int arow = ((lane >> 3) & 1) * 8 + (lane & 7);
            const int akof = (lane >> 4) * 8;
            const int brow = ((lane >> 4) & 1) * 8 + (lane & 7);
            const int bkof = ((lane >> 3) & 1) * 8;

#pragma unroll 1
            for (int kc = 0; kc < NKC + 1; kc++) {
                if (kc < NKC) {  // issue stage kc into buffer kc&1
                    const int k0 = kbeg + kc * 32;
                    const int buf = kc & 1;
#pragma unroll
                    for (int j = 0; j < 2; j++) {
                        int c = tid + j * 256;
                        int r = c >> 2, sg = c & 3;
                        uint32_t so = sbase + (uint32_t)(buf * RBUF + r * LDT + sg * 8) * 2;
                        size_t ga = (size_t)r * CAT + k0 + sg * 8;
                        size_t gb = (size_t)(bn0 + r) * CAT + k0 + sg * 8;
                        cp16(so, g_cathi + ga);
                        cp16(so + OFF_B * 2, g_WcatThi + gb);
                        cp16(so + OFF_BL2 * 2, g_WcatTlo + gb);
                    }
                    asm volatile("cp.async.commit_group;" ::: "memory");
                }
                if (kc == 0) continue;
                if (kc < NKC)
                    asm volatile("cp.async.wait_group 1;" ::: "memory");
                else
                    asm volatile("cp.async.wait_group 0;" ::: "memory");
                __syncthreads();
                const int cc = kc - 1;
                const uint32_t bo = sbase + (uint32_t)((cc & 1) * RBUF) * 2;
#pragma unroll
                for (int ks = 0; ks < 2; ks++) {
                    const int k0 = ks * 16;
                    uint32_t bh[4][2], bl[4][2];
#pragma unroll
                    for (int p = 0; p < 2; p++) {
                        uint32_t ab = bo + (uint32_t)(OFF_B + (wn * 32 + p * 16 + brow) * LDT + k0 + bkof) * 2;
                        ldsm4(bh[2 * p][0], bh[2 * p][1], bh[2 * p + 1][0], bh[2 * p + 1][1], ab);
                        ldsm4(bl[2 * p][0], bl[2 * p][1], bl[2 * p + 1][0], bl[2 * p + 1][1],
                              ab + (uint32_t)(OFF_BL2 - OFF_B) * 2);
                    }
#pragma unroll
                    for (int mf = 0; mf < 4; mf++) {
                        uint32_t ah[4];
                        uint32_t aa = bo + (uint32_t)((wm * 64 + mf * 16 + arow) * LDT + k0 + akof) * 2;
                        ldsm4(ah[0], ah[1], ah[2], ah[3], aa);
#pragma unroll
                        for (int nf = 0; nf < 4; nf++) {
                            mma16816(acc[mf][nf], ah, bh[nf]);
                            mma16816(acc[mf][nf], ah, bl[nf]);
                        }
                    }
                }
                __syncthreads();
            }
            float* P = g_gatep + (size_t)ksp * Bv * G4H;
#pragma unroll
            for (int mf = 0; mf < 4; mf++) {
#pragma unroll
                for (int half = 0; half < 2; half++) {
                    int m = wm * 64 + mf * 16 + (lane >> 2) + half * 8;
#pragma unroll
                    for (int nf = 0; nf < 4; nf++) {
                        int n = bn0 + wn * 32 + nf * 8 + (lane & 3) * 2;
                        float2 v{acc[mf][nf][half * 2 + 0], acc[mf][nf][half * 2 + 1]};
                        *reinterpret_cast<float2*>(P + (size_t)m * G4H + n) = v;
                    }
                }
            }
        }
        gridbar(tgt);

        // ---------- P4: gates reduce + LSTM pointwise ----------
        {
            for (int i = tid; i < (Bv * Hv) / NBLK; i += 256) {
                int idx = blk * ((Bv * Hv) / NBLK) + i;
                int b = idx / Hv, j = idx % Hv;
                size_t base = (size_t)b * G4H;
                const float* EG = g_embgate + ((size_t)t * Bv) * G4H + base;
                float ig = EG[j], fg = EG[Hv + j], gg = EG[2 * Hv + j], og = EG[3 * Hv + j];
#pragma unroll
                for (int s = 0; s < S_GT; s++) {
                    const float* P = g_gatep + (size_t)s * Bv * G4H + base;
                    ig += P[j];
                    fg += P[Hv + j];
                    gg += P[2 * Hv + j];
                    og += P[3 * Hv + j];
                }
                ig = sigmoidf_(ig);
                fg = sigmoidf_(fg);
                og = sigmoidf_(og);
                gg = tanhf(gg);
                float c2 = fg * g_c[idx] + ig * gg;
                float h2 = og * tanhf(c2);
                g_c[idx] = c2;
                g_h[idx] = h2;
                __half hh = __float2half_rn(h2);
                g_cathi[(size_t)b * CAT + Fv + j] = hh;
                g_Hallhi[((size_t)t * Bv + b) * Hv + j] = hh;
            }
        }
        gridbar(tgt);
    }
}

// ---------------- generic fp16 mma GEMM 128x128 (preproc) ----------------
template <int PASSES, bool HOUT>
__global__ void __launch_bounds__(256) gemm_h2(
    int Kspan, int lda, int ldb,
    const __half* __restrict__ Ah,
    const __half* __restrict__ Bh, const __half* __restrict__ Bl,
    void* __restrict__ Cv, int ldc,
    const float* __restrict__ bias1, const float* __restrict__ bias2) {
    constexpr int NREG = 1 + PASSES;
    constexpr int RBUF = NREG * 128 * LDT;
    constexpr int OFF_B = 128 * LDT;
    constexpr int OFF_BL2 = 2 * 128 * LDT;
    extern __shared__ __half smb[];
    const int tid = threadIdx.x, lane = tid & 31, wid = tid >> 5;
    const int wm = wid & 1, wn = wid >> 1;
    const int bm0 = blockIdx.x * 128, bn0 = blockIdx.y * 128;
    const uint32_t sbase = smem_u32(smb);

    float acc[4][4][4];
#pragma unroll
    for (int i = 0; i < 4; i++)
#pragma unroll
        for (int j = 0; j < 4; j++)
#pragma unroll
            for (int k = 0; k < 4; k++) acc[i][j][k] = 0.f;

    auto issue = [&](int buf, int kc) {
        const int k0 = kc * 32;
#pragma unroll
        for (int j = 0; j < 2; j++) {
            int c = tid + j * 256;
            int r = c >> 2, sg = c & 3;
            uint32_t so = sbase + (uint32_t)(buf * RBUF + r * LDT + sg * 8) * 2;
            size_t ga = (size_t)(bm0 + r) * lda + k0 + sg * 8;
            size_t gb = (size_t)(bn0 + r) * ldb + k0 + sg * 8;
            cp16(so, Ah + ga);
            cp16(so + OFF_B * 2, Bh + gb);
            if (PASSES == 2) cp16(so + OFF_BL2 * 2, Bl + gb);
        }
        asm volatile("cp.async.commit_group;" ::: "memory");
    };

    const int arow = ((lane >> 3) & 1) * 8 + (lane & 7);
    const int akof = (lane >> 4) * 8;
    const int brow = ((lane >> 4) & 1) * 8 + (lane & 7);
    const int bkof = ((lane >> 3) & 1) * 8;

    const int NKC = Kspan / 32;
    issue(0, 0);
    for (int kc = 0; kc < NKC; kc++) {
        if (kc + 1 < NKC) {
            issue((kc + 1) & 1, kc + 1);
            asm volatile("cp.async.wait_group 1;" ::: "memory");
        } else {
            asm volatile("cp.async.wait_group 0;" ::: "memory");
        }
        __syncthreads();
        const uint32_t bo = sbase + (uint32_t)((kc & 1) * RBUF) * 2;
#pragma unroll
        for (int ks = 0; ks < 2; ks++) {
            const int k0 = ks * 16;
            uint32_t bh[4][2], bl[4][2];
#pragma unroll
            for (int p = 0; p < 2; p++) {
                uint32_t ab = bo + (uint32_t)(OFF_B + (wn * 32 + p * 16 + brow) * LDT + k0 + bkof) * 2;
                ldsm4(bh[2 * p][0], bh[2 * p][1], bh[2 * p + 1][0], bh[2 * p + 1][1], ab);
                if (PASSES == 2)
                    ldsm4(bl[2 * p][0], bl[2 * p][1], bl[2 * p + 1][0], bl[2 * p + 1][1],
                          ab + (uint32_t)(OFF_BL2 - OFF_B) * 2);
            }
#pragma unroll
            for (int mf = 0; mf < 4; mf++) {
                uint32_t ah[4];
                uint32_t aa = bo + (uint32_t)((wm * 64 + mf * 16 + arow) * LDT + k0 + akof) * 2;
                ldsm4(ah[0], ah[1], ah[2], ah[3], aa);
#pragma unroll
                for (int nf = 0; nf < 4; nf++) {
                    mma16816(acc[mf][nf], ah, bh[nf]);
                    if (PASSES == 2) mma16816(acc[mf][nf], ah, bl[nf]);
                }
            }
        }
        __syncthreads();
    }

#pragma unroll
    for (int mf = 0; mf < 4; mf++) {
#pragma unroll
        for (int half = 0; half < 2; half++) {
            int m = bm0 + wm * 64 + mf * 16 + (lane >> 2) + half * 8;
#pragma unroll
            for (int nf = 0; nf < 4; nf++) {
                int n = bn0 + wn * 32 + nf * 8 + (lane & 3) * 2;
                float vx = acc[mf][nf][half * 2 + 0];
                float vy = acc[mf][nf][half * 2 + 1];
                if (bias1) { vx += bias1[n]; vy += bias1[n + 1]; }
                if (bias2) { vx += bias2[n]; vy += bias2[n + 1]; }
                if (HOUT) {
                    __half* Ch = (__half*)Cv;
                    *reinterpret_cast<__half2*>(Ch + (size_t)m * ldc + n) =
                        __floats2half2_rn(vx, vy);
                } else {
                    float* Cf = (float*)Cv;
                    float2 v{vx, vy};
                    *reinterpret_cast<float2*>(Cf + (size_t)m * ldc + n) = v;
                }
            }
        }
    }
}

// ---------------- big logits GEMM: 128x256 tile, 512 thr, 3-stage ----------------
__global__ void __launch_bounds__(512) gemm_big(
    const __half* __restrict__ Ah, const __half* __restrict__ Bh,
    const float* __restrict__ bias, float* __restrict__ C) {
    extern __shared__ __half smb[];
    const int tid = threadIdx.x, lane = tid & 31, wid = tid >> 5;
    const int wm = wid & 3, wn = wid >> 2;
    const int bm0 = blockIdx.x * 128, bn0 = blockIdx.y * 256;
    const uint32_t sbase = smem_u32(smb);

    float acc[2][8][4];
#pragma unroll
    for (int i = 0; i < 2; i++)
#pragma unroll
        for (int j = 0; j < 8; j++)
#pragma unroll
            for (int k = 0; k < 4; k++) acc[i][j][k] = 0.f;

    auto issue = [&](int st, int kc) {
        const int k0 = kc * 32;
        {
            int r = tid >> 2, sg = tid & 3;
            uint32_t so = sbase + (uint32_t)(st * BIG_STG + r * LDT + sg * 8) * 2;
            cp16(so, Ah + (size_t)(bm0 + r) * Hv + k0 + sg * 8);
        }
#pragma unroll
        for (int j = 0; j < 2; j++) {
            int c = tid + j * 512;
            int r = c >> 2, sg = c & 3;
            uint32_t so = sbase + (uint32_t)(st * BIG_STG + BIG_OFFB + r * LDT + sg * 8) * 2;
            cp16(so, Bh + (size_t)(bn0 + r) * Hv + k0 + sg * 8);
        }
        asm volatile("cp.async.commit_group;" ::: "memory");
    };

    const int arow = ((lane >> 3) & 1) * 8 + (lane & 7);
    const int akof = (lane >> 4) * 8;
    const int brow = ((lane >> 4) & 1) * 8 + (lane & 7);
    const int bkof = ((lane >> 3) & 1) * 8;

    constexpr int NKC = Hv / 32;
    issue(0, 0);
    issue(1, 1);
    for (int kc = 0; kc < NKC; kc++) {
        if (kc + 1 < NKC)
            asm volatile("cp.async.wait_group 1;" ::: "memory");
        else
            asm volatile("cp.async.wait_group 0;" ::: "memory");
        __syncthreads();
        if (kc + 2 < NKC) issue((kc + 2) % 3, kc + 2);
        const uint32_t bo = sbase + (uint32_t)((kc % 3) * BIG_STG) * 2;
#pragma unroll
        for (int ks = 0; ks < 2; ks++) {
            const int k0 = ks * 16;
            uint32_t bf[8][2];
#pragma unroll
            for (int p = 0; p < 4; p++) {
                uint32_t ab = bo + (uint32_t)(BIG_OFFB + (wn * 64 + p * 16 + brow) * LDT + k0 + bkof) * 2;
                ldsm4(bf[2 * p][0], bf[2 * p][1], bf[2 * p + 1][0], bf[2 * p + 1][1], ab);
            }
#pragma unroll
            for (int mf = 0; mf < 2; mf++) {
                uint32_t ah4[4];
                uint32_t aa = bo + (uint32_t)((wm * 32 + mf * 16 + arow) * LDT + k0 + akof) * 2;
                ldsm4(ah4[0], ah4[1], ah4[2], ah4[3], aa);
#pragma unroll
                for (int nf = 0; nf < 8; nf++) mma16816(acc[mf][nf], ah4, bf[nf]);
            }
        }
    }

#pragma unroll
    for (int mf = 0; mf < 2; mf++) {
#pragma unroll
        for (int half = 0; half < 2; half++) {
            int m = bm0 + wm * 32 + mf * 16 + (lane >> 2) + half * 8;
            int tt = m >> 7, bb = m & 127;
            float* dst = C + ((size_t)bb * Tv + tt) * (size_t)Vv;
#pragma unroll
            for (int nf = 0; nf < 8; nf++) {
                int n = bn0 + wn * 64 + nf * 8 + (lane & 3) * 2;
                float2 v;
                v.x = acc[mf][nf][half * 2 + 0] + bias[n];
                v.y = acc[mf][nf][half * 2 + 1] + bias[n + 1];
                *reinterpret_cast<float2*>(dst + n) = v;
            }
        }
    }
}

// ---------------- host orchestration ----------------
extern "C" void kernel_launch(void* const* d_in, const int* in_sizes, int n_in,
                              void* d_out, int out_size) {
    const float* X       = (const float*)d_in[0];
    const void*  yraw    = d_in[1];
    const float* emb     = (const float*)d_in[2];
    const float* fc1_w   = (const float*)d_in[3];
    const float* fc1_b   = (const float*)d_in[4];
    const float* fc2_w   = (const float*)d_in[5];
    const float* fc2_b   = (const float*)d_in[6];
    const float* score_w = (const float*)d_in[7];
    const float* score_b = (const float*)d_in[8];
    const float* sm_w    = (const float*)d_in[9];
    const float* sm_b    = (const float*)d_in[10];
    const float* lm_w    = (const float*)d_in[11];
    const float* lm_b    = (const float*)d_in[12];
    const float* w_ih    = (const float*)d_in[13];
    const float* b_ih    = (const float*)d_in[14];
    const float* w_hh    = (const float*)d_in[15];
    const float* b_hh    = (const float*)d_in[16];
    const float* out_w   = (const float*)d_in[17];
    const float* out_b   = (const float*)d_in[18];

    float *p_mean, *p_embgate;
    __half *p_embxhi, *p_Hallhi, *p_owThi, *p_xench;
    __half *p_WcatThi, *p_WcatTlo, *p_fc2Thi, *p_wihEThi, *p_wihETlo, *p_Xhi;
    float *p_hp, *p_cp;
    cudaGetSymbolAddress((void**)&p_mean, g_mean);
    cudaGetSymbolAddress((void**)&p_embgate, g_embgate);
    cudaGetSymbolAddress((void**)&p_hp, g_hp);
    cudaGetSymbolAddress((void**)&p_cp, g_cp);
    cudaGetSymbolAddress((void**)&p_embxhi, g_embxhi);
    cudaGetSymbolAddress((void**)&p_Hallhi, g_Hallhi);
    cudaGetSymbolAddress((void**)&p_owThi, g_owThi);
    cudaGetSymbolAddress((void**)&p_xench, g_xench);
    cudaGetSymbolAddress((void**)&p_WcatThi, g_WcatThi);
    cudaGetSymbolAddress((void**)&p_WcatTlo, g_WcatTlo);
    cudaGetSymbolAddress((void**)&p_fc2Thi, g_fc2Thi);
    cudaGetSymbolAddress((void**)&p_wihEThi, g_wihEThi);
    cudaGetSymbolAddress((void**)&p_wihETlo, g_wihETlo);
    cudaGetSymbolAddress((void**)&p_Xhi, g_Xhi);

    float* outp = (float*)d_out;
    const size_t osz = (size_t)Bv * Tv * Vv;
    const size_t wsz = (size_t)Bv * Tv * Lv;
    float* wout = ((size_t)out_size >= osz + wsz) ? (outp + osz) : nullptr;

    static int smem_set = 0;
    if (!smem_set) {
        cudaFuncSetAttribute(gemm_big, cudaFuncAttributeMaxDynamicSharedMemorySize, SMEM_BIG);
        cudaFuncSetAttribute(loop_kernel, cudaFuncAttributeMaxDynamicSharedMemorySize, SMEM_LOOP);
        cudaFuncSetAttribute(gemm_h2<1, true>,
                             cudaFuncAttributeMaxDynamicSharedMemorySize, SMEM_P1);
        cudaFuncSetAttribute(gemm_h2<2, false>,
                             cudaFuncAttributeMaxDynamicSharedMemorySize, SMEM_P2);
        smem_set = 1;
    }

    // --- step-invariant preprocessing ---
    detect_y_kernel<<<1, 256>>>((const int*)yraw);
    gather_emb_kernel<<<(Tv * Bv * Ev) / 256, 256>>>(yraw, emb);
    mean_kernel<<<(Bv * Fv) / 256, 256>>>(X);
    convX_kernel<<<(int)(((size_t)Bv * Lv * Fv) / 4 / 256), 256>>>((const float4*)X);
    transW_kernel<<<dim3(Vv / 32, Hv / 32), dim3(32, 8)>>>(
        out_w, nullptr, Hv, Hv, Vv, p_owThi, nullptr);
    transW_kernel<<<dim3(G4H / 32, CAT / 32), dim3(32, 8)>>>(
        w_ih + (size_t)Ev * G4H, w_hh, Fv, CAT, G4H, p_WcatThi, p_WcatTlo);
    transW_kernel<<<dim3(Av / 32, Fv / 32), dim3(32, 8)>>>(
        fc2_w, nullptr, Fv, Fv, Av, p_fc2Thi, nullptr);
    transW_kernel<<<dim3(G4H / 32, Ev / 32), dim3(32, 8)>>>(
        w_ih, nullptr, Ev, Ev, G4H, p_wihEThi, p_wihETlo);
    skgemm<32, 32><<<dim3(Hv / 32, S_HC), 256>>>(Hv, Fv, S_HC, p_mean, Fv, sm_w, Hv, p_hp);
    skgemm<32, 32><<<dim3(Hv / 32, S_HC), 256>>>(Hv, Fv, S_HC, p_mean, Fv, lm_w, Hv, p_cp);
    reduce_hc<<<(Bv * Hv) / 256, 256>>>(sm_b, lm_b);
    gemm_h2<1, true><<<dim3((Bv * Lv) / 128, Av / 128), 256, SMEM_P1>>>(
        Fv, Fv, Fv, p_Xhi, p_fc2Thi, nullptr, p_xench, Av, fc2_b, nullptr);
    gemm_h2<2, false><<<dim3((Tv * Bv) / 128, G4H / 128), 256, SMEM_P2>>>(
        Ev, Ev, Ev, p_embxhi, p_wihEThi, p_wihETlo, p_embgate, G4H, b_ih, b_hh);

    // --- persistent recurrent loop (one launch) ---
    reset_bar_kernel<<<1, 1>>>();
    loop_kernel<<<NBLK, 256, SMEM_LOOP>>>(fc1_w, fc1_b, score_w, score_b, wout);

    // --- logits: 1-pass fp16 128x256 3-stage mma, remap epilogue ---
    gemm_big<<<dim3(Tv * Bv / 128, Vv / 256), 512, SMEM_BIG>>>(
        p_Hallhi, p_owThi, out_b, outp);
}

// round 8
// speedup vs baseline: 6.4299x; 1.1844x over previous
#include <cuda_runtime.h>
#include <cuda_fp16.h>
#include <cstdint>

// ---------------- problem constants ----------------
namespace {
constexpr int Bv = 128, Lv = 64, Tv = 20, Vv = 32000;
constexpr int Ev = 512, Hv = 1024, Av = 512, Fv = 2048;
constexpr int G4H = 4 * Hv;          // 4096
constexpr int CAT = Fv + Hv;         // 3072 : [ctx | h]
constexpr int S_XD = 8, S_GT = 4, S_HC = 4;
constexpr int LDT = 40;              // smem leading dim (fp16), conflict-free pad
constexpr int NBLK = 128;            // persistent loop grid
// big logits kernel: 128x256 tile, 3-stage
constexpr int BIG_STG = (128 + 256) * LDT;
constexpr int BIG_OFFB = 128 * LDT;
constexpr int SMEM_BIG = 3 * BIG_STG * 2;         // 92160 bytes
constexpr int SMEM_P1 = 2 * (2 * 128 * LDT) * 2;  // 40960
constexpr int SMEM_LOOP = SMEM_P1;                // loop needs max(P1 smem, mma 2-region)
}

// ---------------- scratch (device globals) ----------------
__device__ float g_mean[Bv * Fv];
__device__ float g_h[Bv * Hv];
__device__ float g_c[Bv * Hv];
__device__ float g_embgate[(size_t)Tv * Bv * G4H];
__device__ float g_xdp[(size_t)S_XD * Bv * Av];
__device__ float g_gatep[(size_t)S_GT * Bv * G4H];
__device__ float g_hp[(size_t)S_HC * Bv * Hv];
__device__ float g_cp[(size_t)S_HC * Bv * Hv];
__device__ unsigned g_bar;
// fp16 operands
__device__ __half g_Xhi[(size_t)Bv * Lv * Fv];
__device__ __half g_xench[(size_t)Bv * Lv * Av];
__device__ __half g_embxhi[(size_t)Tv * Bv * Ev];
__device__ __half g_cathi[(size_t)Bv * CAT];
__device__ __half g_Hallhi[(size_t)Tv * Bv * Hv];
__device__ __half g_owThi[(size_t)Vv * Hv];
__device__ __half g_WcatThi[(size_t)G4H * CAT];
__device__ __half g_fc2Thi[(size_t)Av * Fv];
__device__ __half g_wihEThi[(size_t)G4H * Ev];
__device__ int g_yflag;

__device__ __forceinline__ float sigmoidf_(float x) { return 1.0f / (1.0f + expf(-x)); }

__device__ __forceinline__ float rcp_fast(float d) {
    float r = __int_as_float(0x7EF311C3 - __float_as_int(d));
    r = r * (2.0f - d * r);
    r = r * (2.0f - d * r);
    return r;
}
__device__ __forceinline__ float tanh_fast(float x) {
    x = fminf(fmaxf(x, -4.97f), 4.97f);
    float x2 = x * x;
    float num = x * (135135.f + x2 * (17325.f + x2 * (378.f + x2)));
    float den = 135135.f + x2 * (62370.f + x2 * (3150.f + x2 * 28.f));
    return num * rcp_fast(den);
}

// ---------------- PTX helpers ----------------
__device__ __forceinline__ uint32_t smem_u32(const void* p) {
    uint32_t a;
    asm("{ .reg .u64 t; cvta.to.shared.u64 t, %1; cvt.u32.u64 %0, t; }" : "=r"(a) : "l"(p));
    return a;
}
__device__ __forceinline__ void cp16(uint32_t s, const void* g) {
    asm volatile("cp.async.cg.shared.global [%0], [%1], 16;" :: "r"(s), "l"(g));
}
__device__ __forceinline__ void ldsm4(uint32_t& r0, uint32_t& r1, uint32_t& r2,
                                      uint32_t& r3, uint32_t a) {
    asm volatile("ldmatrix.sync.aligned.m8n8.x4.shared.b16 {%0,%1,%2,%3}, [%4];"
                 : "=r"(r0), "=r"(r1), "=r"(r2), "=r"(r3) : "r"(a));
}
__device__ __forceinline__ void mma16816(float* c, const uint32_t* a, const uint32_t* b) {
    asm volatile(
        "mma.sync.aligned.m16n8k16.row.col.f32.f16.f16.f32 "
        "{%0,%1,%2,%3}, {%4,%5,%6,%7}, {%8,%9}, {%0,%1,%2,%3};"
        : "+f"(c[0]), "+f"(c[1]), "+f"(c[2]), "+f"(c[3])
        : "r"(a[0]), "r"(a[1]), "r"(a[2]), "r"(a[3]), "r"(b[0]), "r"(b[1]));
}

// grid barrier: monotonic counter, release-arrive + acquire-spin (thread 0 only)
__device__ __forceinline__ void gridbar(unsigned& tgt) {
    __syncthreads();
    if (threadIdx.x == 0) {
        tgt += NBLK;
        __threadfence();
        atomicAdd(&g_bar, 1u);
        unsigned v;
        do {
            asm volatile("ld.acquire.gpu.u32 %0, [%1];" : "=r"(v) : "l"(&g_bar));
            if (v >= tgt) break;
            __nanosleep(32);
        } while (true);
    }
    __syncthreads();
}

__global__ void reset_bar_kernel() { g_bar = 0; }

// ---------------- y dtype detector + gather ----------------
__global__ void detect_y_kernel(const int* __restrict__ y32) {
    __shared__ int ok;
    if (threadIdx.x == 0) ok = 1;
    __syncthreads();
    for (int i = threadIdx.x; i < (Bv * (Tv + 1)) / 2; i += blockDim.x)
        if (y32[2 * i + 1] != 0) ok = 0;
    __syncthreads();
    if (threadIdx.x == 0) g_yflag = ok;
}

__global__ void gather_emb_kernel(const void* __restrict__ yraw,
                                  const float* __restrict__ emb) {
    size_t idx = (size_t)blockIdx.x * blockDim.x + threadIdx.x;
    if (idx >= (size_t)Tv * Bv * Ev) return;
    int e = (int)(idx % Ev);
    int r = (int)(idx / Ev);
    int b = r % Bv, t = r / Bv;
    int token;
    if (g_yflag)
        token = (int)((const long long*)yraw)[(size_t)b * (Tv + 1) + t];
    else
        token = ((const int*)yraw)[(size_t)b * (Tv + 1) + t];
    g_embxhi[idx] = __float2half_rn(emb[(size_t)token * Ev + e]);
}

__global__ void mean_kernel(const float* __restrict__ X) {
    int idx = blockIdx.x * blockDim.x + threadIdx.x;
    int f = idx % Fv, b = idx / Fv;
    const float* Xb = X + (size_t)b * Lv * Fv + f;
    float s = 0.f;
#pragma unroll
    for (int l = 0; l < Lv; l++) s += Xb[(size_t)l * Fv];
    g_mean[idx] = s * (1.0f / Lv);
}

__global__ void convX_kernel(const float4* __restrict__ X4) {
    size_t i = (size_t)blockIdx.x * blockDim.x + threadIdx.x;
    float4 v = X4[i];
    __half2* o = reinterpret_cast<__half2*>(g_Xhi) + 2 * i;
    o[0] = __floats2half2_rn(v.x, v.y);
    o[1] = __floats2half2_rn(v.z, v.w);
}

// ---------------- weight transpose + fp16 hi: src [K,N] -> dst [N,K] ----------------
__global__ void transW_kernel(const float* __restrict__ s1, const float* __restrict__ s2,
                              int Ksplit, int K, int N,
                              __half* __restrict__ dhi) {
    __shared__ float tile[32][33];
    int n0 = blockIdx.x * 32, k0 = blockIdx.y * 32;
    int tx = threadIdx.x, ty = threadIdx.y;
#pragma unroll
    for (int i = 0; i < 4; i++) {
        int k = k0 + ty + i * 8;
        const float* s = (k < Ksplit) ? (s1 + (size_t)k * N) : (s2 + (size_t)(k - Ksplit) * N);
        tile[ty + i * 8][tx] = s[n0 + tx];
    }
    __syncthreads();
#pragma unroll
    for (int i = 0; i < 4; i++) {
        int n = n0 + ty + i * 8;
        int k = k0 + tx;
        dhi[(size_t)n * K + k] = __float2half_rn(tile[tx][ty + i * 8]);
    }
}

// ---------------- split-K SIMT GEMM for M=128 (h0/c0 only) ----------------
template <int BN, int BK>
__global__ __launch_bounds__(256) void skgemm(
    int N, int K, int S,
    const float* __restrict__ A, int lda,
    const float* __restrict__ B1, int ldb,
    float* __restrict__ Part) {
    __shared__ float As[BK][128 + 4];
    __shared__ float Bs[BK][BN];
    int tid = threadIdx.x;
    int bn0 = blockIdx.x * BN;
    int s = blockIdx.y;
    int Ks = K / S, kbeg = s * Ks, kend = kbeg + Ks;
    int tx = tid & 15, ty = tid >> 4;
    float acc[8][2] = {};
    for (int k0 = kbeg; k0 < kend; k0 += BK) {
#pragma unroll
        for (int it = 0; it < (128 * BK) / 256; it++) {
            int i = tid + it * 256;
            int r = i / BK, c = i % BK;
            As[c][r] = A[(size_t)r * lda + k0 + c];
        }
#pragma unroll
        for (int it = 0; it < (BK * BN) / 256; it++) {
            int i = tid + it * 256;
            int r = i / BN, c = i % BN;
            Bs[r][c] = B1[(size_t)(k0 + r) * ldb + bn0 + c];
        }
        __syncthreads();
#pragma unroll
        for (int kk = 0; kk < BK; kk++) {
            float ar[8], br[2];
#pragma unroll
            for (int i = 0; i < 8; i += 4)
                *reinterpret_cast<float4*>(ar + i) =
                    *reinterpret_cast<const float4*>(&As[kk][ty * 8 + i]);
            br[0] = Bs[kk][tx * 2];
            br[1] = Bs[kk][tx * 2 + 1];
#pragma unroll
            for (int i = 0; i < 8; i++) {
                acc[i][0] = fmaf(ar[i], br[0], acc[i][0]);
                acc[i][1] = fmaf(ar[i], br[1], acc[i][1]);
            }
        }
        __syncthreads();
    }
    float* P = Part + (size_t)s * 128 * N;
#pragma unroll
    for (int i = 0; i < 8; i++) {
        int r = ty * 8 + i;
        P[(size_t)r * N + bn0 + tx * 2] = acc[i][0];
        P[(size_t)r * N + bn0 + tx * 2 + 1] = acc[i][1];
    }
}

__global__ void reduce_hc(const float* __restrict__ sm_b, const float* __restrict__ lm_b) {
    int idx = blockIdx.x * blockDim.x + threadIdx.x;
    int b = idx / Hv, j = idx % Hv;
    float h = sm_b[j], c = lm_b[j];
#pragma unroll
    for (int s = 0; s < S_HC; s++) {
        h += g_hp[(size_t)s * Bv * Hv + idx];
        c += g_cp[(size_t)s * Bv * Hv + idx];
    }
    g_h[idx] = h;
    g_c[idx] = c;
    g_cathi[(size_t)b * CAT + Fv + j] = __float2half_rn(h);
}

// ---------------- PERSISTENT recurrent-loop kernel ----------------
__global__ void __launch_bounds__(256) loop_kernel(
    const float* __restrict__ fc1_w, const float* __restrict__ fc1_b,
    const float* __restrict__ score_w, const float* __restrict__ score_b,
    float* __restrict__ wout) {
    extern __shared__ char smem[];
    const int tid = threadIdx.x, lane = tid & 31, warp = tid >> 5;
    const int blk = blockIdx.x;
    unsigned tgt = 0;

    for (int t = 0; t < Tv; t++) {
        // ---------- P1: xd partials = h @ fc1_w (split-K, SIMT fp32) ----------
        {
            float* As = (float*)smem;            // [32][132]
            float* Bs = As + 32 * 132;           // [32][32]
            const int bn0 = (blk & 15) * 32;
            const int sp = blk >> 4;
            const int kbeg = sp * (Hv / S_XD);
            const int tx = tid & 15, ty = tid >> 4;
            float acc[8][2] = {};
            for (int k0 = kbeg; k0 < kbeg + Hv / S_XD; k0 += 32) {
#pragma unroll
                for (int it = 0; it < 16; it++) {
                    int i = tid + it * 256;
                    int r = i >> 5, c = i & 31;
                    As[c * 132 + r] = g_h[(size_t)r * Hv + k0 + c];
                }
#pragma unroll
                for (int it = 0; it < 4; it++) {
                    int i = tid + it * 256;
                    int r = i >> 5, c = i & 31;
                    Bs[r * 32 + c] = fc1_w[(size_t)(k0 + r) * Av + bn0 + c];
                }
                __syncthreads();
#pragma unroll
                for (int kk = 0; kk < 32; kk++) {
                    float ar[8], br0 = Bs[kk * 32 + tx * 2], br1 = Bs[kk * 32 + tx * 2 + 1];
#pragma unroll
                    for (int i = 0; i < 8; i += 4)
                        *reinterpret_cast<float4*>(ar + i) =
                            *reinterpret_cast<const float4*>(&As[kk * 132 + ty * 8 + i]);
#pragma unroll
                    for (int i = 0; i < 8; i++) {
                        acc[i][0] = fmaf(ar[i], br0, acc[i][0]);
                        acc[i][1] = fmaf(ar[i], br1, acc[i][1]);
                    }
                }
                __syncthreads();
            }
            float* P = g_xdp + (size_t)sp * Bv * Av;
#pragma unroll
            for (int i = 0; i < 8; i++) {
                int r = ty * 8 + i;
                P[(size_t)r * Av + bn0 + tx * 2] = acc[i][0];
                P[(size_t)r * Av + bn0 + tx * 2 + 1] = acc[i][1];
            }
        }
        gridbar(tgt);

        // ---------- P2: attention + softmax + context (block = batch b) ----------
        {
            float* xd_s = (float*)smem;      // 512
            float* sc = xd_s + Av;           // 64
            float* al = sc + Lv;             // 64
            float* red = al + Lv;            // 2
            const int b = blk;
            for (int a = tid; a < Av; a += 256) {
                float s = fc1_b[a];
#pragma unroll
                for (int p = 0; p < S_XD; p++) s += g_xdp[(size_t)p * Bv * Av + b * Av + a];
                xd_s[a] = s;
            }
            __syncthreads();
            for (int l = warp; l < Lv; l += 8) {
                const __half2* xe2 =
                    reinterpret_cast<const __half2*>(g_xench + (size_t)(b * Lv + l) * Av);
                float s = 0.f;
                for (int a = lane; a < Av / 2; a += 32) {
                    float2 x = __half22float2(xe2[a]);
                    s += tanh_fast(x.x + xd_s[2 * a]) * score_w[2 * a];
                    s += tanh_fast(x.y + xd_s[2 * a + 1]) * score_w[2 * a + 1];
                }
#pragma unroll
                for (int o = 16; o; o >>= 1) s += __shfl_xor_sync(0xFFFFFFFFu, s, o);
                if (lane == 0) sc[l] = s + score_b[0];
            }
            __syncthreads();
            if (warp == 0) {
                float m = fmaxf(sc[lane], sc[lane + 32]);
#pragma unroll
                for (int o = 16; o; o >>= 1) m = fmaxf(m, __shfl_xor_sync(0xFFFFFFFFu, m, o));
                float s = expf(sc[lane] - m) + expf(sc[lane + 32] - m);
#pragma unroll
                for (int o = 16; o; o >>= 1) s += __shfl_xor_sync(0xFFFFFFFFu, s, o);
                if (lane == 0) { red[0] = m; red[1] = s; }
            }
            __syncthreads();
            float inv = 1.0f / red[1], smax = red[0];
            for (int l = tid; l < Lv; l += 256) {
                float a = expf(sc[l] - smax) * inv;
                al[l] = a;
                if (wout) wout[((size_t)b * Tv + t) * Lv + l] = a;
            }
            __syncthreads();
            // context, half2-vectorized
            const __half2* Xb2 = reinterpret_cast<const __half2*>(g_Xhi + (size_t)b * Lv * Fv);
            __half2* cat2 = reinterpret_cast<__half2*>(g_cathi + (size_t)b * CAT);
            for (int f2 = tid; f2 < Fv / 2; f2 += 256) {
                float sx = 0.f, sy = 0.f;
#pragma unroll
                for (int l = 0; l < Lv; l++) {
                    float2 x = __half22float2(Xb2[(size_t)l * (Fv / 2) + f2]);
                    sx = fmaf(al[l], x.x, sx);
                    sy = fmaf(al[l], x.y, sy);
                }
                cat2[f2] = __floats2half2_rn(sx, sy);
            }
        }
        gridbar(tgt);

        // ---------- P3: gates partials = cat @ WcatT (1-pass fp16 mma, split-K) ----------
        {
            constexpr int RBUF = 2 * 128 * LDT;
            constexpr int OFF_B = 128 * LDT;
            constexpr int KSPAN = CAT / S_GT;     // 768
            constexpr int NKC = KSPAN / 32;       // 24
            __half* smb = (__half*)smem;
            const uint32_t sbase = smem_u32(smb);
            const int bn0 = (blk & 31) * 128;
            const int ksp = blk >> 5;
            const int kbeg = ksp * KSPAN;
            const int wm = warp & 1, wn = warp >> 1;
            float acc[4][4][4] = {};
            const int arow = ((lane >> 3) & 1) * 8 + (lane & 7);
            const int akof = (lane >> 4) * 8;
            const int brow = ((lane >> 4) & 1) * 8 + (lane & 7);
            const int bkof = ((lane >> 3) & 1) * 8;

#pragma unroll 1
            for (int kc = 0; kc < NKC + 1; kc++) {
                if (kc < NKC) {
                    const int k0 = kbeg + kc * 32;
                    const int buf = kc & 1;
#pragma unroll
                    for (int j = 0; j < 2; j++) {
                        int c = tid + j * 256;
                        int r = c >> 2, sg = c & 3;
                        uint32_t so = sbase + (uint32_t)(buf * RBUF + r * LDT + sg * 8) * 2;
                        cp16(so, g_cathi + (size_t)r * CAT + k0 + sg * 8);
                        cp16(so + OFF_B * 2, g_WcatThi + (size_t)(bn0 + r) * CAT + k0 + sg * 8);
                    }
                    asm volatile("cp.async.commit_group;" ::: "memory");
                }
                if (kc == 0) continue;
                if (kc < NKC)
                    asm volatile("cp.async.wait_group 1;" ::: "memory");
                else
                    asm volatile("cp.async.wait_group 0;" ::: "memory");
                __syncthreads();
                const int cc = kc - 1;
                const uint32_t bo = sbase + (uint32_t)((cc & 1) * RBUF) * 2;
#pragma unroll
                for (int ks = 0; ks < 2; ks++) {
                    const int k0 = ks * 16;
                    uint32_t bh[4][2];
#pragma unroll
                    for (int p = 0; p < 2; p++) {
                        uint32_t ab = bo + (uint32_t)(OFF_B + (wn * 32 + p * 16 + brow) * LDT + k0 + bkof) * 2;
                        ldsm4(bh[2 * p][0], bh[2 * p][1], bh[2 * p + 1][0], bh[2 * p + 1][1], ab);
                    }
#pragma unroll
                    for (int mf = 0; mf < 4; mf++) {
                        uint32_t ah[4];
                        uint32_t aa = bo + (uint32_t)((wm * 64 + mf * 16 + arow) * LDT + k0 + akof) * 2;
                        ldsm4(ah[0], ah[1], ah[2], ah[3], aa);
#pragma unroll
                        for (int nf = 0; nf < 4; nf++) mma16816(acc[mf][nf], ah, bh[nf]);
                    }
                }
                __syncthreads();
            }
            float* P = g_gatep + (size_t)ksp * Bv * G4H;
#pragma unroll
            for (int mf = 0; mf < 4; mf++) {
#pragma unroll
                for (int half = 0; half < 2; half++) {
                    int m = wm * 64 + mf * 16 + (lane >> 2) + half * 8;
#pragma unroll
                    for (int nf = 0; nf < 4; nf++) {
                        int n = bn0 + wn * 32 + nf * 8 + (lane & 3) * 2;
                        float2 v{acc[mf][nf][half * 2 + 0], acc[mf][nf][half * 2 + 1]};
                        *reinterpret_cast<float2*>(P + (size_t)m * G4H + n) = v;
                    }
                }
            }
        }
        gridbar(tgt);

        // ---------- P4: gates reduce + LSTM pointwise ----------
        {
            for (int i = tid; i < (Bv * Hv) / NBLK; i += 256) {
                int idx = blk * ((Bv * Hv) / NBLK) + i;
                int b = idx / Hv, j = idx % Hv;
                size_t base = (size_t)b * G4H;
                const float* EG = g_embgate + ((size_t)t * Bv) * G4H + base;
                float ig = EG[j], fg = EG[Hv + j], gg = EG[2 * Hv + j], og = EG[3 * Hv + j];
#pragma unroll
                for (int s = 0; s < S_GT; s++) {
                    const float* P = g_gatep + (size_t)s * Bv * G4H + base;
                    ig += P[j];
                    fg += P[Hv + j];
                    gg += P[2 * Hv + j];
                    og += P[3 * Hv + j];
                }
                ig = sigmoidf_(ig);
                fg = sigmoidf_(fg);
                og = sigmoidf_(og);
                gg = tanhf(gg);
                float c2 = fg * g_c[idx] + ig * gg;
                float h2 = og * tanhf(c2);
                g_c[idx] = c2;
                g_h[idx] = h2;
                __half hh = __float2half_rn(h2);
                g_cathi[(size_t)b * CAT + Fv + j] = hh;
                g_Hallhi[((size_t)t * Bv + b) * Hv + j] = hh;
            }
        }
        gridbar(tgt);
    }
}

// ---------------- generic fp16 mma GEMM 128x128 (preproc, 1-pass) ----------------
template <bool HOUT>
__global__ void __launch_bounds__(256) gemm_h1(
    int Kspan, int lda, int ldb,
    const __half* __restrict__ Ah, const __half* __restrict__ Bh,
    void* __restrict__ Cv, int ldc,
    const float* __restrict__ bias1, const float* __restrict__ bias2) {
    constexpr int RBUF = 2 * 128 * LDT;
    constexpr int OFF_B = 128 * LDT;
    extern __shared__ __half smb[];
    const int tid = threadIdx.x, lane = tid & 31, wid = tid >> 5;
    const int wm = wid & 1, wn = wid >> 1;
    const int bm0 = blockIdx.x * 128, bn0 = blockIdx.y * 128;
    const uint32_t sbase = smem_u32(smb);

    float acc[4][4][4];
#pragma unroll
    for (int i = 0; i < 4; i++)
#pragma unroll
        for (int j = 0; j < 4; j++)
#pragma unroll
            for (int k = 0; k < 4; k++) acc[i][j][k] = 0.f;

    auto issue = [&](int buf, int kc) {
        const int k0 = kc * 32;
#pragma unroll
        for (int j = 0; j < 2; j++) {
            int c = tid + j * 256;
            int r = c >> 2, sg = c & 3;
            uint32_t so = sbase + (uint32_t)(buf * RBUF + r * LDT + sg * 8) * 2;
            cp16(so, Ah + (size_t)(bm0 + r) * lda + k0 + sg * 8);
            cp16(so + OFF_B * 2, Bh + (size_t)(bn0 + r) * ldb + k0 + sg * 8);
        }
        asm volatile("cp.async.commit_group;" ::: "memory");
    };

    const int arow = ((lane >> 3) & 1) * 8 + (lane & 7);
    const int akof = (lane >> 4) * 8;
    const int brow = ((lane >> 4) & 1) * 8 + (lane & 7);
    const int bkof = ((lane >> 3) & 1) * 8;

    const int NKC = Kspan / 32;
    issue(0, 0);
    for (int kc = 0; kc < NKC; kc++) {
        if (kc + 1 < NKC) {
            issue((kc + 1) & 1, kc + 1);
            asm volatile("cp.async.wait_group 1;" ::: "memory");
        } else {
            asm volatile("cp.async.wait_group 0;" ::: "memory");
        }
        __syncthreads();
        const uint32_t bo = sbase + (uint32_t)((kc & 1) * RBUF) * 2;
#pragma unroll
        for (int ks = 0; ks < 2; ks++) {
            const int k0 = ks * 16;
            uint32_t bh[4][2];
#pragma unroll
            for (int p = 0; p < 2; p++) {
                uint32_t ab = bo + (uint32_t)(OFF_B + (wn * 32 + p * 16 + brow) * LDT + k0 + bkof) * 2;
                ldsm4(bh[2 * p][0], bh[2 * p][1], bh[2 * p + 1][0], bh[2 * p + 1][1], ab);
            }
#pragma unroll
            for (int mf = 0; mf < 4; mf++) {
                uint32_t ah[4];
                uint32_t aa = bo + (uint32_t)((wm * 64 + mf * 16 + arow) * LDT + k0 + akof) * 2;
                ldsm4(ah[0], ah[1], ah[2], ah[3], aa);
#pragma unroll
                for (int nf = 0; nf < 4; nf++) mma16816(acc[mf][nf], ah, bh[nf]);
            }
        }
        __syncthreads();
    }

#pragma unroll
    for (int mf = 0; mf < 4; mf++) {
#pragma unroll
        for (int half = 0; half < 2; half++) {
            int m = bm0 + wm * 64 + mf * 16 + (lane >> 2) + half * 8;
#pragma unroll
            for (int nf = 0; nf < 4; nf++) {
                int n = bn0 + wn * 32 + nf * 8 + (lane & 3) * 2;
                float vx = acc[mf][nf][half * 2 + 0];
                float vy = acc[mf][nf][half * 2 + 1];
                if (bias1) { vx += bias1[n]; vy += bias1[n + 1]; }
                if (bias2) { vx += bias2[n]; vy += bias2[n + 1]; }
                if (HOUT) {
                    __half* Ch = (__half*)Cv;
                    *reinterpret_cast<__half2*>(Ch + (size_t)m * ldc + n) =
                        __floats2half2_rn(vx, vy);
                } else {
                    float* Cf = (float*)Cv;
                    float2 v{vx, vy};
                    *reinterpret_cast<float2*>(Cf + (size_t)m * ldc + n) = v;
                }
            }
        }
    }
}

// ---------------- big logits GEMM: 128x256 tile, 512 thr, 3-stage ----------------
__global__ void __launch_bounds__(512) gemm_big(
    const __half* __restrict__ Ah, const __half* __restrict__ Bh,
    const float* __restrict__ bias, float* __restrict__ C) {
    extern __shared__ __half smb[];
    const int tid = threadIdx.x, lane = tid & 31, wid = tid >> 5;
    const int wm = wid & 3, wn = wid >> 2;
    const int bm0 = blockIdx.x * 128, bn0 = blockIdx.y * 256;
    const uint32_t sbase = smem_u32(smb);

    float acc[2][8][4];
#pragma unroll
    for (int i = 0; i < 2; i++)
#pragma unroll
        for (int j = 0; j < 8; j++)
#pragma unroll
            for (int k = 0; k < 4; k++) acc[i][j][k] = 0.f;

    auto issue = [&](int st, int kc) {
        const int k0 = kc * 32;
        {
            int r = tid >> 2, sg = tid & 3;
            uint32_t so = sbase + (uint32_t)(st * BIG_STG + r * LDT + sg * 8) * 2;
            cp16(so, Ah + (size_t)(bm0 + r) * Hv + k0 + sg * 8);
        }
#pragma unroll
        for (int j = 0; j < 2; j++) {
            int c = tid + j * 512;
            int r = c >> 2, sg = c & 3;
            uint32_t so = sbase + (uint32_t)(st * BIG_STG + BIG_OFFB + r * LDT + sg * 8) * 2;
            cp16(so, Bh + (size_t)(bn0 + r) * Hv + k0 + sg * 8);
        }
        asm volatile("cp.async.commit_group;" ::: "memory");
    };

    const int arow = ((lane >> 3) & 1) * 8 + (lane & 7);
    const int akof = (lane >> 4) * 8;
    const int brow = ((lane >> 4) & 1) * 8 + (lane & 7);
    const int bkof = ((lane >> 3) & 1) * 8;

    constexpr int NKC = Hv / 32;
    issue(0, 0);
    issue(1, 1);
    for (int kc = 0; kc < NKC; kc++) {
        if (kc + 1 < NKC)
            asm volatile("cp.async.wait_group 1;" ::: "memory");
        else
            asm volatile("cp.async.wait_group 0;" ::: "memory");
        __syncthreads();
        if (kc + 2 < NKC) issue((kc + 2) % 3, kc + 2);
        const uint32_t bo = sbase + (uint32_t)((kc % 3) * BIG_STG) * 2;
#pragma unroll
        for (int ks = 0; ks < 2; ks++) {
            const int k0 = ks * 16;
            uint32_t bf[8][2];
#pragma unroll
            for (int p = 0; p < 4; p++) {
                uint32_t ab = bo + (uint32_t)(BIG_OFFB + (wn * 64 + p * 16 + brow) * LDT + k0 + bkof) * 2;
                ldsm4(bf[2 * p][0], bf[2 * p][1], bf[2 * p + 1][0], bf[2 * p + 1][1], ab);
            }
#pragma unroll
            for (int mf = 0; mf < 2; mf++) {
                uint32_t ah4[4];
                uint32_t aa = bo + (uint32_t)((wm * 32 + mf * 16 + arow) * LDT + k0 + akof) * 2;
                ldsm4(ah4[0], ah4[1], ah4[2], ah4[3], aa);
#pragma unroll
                for (int nf = 0; nf < 8; nf++) mma16816(acc[mf][nf], ah4, bf[nf]);
            }
        }
    }

#pragma unroll
    for (int mf = 0; mf < 2; mf++) {
#pragma unroll
        for (int half = 0; half < 2; half++) {
            int m = bm0 + wm * 32 + mf * 16 + (lane >> 2) + half * 8;
            int tt = m >> 7, bb = m & 127;
            float* dst = C + ((size_t)bb * Tv + tt) * (size_t)Vv;
#pragma unroll
            for (int nf = 0; nf < 8; nf++) {
                int n = bn0 + wn * 64 + nf * 8 + (lane & 3) * 2;
                float2 v;
                v.x = acc[mf][nf][half * 2 + 0] + bias[n];
                v.y = acc[mf][nf][half * 2 + 1] + bias[n + 1];
                *reinterpret_cast<float2*>(dst + n) = v;
            }
        }
    }
}

// ---------------- host orchestration ----------------
extern "C" void kernel_launch(void* const* d_in, const int* in_sizes, int n_in,
                              void* d_out, int out_size) {
    const float* X       = (const float*)d_in[0];
    const void*  yraw    = d_in[1];
    const float* emb     = (const float*)d_in[2];
    const float* fc1_w   = (const float*)d_in[3];
    const float* fc1_b   = (const float*)d_in[4];
    const float* fc2_w   = (const float*)d_in[5];
    const float* fc2_b   = (const float*)d_in[6];
    const float* score_w = (const float*)d_in[7];
    const float* score_b = (const float*)d_in[8];
    const float* sm_w    = (const float*)d_in[9];
    const float* sm_b    = (const float*)d_in[10];
    const float* lm_w    = (const float*)d_in[11];
    const float* lm_b    = (const float*)d_in[12];
    const float* w_ih    = (const float*)d_in[13];
    const float* b_ih    = (const float*)d_in[14];
    const float* w_hh    = (const float*)d_in[15];
    const float* b_hh    = (const float*)d_in[16];
    const float* out_w   = (const float*)d_in[17];
    const float* out_b   = (const float*)d_in[18];

    float *p_mean, *p_embgate, *p_hp, *p_cp;
    __half *p_embxhi, *p_Hallhi, *p_owThi, *p_xench;
    __half *p_WcatThi, *p_fc2Thi, *p_wihEThi, *p_Xhi;
    cudaGetSymbolAddress((void**)&p_mean, g_mean);
    cudaGetSymbolAddress((void**)&p_embgate, g_embgate);
    cudaGetSymbolAddress((void**)&p_hp, g_hp);
    cudaGetSymbolAddress((void**)&p_cp, g_cp);
    cudaGetSymbolAddress((void**)&p_embxhi, g_embxhi);
    cudaGetSymbolAddress((void**)&p_Hallhi, g_Hallhi);
    cudaGetSymbolAddress((void**)&p_owThi, g_owThi);
    cudaGetSymbolAddress((void**)&p_xench, g_xench);
    cudaGetSymbolAddress((void**)&p_WcatThi, g_WcatThi);
    cudaGetSymbolAddress((void**)&p_fc2Thi, g_fc2Thi);
    cudaGetSymbolAddress((void**)&p_wihEThi, g_wihEThi);
    cudaGetSymbolAddress((void**)&p_Xhi, g_Xhi);

    float* outp = (float*)d_out;
    const size_t osz = (size_t)Bv * Tv * Vv;
    const size_t wsz = (size_t)Bv * Tv * Lv;
    float* wout = ((size_t)out_size >= osz + wsz) ? (outp + osz) : nullptr;

    static int smem_set = 0;
    if (!smem_set) {
        cudaFuncSetAttribute(gemm_big, cudaFuncAttributeMaxDynamicSharedMemorySize, SMEM_BIG);
        cudaFuncSetAttribute(loop_kernel, cudaFuncAttributeMaxDynamicSharedMemorySize, SMEM_LOOP);
        cudaFuncSetAttribute(gemm_h1<true>,
                             cudaFuncAttributeMaxDynamicSharedMemorySize, SMEM_P1);
        cudaFuncSetAttribute(gemm_h1<false>,
                             cudaFuncAttributeMaxDynamicSharedMemorySize, SMEM_P1);
        smem_set = 1;
    }

    // --- step-invariant preprocessing ---
    detect_y_kernel<<<1, 256>>>((const int*)yraw);
    gather_emb_kernel<<<(Tv * Bv * Ev) / 256, 256>>>(yraw, emb);
    mean_kernel<<<(Bv * Fv) / 256, 256>>>(X);
    convX_kernel<<<(int)(((size_t)Bv * Lv * Fv) / 4 / 256), 256>>>((const float4*)X);
    transW_kernel<<<dim3(Vv / 32, Hv / 32), dim3(32, 8)>>>(
        out_w, nullptr, Hv, Hv, Vv, p_owThi);
    transW_kernel<<<dim3(G4H / 32, CAT / 32), dim3(32, 8)>>>(
        w_ih + (size_t)Ev * G4H, w_hh, Fv, CAT, G4H, p_WcatThi);
    transW_kernel<<<dim3(Av / 32, Fv / 32), dim3(32, 8)>>>(
        fc2_w, nullptr, Fv, Fv, Av, p_fc2Thi);
    transW_kernel<<<dim3(G4H / 32, Ev / 32), dim3(32, 8)>>>(
        w_ih, nullptr, Ev, Ev, G4H, p_wihEThi);
    skgemm<32, 32><<<dim3(Hv / 32, S_HC), 256>>>(Hv, Fv, S_HC, p_mean, Fv, sm_w, Hv, p_hp);
    skgemm<32, 32><<<dim3(Hv / 32, S_HC), 256>>>(Hv, Fv, S_HC, p_mean, Fv, lm_w, Hv, p_cp);
    reduce_hc<<<(Bv * Hv) / 256, 256>>>(sm_b, lm_b);
    // x_enc (1-pass, fp16 out)
    gemm_h1<true><<<dim3((Bv * Lv) / 128, Av / 128), 256, SMEM_P1>>>(
        Fv, Fv, Fv, p_Xhi, p_fc2Thi, p_xench, Av, fc2_b, nullptr);
    // embgate (1-pass, fp32 out)
    gemm_h1<false><<<dim3((Tv * Bv) / 128, G4H / 128), 256, SMEM_P1>>>(
        Ev, Ev, Ev, p_embxhi, p_wihEThi, p_embgate, G4H, b_ih, b_hh);

    // --- persistent recurrent loop (one launch) ---
    reset_bar_kernel<<<1, 1>>>();
    loop_kernel<<<NBLK, 256, SMEM_LOOP>>>(fc1_w, fc1_b, score_w, score_b, wout);

    // --- logits: 1-pass fp16 128x256 3-stage mma, remap epilogue ---
    gemm_big<<<dim3(Tv * Bv / 128, Vv / 256), 512, SMEM_BIG>>>(
        p_Hallhi, p_owThi, out_b, outp);
}